// round 1
// baseline (speedup 1.0000x reference)
#include <cuda_runtime.h>

// Problem constants
#define BB 16
#define CIN 1024
#define PP 512
#define NN 2048          // H*W = 64*32
#define LL 256           // stripe positions = 8*32
#define DH 128           // head dim = 512/4
#define INVF 0.99999500003749969f      // 1/sqrt(1+1e-5)
#define QSCALE 0.08838834764831843f    // 128^-0.5

// Scratch (device globals: no allocation allowed)
__device__ float g_out1[(size_t)BB * PP * NN];
__device__ float g_q  [(size_t)BB * PP * NN];
__device__ float g_k  [(size_t)BB * PP * NN];
__device__ float g_v  [(size_t)BB * PP * NN];
__device__ float g_out2[(size_t)BB * PP * NN];

// ---------------------------------------------------------------------------
// Batched SGEMM:  C[bz] (M x 2048) = A (M x K) @ B[bz] (K x 2048)
// EPI 0: C = acc * oscale
// EPI 1: C = relu(acc * (g[m]*INVF) + (cb[m]*g[m]*INVF + beta[m]))
// EPI 2: like 1 but += resid[bz][m][n] before relu
// 128x128 block tile, 16-deep k, 256 threads, 8x8 microtile (4+4 split).
// ---------------------------------------------------------------------------
template <int EPI>
__global__ __launch_bounds__(256)
void sgemm(const float* __restrict__ A, const float* __restrict__ Bm,
           float* __restrict__ C,
           const float* __restrict__ g, const float* __restrict__ beta,
           const float* __restrict__ cb, const float* __restrict__ resid,
           int M, int K, float oscale)
{
    __shared__ float As[16][132];   // [k][m], padded
    __shared__ float Bs[16][128];   // [k][n]

    const int bz = blockIdx.z;
    const float* Bp = Bm + (size_t)bz * K * NN;
    float* Cp = C + (size_t)bz * M * NN;
    const int m0 = blockIdx.y * 128;
    const int n0 = blockIdx.x * 128;
    const int t  = threadIdx.x;
    const int tx = t & 15;
    const int ty = t >> 4;

    float acc[8][8];
#pragma unroll
    for (int i = 0; i < 8; i++)
#pragma unroll
        for (int j = 0; j < 8; j++) acc[i][j] = 0.f;

    for (int k0 = 0; k0 < K; k0 += 16) {
        // A tile: 128 rows x 16 k  (row-major global, transposed into As[k][m])
#pragma unroll
        for (int r = 0; r < 2; r++) {
            int i = t + r * 256;            // 0..511 float4s
            int row = i >> 2, seg = i & 3;
            float4 v4 = *(const float4*)(A + (size_t)(m0 + row) * K + k0 + seg * 4);
            As[seg * 4 + 0][row] = v4.x;
            As[seg * 4 + 1][row] = v4.y;
            As[seg * 4 + 2][row] = v4.z;
            As[seg * 4 + 3][row] = v4.w;
        }
        // B tile: 16 k x 128 n
#pragma unroll
        for (int r = 0; r < 2; r++) {
            int i = t + r * 256;
            int kk = i >> 5, seg = i & 31;
            *(float4*)&Bs[kk][seg * 4] =
                *(const float4*)(Bp + (size_t)(k0 + kk) * NN + n0 + seg * 4);
        }
        __syncthreads();

#pragma unroll
        for (int kk = 0; kk < 16; kk++) {
            float a[8], b[8];
            *(float4*)&a[0] = *(const float4*)&As[kk][ty * 4];
            *(float4*)&a[4] = *(const float4*)&As[kk][64 + ty * 4];
            *(float4*)&b[0] = *(const float4*)&Bs[kk][tx * 4];
            *(float4*)&b[4] = *(const float4*)&Bs[kk][64 + tx * 4];
#pragma unroll
            for (int i = 0; i < 8; i++)
#pragma unroll
                for (int j = 0; j < 8; j++) acc[i][j] += a[i] * b[j];
        }
        __syncthreads();
    }

    // Epilogue + store (float4)
#pragma unroll
    for (int i = 0; i < 8; i++) {
        int m = m0 + ((i < 4) ? (ty * 4 + i) : (64 + ty * 4 + i - 4));
        float s = 1.f, tt = 0.f;
        if (EPI) { s = g[m] * INVF; tt = cb[m] * s + beta[m]; }
#pragma unroll
        for (int h = 0; h < 2; h++) {
            int n = n0 + h * 64 + tx * 4;
            float4 rv = make_float4(0.f, 0.f, 0.f, 0.f);
            if (EPI == 2)
                rv = *(const float4*)(resid + (size_t)bz * M * NN + (size_t)m * NN + n);
            float vals[4];
            const float* pr = &rv.x;
#pragma unroll
            for (int j = 0; j < 4; j++) {
                float v = acc[i][h * 4 + j];
                if (EPI == 0) {
                    v *= oscale;
                } else {
                    v = v * s + tt;
                    if (EPI == 2) v += pr[j];
                    v = fmaxf(v, 0.f);
                }
                vals[j] = v;
            }
            *(float4*)(Cp + (size_t)m * NN + n) =
                make_float4(vals[0], vals[1], vals[2], vals[3]);
        }
    }
}

// ---------------------------------------------------------------------------
// Fused stripe attention + residual + BN2 + ReLU.
// One block per (b, stripe, head, x-tile of 64 queries). 256 threads.
// q/k/v layout: [b][p][hw] with head = contiguous 128 rows, stripe = contiguous
// 256 cols. Full softmax over the stripe's 256 keys via smem score matrix.
// smem: Qs[128][64] + KVs[128][68] + St[256][68] + red[512]  = 139,264 B
// ---------------------------------------------------------------------------
#define ATTN_SMEM ((128 * 64 + 128 * 68 + 256 * 68 + 512) * 4)

__global__ __launch_bounds__(256)
void attn_kernel(const float* __restrict__ q, const float* __restrict__ k,
                 const float* __restrict__ v, const float* __restrict__ out1,
                 const float* __restrict__ g2, const float* __restrict__ be2,
                 float* __restrict__ out2)
{
    extern __shared__ float sm[];
    float* Qs  = sm;                  // [dd][x]   128 x 64
    float* KVs = sm + 8192;           // [dd][y]   128 x 68 (pad)
    float* St  = sm + 8192 + 8704;    // [y][x]    256 x 68 (pad)
    float* red = St + 256 * 68;       // 512 floats

    const int xt = blockIdx.x;        // 0..3  (64-query tile)
    const int sp = blockIdx.y >> 2;   // stripe 0..7
    const int hh = blockIdx.y & 3;    // head 0..3
    const int b  = blockIdx.z;
    const int t  = threadIdx.x;

    const size_t base = (size_t)b * PP * NN + (size_t)hh * DH * NN + (size_t)sp * LL;
    const float* qp = q + base + xt * 64;
    const float* kp = k + base;
    const float* vp = v + base;

    // Load Q tile: 128 (d) x 64 (x)
#pragma unroll
    for (int r = 0; r < 8; r++) {
        int i = t + r * 256;
        int row = i >> 4, seg = i & 15;
        *(float4*)&Qs[row * 64 + seg * 4] =
            *(const float4*)(qp + (size_t)row * NN + seg * 4);
    }

    // ---- Phase B: S^T[y][x] = sum_d q[d][x] * k[d][y]  (q pre-scaled) ----
    const int xq = t & 15, yq = t >> 4;
    for (int yc = 0; yc < 4; yc++) {
        __syncthreads();
#pragma unroll
        for (int r = 0; r < 8; r++) {
            int i = t + r * 256;
            int row = i >> 4, seg = i & 15;
            *(float4*)&KVs[row * 68 + seg * 4] =
                *(const float4*)(kp + (size_t)row * NN + yc * 64 + seg * 4);
        }
        __syncthreads();

        float acc[4][4];
#pragma unroll
        for (int yi = 0; yi < 4; yi++)
#pragma unroll
            for (int xi = 0; xi < 4; xi++) acc[yi][xi] = 0.f;

        for (int dd = 0; dd < 128; dd++) {
            float4 aq = *(const float4*)&Qs[dd * 64 + xq * 4];
            float4 bk = *(const float4*)&KVs[dd * 68 + yq * 4];
            acc[0][0] += bk.x * aq.x; acc[0][1] += bk.x * aq.y;
            acc[0][2] += bk.x * aq.z; acc[0][3] += bk.x * aq.w;
            acc[1][0] += bk.y * aq.x; acc[1][1] += bk.y * aq.y;
            acc[1][2] += bk.y * aq.z; acc[1][3] += bk.y * aq.w;
            acc[2][0] += bk.z * aq.x; acc[2][1] += bk.z * aq.y;
            acc[2][2] += bk.z * aq.z; acc[2][3] += bk.z * aq.w;
            acc[3][0] += bk.w * aq.x; acc[3][1] += bk.w * aq.y;
            acc[3][2] += bk.w * aq.z; acc[3][3] += bk.w * aq.w;
        }
#pragma unroll
        for (int yi = 0; yi < 4; yi++)
#pragma unroll
            for (int xi = 0; xi < 4; xi++)
                St[(yc * 64 + yq * 4 + yi) * 68 + xq * 4 + xi] = acc[yi][xi];
    }
    __syncthreads();

    // ---- Phase C: softmax over y for each column x ----
    {
        const int cx = t & 63;
        const int tg = t >> 6;
        float mx = -1e30f;
        for (int yy = tg * 64; yy < tg * 64 + 64; yy++)
            mx = fmaxf(mx, St[yy * 68 + cx]);
        red[tg * 64 + cx] = mx;
        __syncthreads();
        float M4 = fmaxf(fmaxf(red[cx], red[64 + cx]),
                         fmaxf(red[128 + cx], red[192 + cx]));
        float ssum = 0.f;
        for (int yy = tg * 64; yy < tg * 64 + 64; yy++) {
            float e = __expf(St[yy * 68 + cx] - M4);
            St[yy * 68 + cx] = e;
            ssum += e;
        }
        red[256 + tg * 64 + cx] = ssum;
        __syncthreads();
        float Sv = red[256 + cx] + red[256 + 64 + cx] +
                   red[256 + 128 + cx] + red[256 + 192 + cx];
        float inv = 1.f / Sv;
        for (int yy = tg * 64; yy < tg * 64 + 64; yy++)
            St[yy * 68 + cx] *= inv;
    }

    // ---- Phase D: O[dd][x] = sum_y V[dd][y] * P[y][x] ----
    const int txd = t & 15, tyd = t >> 4;
    float acc2[8][4];
#pragma unroll
    for (int i = 0; i < 8; i++)
#pragma unroll
        for (int j = 0; j < 4; j++) acc2[i][j] = 0.f;

    for (int yc = 0; yc < 4; yc++) {
        __syncthreads();
#pragma unroll
        for (int r = 0; r < 8; r++) {
            int i = t + r * 256;
            int row = i >> 4, seg = i & 15;
            *(float4*)&KVs[row * 68 + seg * 4] =
                *(const float4*)(vp + (size_t)row * NN + yc * 64 + seg * 4);
        }
        __syncthreads();

        for (int yi = 0; yi < 64; yi += 4) {
            int y = yc * 64 + yi;
            float4 p0 = *(const float4*)&St[(y + 0) * 68 + txd * 4];
            float4 p1 = *(const float4*)&St[(y + 1) * 68 + txd * 4];
            float4 p2 = *(const float4*)&St[(y + 2) * 68 + txd * 4];
            float4 p3 = *(const float4*)&St[(y + 3) * 68 + txd * 4];
#pragma unroll
            for (int i = 0; i < 8; i++) {
                float4 vv = *(const float4*)&KVs[(tyd * 8 + i) * 68 + yi];
                acc2[i][0] += vv.x * p0.x + vv.y * p1.x + vv.z * p2.x + vv.w * p3.x;
                acc2[i][1] += vv.x * p0.y + vv.y * p1.y + vv.z * p2.y + vv.w * p3.y;
                acc2[i][2] += vv.x * p0.z + vv.y * p1.z + vv.z * p2.z + vv.w * p3.z;
                acc2[i][3] += vv.x * p0.w + vv.y * p1.w + vv.z * p2.w + vv.w * p3.w;
            }
        }
    }

    // ---- Epilogue: out2 = relu((O + out1) * g2*INVF + be2) ----
#pragma unroll
    for (int i = 0; i < 8; i++) {
        int dd = tyd * 8 + i;
        int p = hh * DH + dd;
        float s = g2[p] * INVF;
        float tt = be2[p];
        size_t idx = base + (size_t)dd * NN + xt * 64 + txd * 4;
        float4 o1v = *(const float4*)(out1 + idx);
        float4 o;
        o.x = fmaxf((acc2[i][0] + o1v.x) * s + tt, 0.f);
        o.y = fmaxf((acc2[i][1] + o1v.y) * s + tt, 0.f);
        o.z = fmaxf((acc2[i][2] + o1v.z) * s + tt, 0.f);
        o.w = fmaxf((acc2[i][3] + o1v.w) * s + tt, 0.f);
        *(float4*)(out2 + idx) = o;
    }
}

// ---------------------------------------------------------------------------
extern "C" void kernel_launch(void* const* d_in, const int* in_sizes, int n_in,
                              void* d_out, int out_size)
{
    const float* x   = (const float*)d_in[0];
    const float* w1  = (const float*)d_in[1];
    const float* b1  = (const float*)d_in[2];
    const float* g1  = (const float*)d_in[3];
    const float* be1 = (const float*)d_in[4];
    const float* wq  = (const float*)d_in[5];
    const float* wk  = (const float*)d_in[6];
    const float* wv  = (const float*)d_in[7];
    const float* g2  = (const float*)d_in[8];
    const float* be2 = (const float*)d_in[9];
    const float* w3  = (const float*)d_in[10];
    const float* b3  = (const float*)d_in[11];
    const float* g3  = (const float*)d_in[12];
    const float* be3 = (const float*)d_in[13];
    float* out = (float*)d_out;

    float *o1, *qb, *kb, *vb, *o2;
    cudaGetSymbolAddress((void**)&o1, g_out1);
    cudaGetSymbolAddress((void**)&qb, g_q);
    cudaGetSymbolAddress((void**)&kb, g_k);
    cudaGetSymbolAddress((void**)&vb, g_v);
    cudaGetSymbolAddress((void**)&o2, g_out2);

    cudaFuncSetAttribute(attn_kernel,
                         cudaFuncAttributeMaxDynamicSharedMemorySize, ATTN_SMEM);

    // 1) out1 = relu(bn1(conv1(x)))
    sgemm<1><<<dim3(16, 4, 16), 256>>>(w1, x, o1, g1, be1, b1, nullptr,
                                       PP, CIN, 1.f);
    // 2) q/k/v projections (q pre-scaled by d^-0.5)
    sgemm<0><<<dim3(16, 4, 16), 256>>>(wq, o1, qb, nullptr, nullptr, nullptr,
                                       nullptr, PP, PP, QSCALE);
    sgemm<0><<<dim3(16, 4, 16), 256>>>(wk, o1, kb, nullptr, nullptr, nullptr,
                                       nullptr, PP, PP, 1.f);
    sgemm<0><<<dim3(16, 4, 16), 256>>>(wv, o1, vb, nullptr, nullptr, nullptr,
                                       nullptr, PP, PP, 1.f);
    // 3) attention + residual-add + bn2 + relu  -> out2
    attn_kernel<<<dim3(4, 32, 16), 256, ATTN_SMEM>>>(qb, kb, vb, o1, g2, be2, o2);
    // 4) out = relu(bn3(conv3(out2)) + x)
    sgemm<2><<<dim3(16, 8, 16), 256>>>(w3, o2, out, g3, be3, b3, x,
                                       CIN, PP, 1.f);
}

// round 3
// speedup vs baseline: 2.0903x; 2.0903x over previous
#include <cuda_runtime.h>
#include <cstdint>

// Problem constants
#define BB 16
#define CIN 1024
#define PP 512
#define NN 2048          // H*W
#define DH 128           // head dim
#define INVF 0.99999500003749969f      // 1/sqrt(1+1e-5)
#define QSCALE 0.08838834764831843f    // 128^-0.5

// tcgen05 only exists in the arch-specific (sm_103a/sm_100a) compilation pass.
#if defined(__CUDA_ARCH__) && (__CUDA_ARCH__ >= 1000) && \
    (defined(__CUDA_ARCH_FEAT_SM103_ALL) || defined(__CUDA_ARCH_FEAT_SM100_ALL) || \
     defined(__CUDA_ARCH_SPECIFIC__) || defined(__CUDA_ARCH_FAMILY_SPECIFIC__))
#define HAS_TCGEN05 1
#else
#define HAS_TCGEN05 0
#endif

// Scratch (device globals: no allocation allowed)
__device__ float g_xT  [(size_t)BB * CIN * NN];   // x transposed  [b][hw][c]
__device__ float g_out1[(size_t)BB * PP * NN];    // [b][p][hw]
__device__ float g_o1T [(size_t)BB * PP * NN];    // [b][hw][p]
__device__ float g_q   [(size_t)BB * PP * NN];
__device__ float g_k   [(size_t)BB * PP * NN];
__device__ float g_v   [(size_t)BB * PP * NN];
__device__ float g_out2[(size_t)BB * PP * NN];    // [b][p][hw]
__device__ float g_o2T [(size_t)BB * PP * NN];    // [b][hw][p]

// ---------------------------------------------------------------------------
// PTX helpers (bodies only instantiated where called, i.e. inside the guard)
// ---------------------------------------------------------------------------
__device__ __forceinline__ uint32_t smem_u32(const void* p) {
    uint32_t a;
    asm("{ .reg .u64 t; cvta.to.shared.u64 t, %1; cvt.u32.u64 %0, t; }"
        : "=r"(a) : "l"(p));
    return a;
}
#if HAS_TCGEN05
__device__ __forceinline__ uint32_t elect1() {
    uint32_t p;
    asm volatile("{ .reg .pred p; elect.sync _|p, 0xFFFFFFFF; selp.b32 %0,1,0,p; }"
                 : "=r"(p));
    return p;
}
__device__ __forceinline__ float to_tf32(float x) {
    float r; asm("cvt.rna.tf32.f32 %0, %1;" : "=f"(r) : "f"(x)); return r;
}
#define SW128(o) ((o) ^ ((((uint32_t)(o)) >> 3) & 0x70))

#define MBAR_INIT(a, c) \
    asm volatile("mbarrier.init.shared.b64 [%0], %1;" :: "r"(a), "r"(c) : "memory")

#define MBAR_WAIT(a, ph) do { \
    uint32_t _d; \
    asm volatile("{ .reg .pred p; mbarrier.try_wait.parity.acquire.cta.shared::cta.b64 p,[%1],%2; selp.b32 %0,1,0,p; }" \
                 : "=r"(_d) : "r"(a), "r"(ph) : "memory"); \
    if (!_d) { \
        asm volatile("{ .reg .pred P;\nLW_%=:\nmbarrier.try_wait.parity.acquire.cta.shared::cta.b64 P,[%0],%1,0x989680;\n@P bra.uni LD_%=;\nbra.uni LW_%=;\nLD_%=:\n}" \
                     :: "r"(a), "r"(ph) : "memory"); \
    } } while (0)

#define TM_ALLOC(sa, n) \
    asm volatile("tcgen05.alloc.cta_group::1.sync.aligned.shared::cta.b32 [%0], %1;" \
                 :: "r"(sa), "r"(n) : "memory")
#define TM_DEALLOC(t, n) \
    asm volatile("tcgen05.dealloc.cta_group::1.sync.aligned.b32 %0, %1;" :: "r"(t), "r"(n))
#define TM_COMMIT(mb) \
    asm volatile("tcgen05.commit.cta_group::1.mbarrier::arrive::one.shared::cluster.b64 [%0];" \
                 :: "r"(mb) : "memory")
#define TM_FENCE_AFTER() asm volatile("tcgen05.fence::after_thread_sync;" ::: "memory")
#define TM_WAIT_LD()     asm volatile("tcgen05.wait::ld.sync.aligned;" ::: "memory")
#define FENCE_ASYNC()    asm volatile("fence.proxy.async.shared::cta;" ::: "memory")

#define TM_LD_X32(r, addr) \
    asm volatile("tcgen05.ld.sync.aligned.32x32b.x32.b32 " \
        "{%0,%1,%2,%3,%4,%5,%6,%7,%8,%9,%10,%11,%12,%13,%14,%15," \
        "%16,%17,%18,%19,%20,%21,%22,%23,%24,%25,%26,%27,%28,%29,%30,%31}, [%32];" \
        : "=r"((r)[0]),"=r"((r)[1]),"=r"((r)[2]),"=r"((r)[3]), \
          "=r"((r)[4]),"=r"((r)[5]),"=r"((r)[6]),"=r"((r)[7]), \
          "=r"((r)[8]),"=r"((r)[9]),"=r"((r)[10]),"=r"((r)[11]), \
          "=r"((r)[12]),"=r"((r)[13]),"=r"((r)[14]),"=r"((r)[15]), \
          "=r"((r)[16]),"=r"((r)[17]),"=r"((r)[18]),"=r"((r)[19]), \
          "=r"((r)[20]),"=r"((r)[21]),"=r"((r)[22]),"=r"((r)[23]), \
          "=r"((r)[24]),"=r"((r)[25]),"=r"((r)[26]),"=r"((r)[27]), \
          "=r"((r)[28]),"=r"((r)[29]),"=r"((r)[30]),"=r"((r)[31]) \
        : "r"(addr))

__device__ __forceinline__ uint64_t mkdesc(uint32_t addr) {
    return ((uint64_t)2 << 61) | ((uint64_t)1 << 46) | ((uint64_t)64 << 32) |
           ((uint64_t)1 << 16) | ((addr >> 4) & 0x3FFF);
}
__device__ __forceinline__ void mma_tf32(uint32_t d, uint64_t ad, uint64_t bd,
                                         uint32_t id, uint32_t en) {
    asm volatile(
        "{ .reg .pred p; setp.ne.u32 p, %5, 0;\n\t"
        "tcgen05.mma.cta_group::1.kind::tf32 [%0], %1, %2, %3, {%4,%4,%4,%4}, p;\n\t}"
        :: "r"(d), "l"(ad), "l"(bd), "r"(id), "r"(0u), "r"(en) : "memory");
}
// idesc: F32 accum, TF32 a/b, N=128, M=128
#define IDESC_TF32 ((1u << 4) | (2u << 7) | (2u << 10) | (16u << 17) | (8u << 24))
#endif  // HAS_TCGEN05

// ---------------------------------------------------------------------------
// Tiled transpose per batch: in[b][R][C] -> out[b][C][R]
// ---------------------------------------------------------------------------
__global__ __launch_bounds__(256)
void transpose_k(const float* __restrict__ in, float* __restrict__ out, int R, int C)
{
    __shared__ float tile[32][33];
    const int b = blockIdx.z;
    const float* ip = in + (size_t)b * R * C;
    float* op = out + (size_t)b * R * C;
    const int c0 = blockIdx.x * 32, r0 = blockIdx.y * 32;
    const int tx = threadIdx.x & 31, ty = threadIdx.x >> 5;  // 32 x 8
#pragma unroll
    for (int i = 0; i < 32; i += 8)
        tile[ty + i][tx] = ip[(size_t)(r0 + ty + i) * C + c0 + tx];
    __syncthreads();
#pragma unroll
    for (int i = 0; i < 32; i += 8)
        op[(size_t)(c0 + ty + i) * R + r0 + tx] = tile[tx][ty + i];
}

// ---------------------------------------------------------------------------
// Batched GEMM:  C[bz][m][n] = sum_k A[m][k] * XT[bz][n][k]
//   A:  weights [M][K], K-contiguous ;  XT: [bz][2048][K], K-contiguous
// sm_103a pass: tcgen05 tf32, 128x128 tile, TMEM accum.
// other passes: fp32 FFMA fallback (correct; not expected to execute on GB300).
// EPI 0: C=acc*oscale ; 1: relu(acc*s+t) ; 2: relu(acc*s+t+resid)
// ---------------------------------------------------------------------------
#define GS_TM  0u
#define GS_MB  16u
#define GS_A0  1024u
#define GS_B0  (1024u + 16384u)
#define GS_A1  (1024u + 32768u)
#define GS_B1  (1024u + 49152u)
#define GSMEM  (1024 + 128 * 132 * 4)   // 68608

template <int EPI>
__global__ __launch_bounds__(256)
void tgemm(const float* __restrict__ A, const float* __restrict__ XT,
           float* __restrict__ C,
           const float* __restrict__ g, const float* __restrict__ beta,
           const float* __restrict__ cb, const float* __restrict__ resid,
           int M, int K, float oscale)
{
#if HAS_TCGEN05
    extern __shared__ char smem[];
    const uint32_t sbase = smem_u32(smem);
    const int t = threadIdx.x, wid = t >> 5, lane = t & 31;
    const int bz = blockIdx.z;
    const int m0 = blockIdx.y * 128, n0 = blockIdx.x * 128;
    const float* Ap = A + (size_t)m0 * K;
    const float* Bp = XT + (size_t)bz * NN * K + (size_t)n0 * K;
    float* Cp = C + (size_t)bz * M * NN;

    if (t == 0) { MBAR_INIT(sbase + GS_MB, 1); MBAR_INIT(sbase + GS_MB + 8, 1); }
    if (wid == 0) TM_ALLOC(sbase + GS_TM, 128);
    __syncthreads();
    uint32_t tmem;
    asm volatile("ld.shared.b32 %0, [%1];" : "=r"(tmem) : "r"(sbase + GS_TM));

    const uint32_t offA[2] = {GS_A0, GS_A1};
    const uint32_t offB[2] = {GS_B0, GS_B1};
    const int nk = K >> 5;

    for (int c = 0; c < nk; c++) {
        const int buf = c & 1;
        const uint32_t mb = sbase + GS_MB + 8 * buf;
        if (c >= 2) MBAR_WAIT(mb, ((c >> 1) - 1) & 1);

        float4 av[4], bv[4];
#pragma unroll
        for (int r = 0; r < 4; r++) {
            int idx = t + r * 256, row = idx >> 3, seg = idx & 7;
            av[r] = *(const float4*)(Ap + (size_t)row * K + c * 32 + seg * 4);
        }
#pragma unroll
        for (int r = 0; r < 4; r++) {
            int idx = t + r * 256, row = idx >> 3, seg = idx & 7;
            bv[r] = *(const float4*)(Bp + (size_t)row * K + c * 32 + seg * 4);
        }
#pragma unroll
        for (int r = 0; r < 4; r++) {
            int idx = t + r * 256, row = idx >> 3, seg = idx & 7;
            float4 v = av[r];
            v.x = to_tf32(v.x); v.y = to_tf32(v.y);
            v.z = to_tf32(v.z); v.w = to_tf32(v.w);
            *(float4*)(smem + offA[buf] + SW128(row * 128 + seg * 16)) = v;
        }
#pragma unroll
        for (int r = 0; r < 4; r++) {
            int idx = t + r * 256, row = idx >> 3, seg = idx & 7;
            float4 v = bv[r];
            v.x = to_tf32(v.x); v.y = to_tf32(v.y);
            v.z = to_tf32(v.z); v.w = to_tf32(v.w);
            *(float4*)(smem + offB[buf] + SW128(row * 128 + seg * 16)) = v;
        }
        __syncthreads();

        if (wid == 0) {
            if (elect1()) {
                FENCE_ASYNC();
                uint64_t ad = mkdesc(sbase + offA[buf]);
                uint64_t bd = mkdesc(sbase + offB[buf]);
#pragma unroll
                for (int s = 0; s < 4; s++)
                    mma_tf32(tmem, ad + s * 2, bd + s * 2, IDESC_TF32,
                             (c > 0 || s > 0) ? 1u : 0u);
                TM_COMMIT(mb);
            }
        }
    }
    {
        const int cl = nk - 1;
        MBAR_WAIT(sbase + GS_MB + 8 * (cl & 1), (cl >> 1) & 1);
    }
    TM_FENCE_AFTER();

    // Epilogue: LDTM -> per-row math -> smem staging -> coalesced STG
    const int sp = wid & 3, ch = wid >> 2;
    uint32_t r0[32], r1[32];
    TM_LD_X32(r0, tmem + ch * 64);
    TM_LD_X32(r1, tmem + ch * 64 + 32);
    TM_WAIT_LD();

    const int ml = sp * 32 + lane;
    const int m = m0 + ml;
    float s = oscale, tt = 0.f;
    if (EPI) { s = g[m] * INVF; tt = cb[m] * s + beta[m]; }
    float* stg = (float*)(smem + 1024);
#pragma unroll
    for (int i = 0; i < 32; i++) {
        float v0 = fmaf(__uint_as_float(r0[i]), s, tt);
        float v1 = fmaf(__uint_as_float(r1[i]), s, tt);
        if (EPI == 1) { v0 = fmaxf(v0, 0.f); v1 = fmaxf(v1, 0.f); }
        stg[ml * 132 + ch * 64 + i]      = v0;
        stg[ml * 132 + ch * 64 + 32 + i] = v1;
    }
    __syncthreads();

#pragma unroll
    for (int rr = 0; rr < 16; rr++) {
        int row = rr * 8 + wid;
        int c4 = lane;
        float4 v = *(float4*)&stg[row * 132 + c4 * 4];
        if (EPI == 2) {
            float4 rv = *(const float4*)(resid + (size_t)bz * M * NN +
                                         (size_t)(m0 + row) * NN + n0 + c4 * 4);
            v.x = fmaxf(v.x + rv.x, 0.f); v.y = fmaxf(v.y + rv.y, 0.f);
            v.z = fmaxf(v.z + rv.z, 0.f); v.w = fmaxf(v.w + rv.w, 0.f);
        }
        *(float4*)(Cp + (size_t)(m0 + row) * NN + n0 + c4 * 4) = v;
    }
    __syncthreads();
    if (wid == 0) TM_DEALLOC(tmem, 128);

#else  // ---------------- fp32 fallback (non-'a' compilation pass) ----------
    extern __shared__ char smem_raw[];
    float (*As)[132] = (float(*)[132])smem_raw;                 // [16][132]
    float (*Bs)[132] = (float(*)[132])(smem_raw + 16 * 132 * 4);

    const int bz = blockIdx.z;
    const int m0 = blockIdx.y * 128, n0 = blockIdx.x * 128;
    const float* Ap = A + (size_t)m0 * K;
    const float* Bp = XT + (size_t)bz * NN * K + (size_t)n0 * K;
    float* Cp = C + (size_t)bz * M * NN;
    const int t = threadIdx.x;
    const int tx = t & 15, ty = t >> 4;

    float acc[8][8];
#pragma unroll
    for (int i = 0; i < 8; i++)
#pragma unroll
        for (int j = 0; j < 8; j++) acc[i][j] = 0.f;

    for (int k0 = 0; k0 < K; k0 += 16) {
#pragma unroll
        for (int r = 0; r < 2; r++) {
            int i = t + r * 256, row = i >> 2, seg = i & 3;
            float4 v4 = *(const float4*)(Ap + (size_t)row * K + k0 + seg * 4);
            As[seg * 4 + 0][row] = v4.x; As[seg * 4 + 1][row] = v4.y;
            As[seg * 4 + 2][row] = v4.z; As[seg * 4 + 3][row] = v4.w;
        }
#pragma unroll
        for (int r = 0; r < 2; r++) {
            int i = t + r * 256, row = i >> 2, seg = i & 3;
            float4 v4 = *(const float4*)(Bp + (size_t)row * K + k0 + seg * 4);
            Bs[seg * 4 + 0][row] = v4.x; Bs[seg * 4 + 1][row] = v4.y;
            Bs[seg * 4 + 2][row] = v4.z; Bs[seg * 4 + 3][row] = v4.w;
        }
        __syncthreads();
#pragma unroll
        for (int kk = 0; kk < 16; kk++) {
            float a[8], b[8];
            *(float4*)&a[0] = *(const float4*)&As[kk][ty * 4];
            *(float4*)&a[4] = *(const float4*)&As[kk][64 + ty * 4];
            *(float4*)&b[0] = *(const float4*)&Bs[kk][tx * 4];
            *(float4*)&b[4] = *(const float4*)&Bs[kk][64 + tx * 4];
#pragma unroll
            for (int i = 0; i < 8; i++)
#pragma unroll
                for (int j = 0; j < 8; j++) acc[i][j] += a[i] * b[j];
        }
        __syncthreads();
    }

#pragma unroll
    for (int i = 0; i < 8; i++) {
        int m = m0 + ((i < 4) ? (ty * 4 + i) : (64 + ty * 4 + i - 4));
        float s = oscale, tt = 0.f;
        if (EPI) { s = g[m] * INVF; tt = cb[m] * s + beta[m]; }
#pragma unroll
        for (int h = 0; h < 2; h++) {
            int n = n0 + h * 64 + tx * 4;
            float4 rv = make_float4(0.f, 0.f, 0.f, 0.f);
            if (EPI == 2)
                rv = *(const float4*)(resid + (size_t)bz * M * NN + (size_t)m * NN + n);
            const float* pr = &rv.x;
            float vals[4];
#pragma unroll
            for (int j = 0; j < 4; j++) {
                float v = acc[i][h * 4 + j];
                if (EPI == 0) v *= oscale;
                else {
                    v = v * s + tt;
                    if (EPI == 2) v += pr[j];
                    v = fmaxf(v, 0.f);
                }
                vals[j] = v;
            }
            *(float4*)(Cp + (size_t)m * NN + n) =
                make_float4(vals[0], vals[1], vals[2], vals[3]);
        }
    }
#endif
}

// ---------------------------------------------------------------------------
// Fused stripe attention + residual + BN2 + ReLU (fp32)
// ---------------------------------------------------------------------------
#define ATTN_SMEM ((128 * 64 + 128 * 68 + 256 * 68 + 512) * 4)
#define LL 256

__global__ __launch_bounds__(256)
void attn_kernel(const float* __restrict__ q, const float* __restrict__ k,
                 const float* __restrict__ v, const float* __restrict__ out1,
                 const float* __restrict__ g2, const float* __restrict__ be2,
                 float* __restrict__ out2)
{
    extern __shared__ float sm[];
    float* Qs  = sm;                  // [dd][x]   128 x 64
    float* KVs = sm + 8192;           // [dd][y]   128 x 68
    float* St  = sm + 8192 + 8704;    // [y][x]    256 x 68
    float* red = St + 256 * 68;

    const int xt = blockIdx.x;
    const int sp = blockIdx.y >> 2;
    const int hh = blockIdx.y & 3;
    const int b  = blockIdx.z;
    const int t  = threadIdx.x;

    const size_t base = (size_t)b * PP * NN + (size_t)hh * DH * NN + (size_t)sp * LL;
    const float* qp = q + base + xt * 64;
    const float* kp = k + base;
    const float* vp = v + base;

#pragma unroll
    for (int r = 0; r < 8; r++) {
        int i = t + r * 256, row = i >> 4, seg = i & 15;
        *(float4*)&Qs[row * 64 + seg * 4] =
            *(const float4*)(qp + (size_t)row * NN + seg * 4);
    }

    const int xq = t & 15, yq = t >> 4;
    for (int yc = 0; yc < 4; yc++) {
        __syncthreads();
#pragma unroll
        for (int r = 0; r < 8; r++) {
            int i = t + r * 256, row = i >> 4, seg = i & 15;
            *(float4*)&KVs[row * 68 + seg * 4] =
                *(const float4*)(kp + (size_t)row * NN + yc * 64 + seg * 4);
        }
        __syncthreads();

        float acc[4][4];
#pragma unroll
        for (int yi = 0; yi < 4; yi++)
#pragma unroll
            for (int xi = 0; xi < 4; xi++) acc[yi][xi] = 0.f;

        for (int dd = 0; dd < 128; dd++) {
            float4 aq = *(const float4*)&Qs[dd * 64 + xq * 4];
            float4 bk = *(const float4*)&KVs[dd * 68 + yq * 4];
            acc[0][0] += bk.x * aq.x; acc[0][1] += bk.x * aq.y;
            acc[0][2] += bk.x * aq.z; acc[0][3] += bk.x * aq.w;
            acc[1][0] += bk.y * aq.x; acc[1][1] += bk.y * aq.y;
            acc[1][2] += bk.y * aq.z; acc[1][3] += bk.y * aq.w;
            acc[2][0] += bk.z * aq.x; acc[2][1] += bk.z * aq.y;
            acc[2][2] += bk.z * aq.z; acc[2][3] += bk.z * aq.w;
            acc[3][0] += bk.w * aq.x; acc[3][1] += bk.w * aq.y;
            acc[3][2] += bk.w * aq.z; acc[3][3] += bk.w * aq.w;
        }
#pragma unroll
        for (int yi = 0; yi < 4; yi++)
#pragma unroll
            for (int xi = 0; xi < 4; xi++)
                St[(yc * 64 + yq * 4 + yi) * 68 + xq * 4 + xi] = acc[yi][xi];
    }
    __syncthreads();

    {
        const int cx = t & 63;
        const int tg = t >> 6;
        float mx = -1e30f;
        for (int yy = tg * 64; yy < tg * 64 + 64; yy++)
            mx = fmaxf(mx, St[yy * 68 + cx]);
        red[tg * 64 + cx] = mx;
        __syncthreads();
        float M4 = fmaxf(fmaxf(red[cx], red[64 + cx]),
                         fmaxf(red[128 + cx], red[192 + cx]));
        float ssum = 0.f;
        for (int yy = tg * 64; yy < tg * 64 + 64; yy++) {
            float e = __expf(St[yy * 68 + cx] - M4);
            St[yy * 68 + cx] = e;
            ssum += e;
        }
        red[256 + tg * 64 + cx] = ssum;
        __syncthreads();
        float Sv = red[256 + cx] + red[256 + 64 + cx] +
                   red[256 + 128 + cx] + red[256 + 192 + cx];
        float inv = 1.f / Sv;
        for (int yy = tg * 64; yy < tg * 64 + 64; yy++)
            St[yy * 68 + cx] *= inv;
    }

    const int txd = t & 15, tyd = t >> 4;
    float acc2[8][4];
#pragma unroll
    for (int i = 0; i < 8; i++)
#pragma unroll
        for (int j = 0; j < 4; j++) acc2[i][j] = 0.f;

    for (int yc = 0; yc < 4; yc++) {
        __syncthreads();
#pragma unroll
        for (int r = 0; r < 8; r++) {
            int i = t + r * 256, row = i >> 4, seg = i & 15;
            *(float4*)&KVs[row * 68 + seg * 4] =
                *(const float4*)(vp + (size_t)row * NN + yc * 64 + seg * 4);
        }
        __syncthreads();

        for (int yi = 0; yi < 64; yi += 4) {
            int y = yc * 64 + yi;
            float4 p0 = *(const float4*)&St[(y + 0) * 68 + txd * 4];
            float4 p1 = *(const float4*)&St[(y + 1) * 68 + txd * 4];
            float4 p2 = *(const float4*)&St[(y + 2) * 68 + txd * 4];
            float4 p3 = *(const float4*)&St[(y + 3) * 68 + txd * 4];
#pragma unroll
            for (int i = 0; i < 8; i++) {
                float4 vv = *(const float4*)&KVs[(tyd * 8 + i) * 68 + yi];
                acc2[i][0] += vv.x * p0.x + vv.y * p1.x + vv.z * p2.x + vv.w * p3.x;
                acc2[i][1] += vv.x * p0.y + vv.y * p1.y + vv.z * p2.y + vv.w * p3.y;
                acc2[i][2] += vv.x * p0.z + vv.y * p1.z + vv.z * p2.z + vv.w * p3.z;
                acc2[i][3] += vv.x * p0.w + vv.y * p1.w + vv.z * p2.w + vv.w * p3.w;
            }
        }
    }

#pragma unroll
    for (int i = 0; i < 8; i++) {
        int dd = tyd * 8 + i;
        int p = hh * DH + dd;
        float s = g2[p] * INVF;
        float tt = be2[p];
        size_t idx = base + (size_t)dd * NN + xt * 64 + txd * 4;
        float4 o1v = *(const float4*)(out1 + idx);
        float4 o;
        o.x = fmaxf((acc2[i][0] + o1v.x) * s + tt, 0.f);
        o.y = fmaxf((acc2[i][1] + o1v.y) * s + tt, 0.f);
        o.z = fmaxf((acc2[i][2] + o1v.z) * s + tt, 0.f);
        o.w = fmaxf((acc2[i][3] + o1v.w) * s + tt, 0.f);
        *(float4*)(out2 + idx) = o;
    }
}

// ---------------------------------------------------------------------------
extern "C" void kernel_launch(void* const* d_in, const int* in_sizes, int n_in,
                              void* d_out, int out_size)
{
    const float* x   = (const float*)d_in[0];
    const float* w1  = (const float*)d_in[1];
    const float* b1  = (const float*)d_in[2];
    const float* g1  = (const float*)d_in[3];
    const float* be1 = (const float*)d_in[4];
    const float* wq  = (const float*)d_in[5];
    const float* wk  = (const float*)d_in[6];
    const float* wv  = (const float*)d_in[7];
    const float* g2  = (const float*)d_in[8];
    const float* be2 = (const float*)d_in[9];
    const float* w3  = (const float*)d_in[10];
    const float* b3  = (const float*)d_in[11];
    const float* g3  = (const float*)d_in[12];
    const float* be3 = (const float*)d_in[13];
    float* out = (float*)d_out;

    float *xT, *o1, *o1T, *qb, *kb, *vb, *o2, *o2T;
    cudaGetSymbolAddress((void**)&xT,  g_xT);
    cudaGetSymbolAddress((void**)&o1,  g_out1);
    cudaGetSymbolAddress((void**)&o1T, g_o1T);
    cudaGetSymbolAddress((void**)&qb,  g_q);
    cudaGetSymbolAddress((void**)&kb,  g_k);
    cudaGetSymbolAddress((void**)&vb,  g_v);
    cudaGetSymbolAddress((void**)&o2,  g_out2);
    cudaGetSymbolAddress((void**)&o2T, g_o2T);

    cudaFuncSetAttribute(tgemm<0>, cudaFuncAttributeMaxDynamicSharedMemorySize, GSMEM);
    cudaFuncSetAttribute(tgemm<1>, cudaFuncAttributeMaxDynamicSharedMemorySize, GSMEM);
    cudaFuncSetAttribute(tgemm<2>, cudaFuncAttributeMaxDynamicSharedMemorySize, GSMEM);
    cudaFuncSetAttribute(attn_kernel, cudaFuncAttributeMaxDynamicSharedMemorySize, ATTN_SMEM);

    // 0) xT[b][hw][c]
    transpose_k<<<dim3(64, 32, BB), 256>>>(x, xT, CIN, NN);
    // 1) out1 = relu(bn1(conv1(x)))        (tf32 tcgen05)
    tgemm<1><<<dim3(16, 4, BB), 256, GSMEM>>>(w1, xT, o1, g1, be1, b1, nullptr,
                                              PP, CIN, 1.f);
    // 1b) out1T
    transpose_k<<<dim3(64, 16, BB), 256>>>(o1, o1T, PP, NN);
    // 2) q/k/v projections (q pre-scaled)
    tgemm<0><<<dim3(16, 4, BB), 256, GSMEM>>>(wq, o1T, qb, nullptr, nullptr, nullptr,
                                              nullptr, PP, PP, QSCALE);
    tgemm<0><<<dim3(16, 4, BB), 256, GSMEM>>>(wk, o1T, kb, nullptr, nullptr, nullptr,
                                              nullptr, PP, PP, 1.f);
    tgemm<0><<<dim3(16, 4, BB), 256, GSMEM>>>(wv, o1T, vb, nullptr, nullptr, nullptr,
                                              nullptr, PP, PP, 1.f);
    // 3) attention + residual + bn2 + relu -> out2   (fp32)
    attn_kernel<<<dim3(4, 32, BB), 256, ATTN_SMEM>>>(qb, kb, vb, o1, g2, be2, o2);
    // 3b) out2T
    transpose_k<<<dim3(64, 16, BB), 256>>>(o2, o2T, PP, NN);
    // 4) out = relu(bn3(conv3(out2)) + x)
    tgemm<2><<<dim3(16, 8, BB), 256, GSMEM>>>(w3, o2T, out, g3, be3, b3, x,
                                              CIN, PP, 1.f);
}

// round 4
// speedup vs baseline: 3.5734x; 1.7095x over previous
#include <cuda_runtime.h>
#include <cstdint>

// Problem constants
#define BB 16
#define CIN 1024
#define PP 512
#define NN 2048          // H*W
#define DH 128           // head dim
#define INVF 0.99999500003749969f      // 1/sqrt(1+1e-5)
#define QSCALE 0.08838834764831843f    // 128^-0.5

#if defined(__CUDA_ARCH__) && (__CUDA_ARCH__ >= 1000) && \
    (defined(__CUDA_ARCH_FEAT_SM103_ALL) || defined(__CUDA_ARCH_FEAT_SM100_ALL) || \
     defined(__CUDA_ARCH_SPECIFIC__) || defined(__CUDA_ARCH_FAMILY_SPECIFIC__))
#define HAS_TCGEN05 1
#else
#define HAS_TCGEN05 0
#endif

// Scratch (device globals)
__device__ float g_xT [(size_t)BB * CIN * NN];   // [b][hw][c]
__device__ float g_o1T[(size_t)BB * PP * NN];    // [b][hw][p]
__device__ float g_qT [(size_t)BB * PP * NN];    // [b][hw][p]
__device__ float g_kT [(size_t)BB * PP * NN];    // [b][hw][p]
__device__ float g_v  [(size_t)BB * PP * NN];    // [b][p][hw]
__device__ float g_o2T[(size_t)BB * PP * NN];    // [b][hw][p]

// ---------------------------------------------------------------------------
__device__ __forceinline__ uint32_t smem_u32(const void* p) {
    uint32_t a;
    asm("{ .reg .u64 t; cvta.to.shared.u64 t, %1; cvt.u32.u64 %0, t; }"
        : "=r"(a) : "l"(p));
    return a;
}
#if HAS_TCGEN05
__device__ __forceinline__ uint32_t elect1() {
    uint32_t p;
    asm volatile("{ .reg .pred p; elect.sync _|p, 0xFFFFFFFF; selp.b32 %0,1,0,p; }"
                 : "=r"(p));
    return p;
}
__device__ __forceinline__ float to_tf32(float x) {
    float r; asm("cvt.rna.tf32.f32 %0, %1;" : "=f"(r) : "f"(x)); return r;
}
#define SW128(o) ((o) ^ ((((uint32_t)(o)) >> 3) & 0x70))

#define MBAR_INIT(a, c) \
    asm volatile("mbarrier.init.shared.b64 [%0], %1;" :: "r"(a), "r"(c) : "memory")

#define MBAR_WAIT(a, ph) do { \
    uint32_t _d; \
    asm volatile("{ .reg .pred p; mbarrier.try_wait.parity.acquire.cta.shared::cta.b64 p,[%1],%2; selp.b32 %0,1,0,p; }" \
                 : "=r"(_d) : "r"(a), "r"((uint32_t)(ph)) : "memory"); \
    if (!_d) { \
        asm volatile("{ .reg .pred P;\nLW_%=:\nmbarrier.try_wait.parity.acquire.cta.shared::cta.b64 P,[%0],%1,0x989680;\n@P bra.uni LD_%=;\nbra.uni LW_%=;\nLD_%=:\n}" \
                     :: "r"(a), "r"((uint32_t)(ph)) : "memory"); \
    } } while (0)

#define TM_ALLOC(sa, n) \
    asm volatile("tcgen05.alloc.cta_group::1.sync.aligned.shared::cta.b32 [%0], %1;" \
                 :: "r"(sa), "r"(n) : "memory")
#define TM_DEALLOC(t, n) \
    asm volatile("tcgen05.dealloc.cta_group::1.sync.aligned.b32 %0, %1;" :: "r"(t), "r"(n))
#define TM_COMMIT(mb) \
    asm volatile("tcgen05.commit.cta_group::1.mbarrier::arrive::one.shared::cluster.b64 [%0];" \
                 :: "r"(mb) : "memory")
#define TM_FENCE_AFTER()  asm volatile("tcgen05.fence::after_thread_sync;" ::: "memory")
#define TM_FENCE_BEFORE() asm volatile("tcgen05.fence::before_thread_sync;" ::: "memory")
#define TM_WAIT_LD()      asm volatile("tcgen05.wait::ld.sync.aligned;" ::: "memory")
#define TM_WAIT_ST()      asm volatile("tcgen05.wait::st.sync.aligned;" ::: "memory")
#define FENCE_ASYNC()     asm volatile("fence.proxy.async.shared::cta;" ::: "memory")

#define TM_LD_X32(r, addr) \
    asm volatile("tcgen05.ld.sync.aligned.32x32b.x32.b32 " \
        "{%0,%1,%2,%3,%4,%5,%6,%7,%8,%9,%10,%11,%12,%13,%14,%15," \
        "%16,%17,%18,%19,%20,%21,%22,%23,%24,%25,%26,%27,%28,%29,%30,%31}, [%32];" \
        : "=r"((r)[0]),"=r"((r)[1]),"=r"((r)[2]),"=r"((r)[3]), \
          "=r"((r)[4]),"=r"((r)[5]),"=r"((r)[6]),"=r"((r)[7]), \
          "=r"((r)[8]),"=r"((r)[9]),"=r"((r)[10]),"=r"((r)[11]), \
          "=r"((r)[12]),"=r"((r)[13]),"=r"((r)[14]),"=r"((r)[15]), \
          "=r"((r)[16]),"=r"((r)[17]),"=r"((r)[18]),"=r"((r)[19]), \
          "=r"((r)[20]),"=r"((r)[21]),"=r"((r)[22]),"=r"((r)[23]), \
          "=r"((r)[24]),"=r"((r)[25]),"=r"((r)[26]),"=r"((r)[27]), \
          "=r"((r)[28]),"=r"((r)[29]),"=r"((r)[30]),"=r"((r)[31]) \
        : "r"(addr))

#define TM_ST_X32(addr, r) \
    asm volatile("tcgen05.st.sync.aligned.32x32b.x32.b32 [%0], " \
        "{%1,%2,%3,%4,%5,%6,%7,%8,%9,%10,%11,%12,%13,%14,%15,%16," \
        "%17,%18,%19,%20,%21,%22,%23,%24,%25,%26,%27,%28,%29,%30,%31,%32};" \
        :: "r"(addr), \
           "r"((r)[0]),"r"((r)[1]),"r"((r)[2]),"r"((r)[3]), \
           "r"((r)[4]),"r"((r)[5]),"r"((r)[6]),"r"((r)[7]), \
           "r"((r)[8]),"r"((r)[9]),"r"((r)[10]),"r"((r)[11]), \
           "r"((r)[12]),"r"((r)[13]),"r"((r)[14]),"r"((r)[15]), \
           "r"((r)[16]),"r"((r)[17]),"r"((r)[18]),"r"((r)[19]), \
           "r"((r)[20]),"r"((r)[21]),"r"((r)[22]),"r"((r)[23]), \
           "r"((r)[24]),"r"((r)[25]),"r"((r)[26]),"r"((r)[27]), \
           "r"((r)[28]),"r"((r)[29]),"r"((r)[30]),"r"((r)[31]) \
        : "memory")

__device__ __forceinline__ uint64_t mkdesc(uint32_t addr) {
    return ((uint64_t)2 << 61) | ((uint64_t)1 << 46) | ((uint64_t)64 << 32) |
           ((uint64_t)1 << 16) | ((addr >> 4) & 0x3FFF);
}
__device__ __forceinline__ void mma_ss(uint32_t d, uint64_t ad, uint64_t bd,
                                       uint32_t id, uint32_t en) {
    asm volatile(
        "{ .reg .pred p; setp.ne.u32 p, %5, 0;\n\t"
        "tcgen05.mma.cta_group::1.kind::tf32 [%0], %1, %2, %3, {%4,%4,%4,%4}, p;\n\t}"
        :: "r"(d), "l"(ad), "l"(bd), "r"(id), "r"(0u), "r"(en) : "memory");
}
__device__ __forceinline__ void mma_ts(uint32_t d, uint32_t a, uint64_t bd,
                                       uint32_t id, uint32_t en) {
    asm volatile(
        "{ .reg .pred p; setp.ne.u32 p, %5, 0;\n\t"
        "tcgen05.mma.cta_group::1.kind::tf32 [%0], [%1], %2, %3, {%4,%4,%4,%4}, p;\n\t}"
        :: "r"(d), "r"(a), "l"(bd), "r"(id), "r"(0u), "r"(en) : "memory");
}
#define IDESC_128 ((1u << 4) | (2u << 7) | (2u << 10) | (16u << 17) | (8u << 24))
#define IDESC_256 ((1u << 4) | (2u << 7) | (2u << 10) | (32u << 17) | (8u << 24))
#endif  // HAS_TCGEN05

// ---------------------------------------------------------------------------
// Tiled transpose per batch: in[b][R][C] -> out[b][C][R]
// ---------------------------------------------------------------------------
__global__ __launch_bounds__(256)
void transpose_k(const float* __restrict__ in, float* __restrict__ out, int R, int C)
{
    __shared__ float tile[32][33];
    const int b = blockIdx.z;
    const float* ip = in + (size_t)b * R * C;
    float* op = out + (size_t)b * R * C;
    const int c0 = blockIdx.x * 32, r0 = blockIdx.y * 32;
    const int tx = threadIdx.x & 31, ty = threadIdx.x >> 5;
#pragma unroll
    for (int i = 0; i < 32; i += 8)
        tile[ty + i][tx] = ip[(size_t)(r0 + ty + i) * C + c0 + tx];
    __syncthreads();
#pragma unroll
    for (int i = 0; i < 32; i += 8)
        op[(size_t)(c0 + ty + i) * R + r0 + tx] = tile[tx][ty + i];
}

// ---------------------------------------------------------------------------
// tcgen05 tf32 batched GEMM:  C[bz] = A (MxK) @ XT[bz] (2048xK)^T
// TRANS=0: C[m][n] ; TRANS=1: C[n][m]
// EPI 0: acc*oscale ; 1: relu(acc*s+t) ; 2: relu(acc*s+t+resid)
// ---------------------------------------------------------------------------
#define GS_TM  0u
#define GS_MB  16u
#define GS_A0  1024u
#define GS_B0  (1024u + 16384u)
#define GS_A1  (1024u + 32768u)
#define GS_B1  (1024u + 49152u)
#define GSMEM  (1024 + 128 * 132 * 4)   // 68608

template <int EPI, int TRANS>
__global__ __launch_bounds__(256)
void tgemm(const float* __restrict__ A, const float* __restrict__ XT,
           float* __restrict__ C,
           const float* __restrict__ g, const float* __restrict__ beta,
           const float* __restrict__ cb, const float* __restrict__ resid,
           int M, int K, float oscale)
{
#if HAS_TCGEN05
    extern __shared__ char smem[];
    const uint32_t sbase = smem_u32(smem);
    const int t = threadIdx.x, wid = t >> 5, lane = t & 31;
    const int bz = blockIdx.z;
    const int m0 = blockIdx.y * 128, n0 = blockIdx.x * 128;
    const float* Ap = A + (size_t)m0 * K;
    const float* Bp = XT + (size_t)bz * NN * K + (size_t)n0 * K;

    if (t == 0) { MBAR_INIT(sbase + GS_MB, 1); MBAR_INIT(sbase + GS_MB + 8, 1); }
    if (wid == 0) TM_ALLOC(sbase + GS_TM, 128);
    __syncthreads();
    uint32_t tmem;
    asm volatile("ld.shared.b32 %0, [%1];" : "=r"(tmem) : "r"(sbase + GS_TM));

    const uint32_t offA[2] = {GS_A0, GS_A1};
    const uint32_t offB[2] = {GS_B0, GS_B1};
    const int nk = K >> 5;

    // register prefetch of chunk 0
    float4 av[4], bv[4];
#pragma unroll
    for (int r = 0; r < 4; r++) {
        int idx = t + r * 256, row = idx >> 3, seg = idx & 7;
        av[r] = *(const float4*)(Ap + (size_t)row * K + seg * 4);
        bv[r] = *(const float4*)(Bp + (size_t)row * K + seg * 4);
    }

    for (int c = 0; c < nk; c++) {
        const int buf = c & 1;
        const uint32_t mb = sbase + GS_MB + 8 * buf;
        if (c >= 2) MBAR_WAIT(mb, ((c >> 1) - 1) & 1);

#pragma unroll
        for (int r = 0; r < 4; r++) {
            int idx = t + r * 256, row = idx >> 3, seg = idx & 7;
            float4 v = av[r];
            v.x = to_tf32(v.x); v.y = to_tf32(v.y);
            v.z = to_tf32(v.z); v.w = to_tf32(v.w);
            *(float4*)(smem + offA[buf] + SW128(row * 128 + seg * 16)) = v;
            v = bv[r];
            v.x = to_tf32(v.x); v.y = to_tf32(v.y);
            v.z = to_tf32(v.z); v.w = to_tf32(v.w);
            *(float4*)(smem + offB[buf] + SW128(row * 128 + seg * 16)) = v;
        }
        if (c + 1 < nk) {
#pragma unroll
            for (int r = 0; r < 4; r++) {
                int idx = t + r * 256, row = idx >> 3, seg = idx & 7;
                av[r] = *(const float4*)(Ap + (size_t)row * K + (c + 1) * 32 + seg * 4);
                bv[r] = *(const float4*)(Bp + (size_t)row * K + (c + 1) * 32 + seg * 4);
            }
        }
        __syncthreads();

        if (wid == 0) {
            if (elect1()) {
                FENCE_ASYNC();
                uint64_t ad = mkdesc(sbase + offA[buf]);
                uint64_t bd = mkdesc(sbase + offB[buf]);
#pragma unroll
                for (int s = 0; s < 4; s++)
                    mma_ss(tmem, ad + s * 2, bd + s * 2, IDESC_128,
                           (c > 0 || s > 0) ? 1u : 0u);
                TM_COMMIT(mb);
            }
        }
    }
    {
        const int cl = nk - 1;
        MBAR_WAIT(sbase + GS_MB + 8 * (cl & 1), (cl >> 1) & 1);
    }
    TM_FENCE_AFTER();

    // Epilogue: LDTM -> per-row math -> smem staging -> coalesced STG
    const int sp = wid & 3, ch = wid >> 2;
    uint32_t r0[32], r1[32];
    TM_LD_X32(r0, tmem + ch * 64);
    TM_LD_X32(r1, tmem + ch * 64 + 32);
    TM_WAIT_LD();

    const int ml = sp * 32 + lane;
    const int m = m0 + ml;
    float s = oscale, tt = 0.f;
    if (EPI) { s = g[m] * INVF; tt = cb[m] * s + beta[m]; }
    float* stg = (float*)(smem + 1024);
#pragma unroll
    for (int i = 0; i < 32; i++) {
        float v0 = fmaf(__uint_as_float(r0[i]), s, tt);
        float v1 = fmaf(__uint_as_float(r1[i]), s, tt);
        if (EPI == 1) { v0 = fmaxf(v0, 0.f); v1 = fmaxf(v1, 0.f); }
        if (TRANS) {
            stg[(ch * 64 + i) * 132 + ml]      = v0;
            stg[(ch * 64 + 32 + i) * 132 + ml] = v1;
        } else {
            stg[ml * 132 + ch * 64 + i]      = v0;
            stg[ml * 132 + ch * 64 + 32 + i] = v1;
        }
    }
    __syncthreads();

    if (TRANS) {
        float* Ct = C + (size_t)bz * NN * M;
#pragma unroll
        for (int rr = 0; rr < 16; rr++) {
            int nn = rr * 8 + wid;
            float4 v = *(float4*)&stg[nn * 132 + lane * 4];
            *(float4*)(Ct + (size_t)(n0 + nn) * M + m0 + lane * 4) = v;
        }
    } else {
        float* Cp = C + (size_t)bz * M * NN;
#pragma unroll
        for (int rr = 0; rr < 16; rr++) {
            int row = rr * 8 + wid;
            float4 v = *(float4*)&stg[row * 132 + lane * 4];
            if (EPI == 2) {
                float4 rv = *(const float4*)(resid + (size_t)bz * M * NN +
                                             (size_t)(m0 + row) * NN + n0 + lane * 4);
                v.x = fmaxf(v.x + rv.x, 0.f); v.y = fmaxf(v.y + rv.y, 0.f);
                v.z = fmaxf(v.z + rv.z, 0.f); v.w = fmaxf(v.w + rv.w, 0.f);
            }
            *(float4*)(Cp + (size_t)(m0 + row) * NN + n0 + lane * 4) = v;
        }
    }
    __syncthreads();
    if (wid == 0) TM_DEALLOC(tmem, 128);

#else  // ---------------- fp32 fallback (never runs on GB300) ---------------
    extern __shared__ char smem_raw[];
    float (*As)[132] = (float(*)[132])smem_raw;
    float (*Bs)[132] = (float(*)[132])(smem_raw + 16 * 132 * 4);
    const int bz = blockIdx.z;
    const int m0 = blockIdx.y * 128, n0 = blockIdx.x * 128;
    const float* Ap = A + (size_t)m0 * K;
    const float* Bp = XT + (size_t)bz * NN * K + (size_t)n0 * K;
    const int t = threadIdx.x, tx = t & 15, ty = t >> 4;
    float acc[8][8];
#pragma unroll
    for (int i = 0; i < 8; i++)
#pragma unroll
        for (int j = 0; j < 8; j++) acc[i][j] = 0.f;
    for (int k0 = 0; k0 < K; k0 += 16) {
#pragma unroll
        for (int r = 0; r < 2; r++) {
            int i = t + r * 256, row = i >> 2, seg = i & 3;
            float4 v4 = *(const float4*)(Ap + (size_t)row * K + k0 + seg * 4);
            As[seg * 4 + 0][row] = v4.x; As[seg * 4 + 1][row] = v4.y;
            As[seg * 4 + 2][row] = v4.z; As[seg * 4 + 3][row] = v4.w;
            v4 = *(const float4*)(Bp + (size_t)row * K + k0 + seg * 4);
            Bs[seg * 4 + 0][row] = v4.x; Bs[seg * 4 + 1][row] = v4.y;
            Bs[seg * 4 + 2][row] = v4.z; Bs[seg * 4 + 3][row] = v4.w;
        }
        __syncthreads();
#pragma unroll
        for (int kk = 0; kk < 16; kk++) {
            float a[8], b[8];
            *(float4*)&a[0] = *(const float4*)&As[kk][ty * 4];
            *(float4*)&a[4] = *(const float4*)&As[kk][64 + ty * 4];
            *(float4*)&b[0] = *(const float4*)&Bs[kk][tx * 4];
            *(float4*)&b[4] = *(const float4*)&Bs[kk][64 + tx * 4];
#pragma unroll
            for (int i = 0; i < 8; i++)
#pragma unroll
                for (int j = 0; j < 8; j++) acc[i][j] += a[i] * b[j];
        }
        __syncthreads();
    }
#pragma unroll
    for (int i = 0; i < 8; i++) {
        int m = m0 + ((i < 4) ? (ty * 4 + i) : (64 + ty * 4 + i - 4));
        float s = oscale, tt = 0.f;
        if (EPI) { s = g[m] * INVF; tt = cb[m] * s + beta[m]; }
#pragma unroll
        for (int h = 0; h < 2; h++) {
            int n = n0 + h * 64 + tx * 4;
#pragma unroll
            for (int j = 0; j < 4; j++) {
                float v = acc[i][h * 4 + j];
                if (EPI == 0) v *= oscale;
                else {
                    v = v * s + tt;
                    if (EPI == 2)
                        v += resid[(size_t)bz * M * NN + (size_t)m * NN + n + j];
                    v = fmaxf(v, 0.f);
                }
                if (TRANS) C[(size_t)bz * NN * M + (size_t)(n + j) * M + m] = v;
                else       C[(size_t)bz * M * NN + (size_t)m * NN + n + j] = v;
            }
        }
    }
#endif
}

// ---------------------------------------------------------------------------
// tcgen05 attention: per (xt, sp, head, b) block of 128 queries x 256 keys.
// S = Q.K^T (SS tf32, TMEM cols 0..255), row softmax from TMEM (lane = query),
// P unnormalized in TMEM as TS A operand, O = P.V (cols 256..383).
// Epilogue: o2T[x][p] = relu(((O/sum) + o1T) * g2*INVF + be2)   (native layout)
// smem: hdr 2KB + Q 64KB + 2x32KB KV buffers = 133120 B
// ---------------------------------------------------------------------------
#define AS_Q   2048u
#define AS_KV0 (2048u + 65536u)
#define AS_KV1 (2048u + 65536u + 32768u)
#define ASMEM  133120

__global__ __launch_bounds__(128)
void attn_tc(const float* __restrict__ qT, const float* __restrict__ kT,
             const float* __restrict__ v, const float* __restrict__ o1T,
             const float* __restrict__ g2, const float* __restrict__ be2,
             float* __restrict__ o2T)
{
    extern __shared__ char sm[];
    const int t = threadIdx.x, wid = t >> 5, lane = t & 31;
    const int xt = blockIdx.x;
    const int sp = blockIdx.y >> 2, hh = blockIdx.y & 3;
    const int b = blockIdx.z;

    const size_t qrow = (size_t)b * NN + sp * 256 + xt * 128;
    const float* qp  = qT  + qrow * PP + hh * DH;
    const float* kp  = kT  + ((size_t)b * NN + sp * 256) * PP + hh * DH;
    const float* vp  = v   + ((size_t)b * PP + hh * DH) * NN + sp * 256;
    const float* o1p = o1T + qrow * PP + hh * DH;
    float* o2p       = o2T + qrow * PP + hh * DH;

#if HAS_TCGEN05
    const uint32_t sbase = smem_u32(sm);
    if (t == 0) { MBAR_INIT(sbase + 16, 1); MBAR_INIT(sbase + 24, 1); }
    if (wid == 0) TM_ALLOC(sbase + 0, 512);
    ((float*)(sm + 1024))[t] = g2[hh * DH + t] * INVF;
    ((float*)(sm + 1536))[t] = be2[hh * DH + t];
    __syncthreads();
    uint32_t tmem;
    asm volatile("ld.shared.b32 %0, [%1];" : "=r"(tmem) : "r"(sbase + 0));
    const uint32_t kvoff[2] = {AS_KV0, AS_KV1};

    // ---- load Q tile [128 x][128 d] into 4 d-chunk atoms ----
#pragma unroll
    for (int r = 0; r < 32; r++) {
        int i = t + r * 128;
        int row = i >> 5, rem = i & 31, j = rem >> 3, seg = rem & 7;
        float4 vq = *(const float4*)(qp + (size_t)row * PP + j * 32 + seg * 4);
        *(float4*)(sm + AS_Q + j * 16384 + SW128(row * 128 + seg * 16)) = vq;
    }

    // ---- S = Q.K^T over 4 d-chunks, double-buffered K ----
    float4 kv[16];
#pragma unroll
    for (int r = 0; r < 16; r++) {
        int i = t + r * 128, row = i >> 3, seg = i & 7;
        kv[r] = *(const float4*)(kp + (size_t)row * PP + seg * 4);
    }
    for (int c = 0; c < 4; c++) {
        const int buf = c & 1;
        const uint32_t mb = sbase + 16 + 8 * buf;
        if (c >= 2) MBAR_WAIT(mb, 0);   // 1st commit on this buffer
#pragma unroll
        for (int r = 0; r < 16; r++) {
            int i = t + r * 128, row = i >> 3, seg = i & 7;
            *(float4*)(sm + kvoff[buf] + SW128(row * 128 + seg * 16)) = kv[r];
        }
        if (c < 3) {
#pragma unroll
            for (int r = 0; r < 16; r++) {
                int i = t + r * 128, row = i >> 3, seg = i & 7;
                kv[r] = *(const float4*)(kp + (size_t)row * PP + (c + 1) * 32 + seg * 4);
            }
        }
        __syncthreads();
        if (wid == 0 && elect1()) {
            FENCE_ASYNC();
            uint64_t qd = mkdesc(sbase + AS_Q + c * 16384);
            uint64_t kd = mkdesc(sbase + kvoff[buf]);
#pragma unroll
            for (int s = 0; s < 4; s++)
                mma_ss(tmem, qd + s * 2, kd + s * 2, IDESC_256,
                       (c > 0 || s > 0) ? 1u : 0u);
            TM_COMMIT(mb);
        }
    }
    MBAR_WAIT(sbase + 24, 1);   // 2nd commit on mb1 = last S MMA done
    TM_FENCE_AFTER();

    // ---- softmax over 256 keys; lane = query row. P unnormalized. ----
    uint32_t rs[32];
    float mx = -1e30f;
#pragma unroll
    for (int cc = 0; cc < 8; cc++) {
        TM_LD_X32(rs, tmem + cc * 32);
        TM_WAIT_LD();
#pragma unroll
        for (int i = 0; i < 32; i++) mx = fmaxf(mx, __uint_as_float(rs[i]));
    }
    float ssum = 0.f;
#pragma unroll
    for (int cc = 0; cc < 8; cc++) {
        TM_LD_X32(rs, tmem + cc * 32);
        TM_WAIT_LD();
#pragma unroll
        for (int i = 0; i < 32; i++) {
            float e = __expf(__uint_as_float(rs[i]) - mx);
            ssum += e;
            rs[i] = __float_as_uint(e);
        }
        TM_ST_X32(tmem + cc * 32, rs);
    }
    TM_WAIT_ST();
    const float sinv = 1.f / ssum;
    TM_FENCE_BEFORE();

    // ---- O = P.V over 4 y-chunks of 64 (TS mode, A=P in TMEM) ----
#pragma unroll
    for (int r = 0; r < 16; r++) {
        int i = t + r * 128, row = i >> 4, seg = i & 15;
        kv[r] = *(const float4*)(vp + (size_t)row * NN + seg * 4);
    }
    for (int j = 0; j < 4; j++) {
        const int buf = j & 1;
        const uint32_t mb = sbase + 16 + 8 * buf;
        if (j >= 2) MBAR_WAIT(mb, 0);   // 3rd commit on this buffer
#pragma unroll
        for (int r = 0; r < 16; r++) {
            int i = t + r * 128, row = i >> 4, seg = i & 15;
            *(float4*)(sm + kvoff[buf] + (seg >> 3) * 16384 +
                       SW128(row * 128 + (seg & 7) * 16)) = kv[r];
        }
        if (j < 3) {
#pragma unroll
            for (int r = 0; r < 16; r++) {
                int i = t + r * 128, row = i >> 4, seg = i & 15;
                kv[r] = *(const float4*)(vp + (size_t)row * NN + (j + 1) * 64 + seg * 4);
            }
        }
        __syncthreads();
        if (wid == 0 && elect1()) {
            FENCE_ASYNC();
            TM_FENCE_AFTER();
            uint64_t vd = mkdesc(sbase + kvoff[buf]);
#pragma unroll
            for (int s = 0; s < 8; s++)
                mma_ts(tmem + 256, tmem + j * 64 + s * 8,
                       vd + (s >> 2) * 1024 + (s & 3) * 2, IDESC_128,
                       (j > 0 || s > 0) ? 1u : 0u);
            TM_COMMIT(mb);
        }
    }
    MBAR_WAIT(sbase + 24, 1);   // 4th commit on mb1 = last PV MMA done
    TM_FENCE_AFTER();

    // ---- epilogue: (O*sinv + o1)*g2' + be2, relu -> o2T (native rows) ----
    const float* g2s  = (const float*)(sm + 1024);
    const float* be2s = (const float*)(sm + 1536);
    const float* myo1 = o1p + (size_t)(wid * 32 + lane) * PP;
    float* myo2       = o2p + (size_t)(wid * 32 + lane) * PP;
#pragma unroll
    for (int k = 0; k < 4; k++) {
        TM_LD_X32(rs, tmem + 256 + k * 32);
        TM_WAIT_LD();
#pragma unroll
        for (int i = 0; i < 32; i += 4) {
            int d = k * 32 + i;
            float4 r1 = *(const float4*)(myo1 + d);
            float4 o;
            o.x = fmaxf(fmaf(fmaf(__uint_as_float(rs[i + 0]), sinv, r1.x), g2s[d + 0], be2s[d + 0]), 0.f);
            o.y = fmaxf(fmaf(fmaf(__uint_as_float(rs[i + 1]), sinv, r1.y), g2s[d + 1], be2s[d + 1]), 0.f);
            o.z = fmaxf(fmaf(fmaf(__uint_as_float(rs[i + 2]), sinv, r1.z), g2s[d + 2], be2s[d + 2]), 0.f);
            o.w = fmaxf(fmaf(fmaf(__uint_as_float(rs[i + 3]), sinv, r1.w), g2s[d + 3], be2s[d + 3]), 0.f);
            *(float4*)(myo2 + d) = o;
        }
    }
    __syncthreads();
    if (wid == 0) TM_DEALLOC(tmem, 512);

#else  // ---------------- fp32 fallback (never runs on GB300) ---------------
    const int x = t;   // 128 threads = 128 query rows
    float sb[256];
    float mx = -1e30f;
    for (int y = 0; y < 256; y++) {
        float s = 0.f;
        for (int d = 0; d < DH; d++)
            s += qp[(size_t)x * PP + d] * kp[(size_t)y * PP + d];
        sb[y] = s;
        mx = fmaxf(mx, s);
    }
    float ssum = 0.f;
    for (int y = 0; y < 256; y++) { sb[y] = __expf(sb[y] - mx); ssum += sb[y]; }
    float sinv = 1.f / ssum;
    for (int d = 0; d < DH; d++) {
        float o = 0.f;
        for (int y = 0; y < 256; y++) o += sb[y] * vp[(size_t)d * NN + y];
        float val = (o * sinv + o1p[(size_t)x * PP + d]) * (g2[hh * DH + d] * INVF)
                    + be2[hh * DH + d];
        o2p[(size_t)x * PP + d] = fmaxf(val, 0.f);
    }
#endif
}

// ---------------------------------------------------------------------------
extern "C" void kernel_launch(void* const* d_in, const int* in_sizes, int n_in,
                              void* d_out, int out_size)
{
    const float* x   = (const float*)d_in[0];
    const float* w1  = (const float*)d_in[1];
    const float* b1  = (const float*)d_in[2];
    const float* g1  = (const float*)d_in[3];
    const float* be1 = (const float*)d_in[4];
    const float* wq  = (const float*)d_in[5];
    const float* wk  = (const float*)d_in[6];
    const float* wv  = (const float*)d_in[7];
    const float* g2  = (const float*)d_in[8];
    const float* be2 = (const float*)d_in[9];
    const float* w3  = (const float*)d_in[10];
    const float* b3  = (const float*)d_in[11];
    const float* g3  = (const float*)d_in[12];
    const float* be3 = (const float*)d_in[13];
    float* out = (float*)d_out;

    float *xT, *o1T, *qT, *kT, *vb, *o2T;
    cudaGetSymbolAddress((void**)&xT,  g_xT);
    cudaGetSymbolAddress((void**)&o1T, g_o1T);
    cudaGetSymbolAddress((void**)&qT,  g_qT);
    cudaGetSymbolAddress((void**)&kT,  g_kT);
    cudaGetSymbolAddress((void**)&vb,  g_v);
    cudaGetSymbolAddress((void**)&o2T, g_o2T);

    cudaFuncSetAttribute((const void*)tgemm<0,0>, cudaFuncAttributeMaxDynamicSharedMemorySize, GSMEM);
    cudaFuncSetAttribute((const void*)tgemm<0,1>, cudaFuncAttributeMaxDynamicSharedMemorySize, GSMEM);
    cudaFuncSetAttribute((const void*)tgemm<1,1>, cudaFuncAttributeMaxDynamicSharedMemorySize, GSMEM);
    cudaFuncSetAttribute((const void*)tgemm<2,0>, cudaFuncAttributeMaxDynamicSharedMemorySize, GSMEM);
    cudaFuncSetAttribute((const void*)attn_tc, cudaFuncAttributeMaxDynamicSharedMemorySize, ASMEM);

    // 0) xT[b][hw][c]
    transpose_k<<<dim3(64, 32, BB), 256>>>(x, xT, CIN, NN);
    // 1) o1T = relu(bn1(conv1(x)))^T   [b][hw][p]
    tgemm<1,1><<<dim3(16, 4, BB), 256, GSMEM>>>(w1, xT, o1T, g1, be1, b1, nullptr,
                                                PP, CIN, 1.f);
    // 2) projections: qT,kT transposed; v normal
    tgemm<0,1><<<dim3(16, 4, BB), 256, GSMEM>>>(wq, o1T, qT, nullptr, nullptr, nullptr,
                                                nullptr, PP, PP, QSCALE);
    tgemm<0,1><<<dim3(16, 4, BB), 256, GSMEM>>>(wk, o1T, kT, nullptr, nullptr, nullptr,
                                                nullptr, PP, PP, 1.f);
    tgemm<0,0><<<dim3(16, 4, BB), 256, GSMEM>>>(wv, o1T, vb, nullptr, nullptr, nullptr,
                                                nullptr, PP, PP, 1.f);
    // 3) attention + residual + bn2 + relu -> o2T [b][hw][p]
    attn_tc<<<dim3(2, 32, BB), 128, ASMEM>>>(qT, kT, vb, o1T, g2, be2, o2T);
    // 4) out = relu(bn3(conv3) + x)
    tgemm<2,0><<<dim3(16, 8, BB), 256, GSMEM>>>(w3, o2T, out, g3, be3, b3, x,
                                                CIN, PP, 1.f);
}

// round 6
// speedup vs baseline: 5.1697x; 1.4467x over previous
#include <cuda_runtime.h>
#include <cstdint>

// Problem constants
#define BB 16
#define CIN 1024
#define PP 512
#define NN 2048          // H*W
#define DH 128           // head dim
#define INVF 0.99999500003749969f      // 1/sqrt(1+1e-5)
#define QSCALE 0.08838834764831843f    // 128^-0.5

#if defined(__CUDA_ARCH__) && (__CUDA_ARCH__ >= 1000) && \
    (defined(__CUDA_ARCH_FEAT_SM103_ALL) || defined(__CUDA_ARCH_FEAT_SM100_ALL) || \
     defined(__CUDA_ARCH_SPECIFIC__) || defined(__CUDA_ARCH_FAMILY_SPECIFIC__))
#define HAS_TCGEN05 1
#else
#define HAS_TCGEN05 0
#endif

// Scratch (device globals)
__device__ float g_xT [(size_t)BB * CIN * NN];   // [b][hw][c]  (tf32-rounded)
__device__ float g_o1T[(size_t)BB * PP * NN];    // [b][hw][p]  (tf32-rounded)
__device__ float g_qT [(size_t)BB * PP * NN];    // [b][hw][p]  (tf32-rounded)
__device__ float g_kT [(size_t)BB * PP * NN];    // [b][hw][p]  (tf32-rounded)
__device__ float g_v  [(size_t)BB * PP * NN];    // [b][p][hw]  (tf32-rounded)
__device__ float g_o2T[(size_t)BB * PP * NN];    // [b][hw][p]  (tf32-rounded)
// Rounded weights: w1 | wq | wk | wv | w3
#define WR_W1 0
#define WR_WQ (512 * 1024)
#define WR_WK (WR_WQ + 512 * 512)
#define WR_WV (WR_WK + 512 * 512)
#define WR_W3 (WR_WV + 512 * 512)
__device__ float g_wr[WR_W3 + 1024 * 512];

// ---------------------------------------------------------------------------
__device__ __forceinline__ uint32_t smem_u32(const void* p) {
    uint32_t a;
    asm("{ .reg .u64 t; cvta.to.shared.u64 t, %1; cvt.u32.u64 %0, t; }"
        : "=r"(a) : "l"(p));
    return a;
}
__device__ __forceinline__ float to_tf32(float x) {
    float r; asm("cvt.rna.tf32.f32 %0, %1;" : "=f"(r) : "f"(x)); return r;
}

#if HAS_TCGEN05
__device__ __forceinline__ uint32_t elect1() {
    uint32_t p;
    asm volatile("{ .reg .pred p; elect.sync _|p, 0xFFFFFFFF; selp.b32 %0,1,0,p; }"
                 : "=r"(p));
    return p;
}
#define SW128(o) ((o) ^ ((((uint32_t)(o)) >> 3) & 0x70))

#define MBAR_INIT(a, c) \
    asm volatile("mbarrier.init.shared.b64 [%0], %1;" :: "r"(a), "r"(c) : "memory")

#define MBAR_WAIT(a, ph) do { \
    uint32_t _d; \
    asm volatile("{ .reg .pred p; mbarrier.try_wait.parity.acquire.cta.shared::cta.b64 p,[%1],%2; selp.b32 %0,1,0,p; }" \
                 : "=r"(_d) : "r"(a), "r"((uint32_t)(ph)) : "memory"); \
    if (!_d) { \
        asm volatile("{ .reg .pred P;\nLW_%=:\nmbarrier.try_wait.parity.acquire.cta.shared::cta.b64 P,[%0],%1,0x989680;\n@P bra.uni LD_%=;\nbra.uni LW_%=;\nLD_%=:\n}" \
                     :: "r"(a), "r"((uint32_t)(ph)) : "memory"); \
    } } while (0)

#define TM_ALLOC(sa, n) \
    asm volatile("tcgen05.alloc.cta_group::1.sync.aligned.shared::cta.b32 [%0], %1;" \
                 :: "r"(sa), "r"(n) : "memory")
#define TM_DEALLOC(t, n) \
    asm volatile("tcgen05.dealloc.cta_group::1.sync.aligned.b32 %0, %1;" :: "r"(t), "r"(n))
#define TM_COMMIT(mb) \
    asm volatile("tcgen05.commit.cta_group::1.mbarrier::arrive::one.shared::cluster.b64 [%0];" \
                 :: "r"(mb) : "memory")
#define TM_FENCE_AFTER()  asm volatile("tcgen05.fence::after_thread_sync;" ::: "memory")
#define TM_FENCE_BEFORE() asm volatile("tcgen05.fence::before_thread_sync;" ::: "memory")
#define TM_WAIT_LD()      asm volatile("tcgen05.wait::ld.sync.aligned;" ::: "memory")
#define TM_WAIT_ST()      asm volatile("tcgen05.wait::st.sync.aligned;" ::: "memory")
#define FENCE_ASYNC()     asm volatile("fence.proxy.async.shared::cta;" ::: "memory")

#define CP_ASYNC16(dst, src) \
    asm volatile("cp.async.cg.shared.global [%0], [%1], 16;" \
                 :: "r"(dst), "l"(src) : "memory")
#define CP_COMMIT() asm volatile("cp.async.commit_group;" ::: "memory")
#define CP_WAIT(n)  asm volatile("cp.async.wait_group %0;" :: "n"(n) : "memory")

#define TM_LD_X32(r, addr) \
    asm volatile("tcgen05.ld.sync.aligned.32x32b.x32.b32 " \
        "{%0,%1,%2,%3,%4,%5,%6,%7,%8,%9,%10,%11,%12,%13,%14,%15," \
        "%16,%17,%18,%19,%20,%21,%22,%23,%24,%25,%26,%27,%28,%29,%30,%31}, [%32];" \
        : "=r"((r)[0]),"=r"((r)[1]),"=r"((r)[2]),"=r"((r)[3]), \
          "=r"((r)[4]),"=r"((r)[5]),"=r"((r)[6]),"=r"((r)[7]), \
          "=r"((r)[8]),"=r"((r)[9]),"=r"((r)[10]),"=r"((r)[11]), \
          "=r"((r)[12]),"=r"((r)[13]),"=r"((r)[14]),"=r"((r)[15]), \
          "=r"((r)[16]),"=r"((r)[17]),"=r"((r)[18]),"=r"((r)[19]), \
          "=r"((r)[20]),"=r"((r)[21]),"=r"((r)[22]),"=r"((r)[23]), \
          "=r"((r)[24]),"=r"((r)[25]),"=r"((r)[26]),"=r"((r)[27]), \
          "=r"((r)[28]),"=r"((r)[29]),"=r"((r)[30]),"=r"((r)[31]) \
        : "r"(addr))

#define TM_ST_X32(addr, r) \
    asm volatile("tcgen05.st.sync.aligned.32x32b.x32.b32 [%0], " \
        "{%1,%2,%3,%4,%5,%6,%7,%8,%9,%10,%11,%12,%13,%14,%15,%16," \
        "%17,%18,%19,%20,%21,%22,%23,%24,%25,%26,%27,%28,%29,%30,%31,%32};" \
        :: "r"(addr), \
           "r"((r)[0]),"r"((r)[1]),"r"((r)[2]),"r"((r)[3]), \
           "r"((r)[4]),"r"((r)[5]),"r"((r)[6]),"r"((r)[7]), \
           "r"((r)[8]),"r"((r)[9]),"r"((r)[10]),"r"((r)[11]), \
           "r"((r)[12]),"r"((r)[13]),"r"((r)[14]),"r"((r)[15]), \
           "r"((r)[16]),"r"((r)[17]),"r"((r)[18]),"r"((r)[19]), \
           "r"((r)[20]),"r"((r)[21]),"r"((r)[22]),"r"((r)[23]), \
           "r"((r)[24]),"r"((r)[25]),"r"((r)[26]),"r"((r)[27]), \
           "r"((r)[28]),"r"((r)[29]),"r"((r)[30]),"r"((r)[31]) \
        : "memory")

__device__ __forceinline__ uint64_t mkdesc(uint32_t addr) {
    return ((uint64_t)2 << 61) | ((uint64_t)1 << 46) | ((uint64_t)64 << 32) |
           ((uint64_t)1 << 16) | ((addr >> 4) & 0x3FFF);
}
__device__ __forceinline__ void mma_ss(uint32_t d, uint64_t ad, uint64_t bd,
                                       uint32_t id, uint32_t en) {
    asm volatile(
        "{ .reg .pred p; setp.ne.u32 p, %5, 0;\n\t"
        "tcgen05.mma.cta_group::1.kind::tf32 [%0], %1, %2, %3, {%4,%4,%4,%4}, p;\n\t}"
        :: "r"(d), "l"(ad), "l"(bd), "r"(id), "r"(0u), "r"(en) : "memory");
}
__device__ __forceinline__ void mma_ts(uint32_t d, uint32_t a, uint64_t bd,
                                       uint32_t id, uint32_t en) {
    asm volatile(
        "{ .reg .pred p; setp.ne.u32 p, %5, 0;\n\t"
        "tcgen05.mma.cta_group::1.kind::tf32 [%0], [%1], %2, %3, {%4,%4,%4,%4}, p;\n\t}"
        :: "r"(d), "r"(a), "l"(bd), "r"(id), "r"(0u), "r"(en) : "memory");
}
#define IDESC_128 ((1u << 4) | (2u << 7) | (2u << 10) | (16u << 17) | (8u << 24))
#define IDESC_256 ((1u << 4) | (2u << 7) | (2u << 10) | (32u << 17) | (8u << 24))
#endif  // HAS_TCGEN05

// ---------------------------------------------------------------------------
// Round weights to tf32 (one-time pre-pass)
// ---------------------------------------------------------------------------
__global__ __launch_bounds__(256)
void round_w(const float* __restrict__ in, float* __restrict__ out, int n4)
{
    int i = blockIdx.x * 256 + threadIdx.x;
    if (i < n4) {
        float4 v = ((const float4*)in)[i];
        v.x = to_tf32(v.x); v.y = to_tf32(v.y);
        v.z = to_tf32(v.z); v.w = to_tf32(v.w);
        ((float4*)out)[i] = v;
    }
}

// ---------------------------------------------------------------------------
// Tiled transpose per batch with tf32 rounding: in[b][R][C] -> out[b][C][R]
// ---------------------------------------------------------------------------
__global__ __launch_bounds__(256)
void transpose_k(const float* __restrict__ in, float* __restrict__ out, int R, int C)
{
    __shared__ float tile[32][33];
    const int b = blockIdx.z;
    const float* ip = in + (size_t)b * R * C;
    float* op = out + (size_t)b * R * C;
    const int c0 = blockIdx.x * 32, r0 = blockIdx.y * 32;
    const int tx = threadIdx.x & 31, ty = threadIdx.x >> 5;
#pragma unroll
    for (int i = 0; i < 32; i += 8)
        tile[ty + i][tx] = ip[(size_t)(r0 + ty + i) * C + c0 + tx];
    __syncthreads();
#pragma unroll
    for (int i = 0; i < 32; i += 8)
        op[(size_t)(c0 + ty + i) * R + r0 + tx] = to_tf32(tile[tx][ty + i]);
}

// ---------------------------------------------------------------------------
// tcgen05 tf32 batched GEMM, cp.async 5-stage pipeline, per-stage mbarriers.
// C[bz] = A (MxK, pre-rounded) @ XT[bz] (2048xK, pre-rounded)^T
// Commit chunk c -> mb[c%5]; wait chunk cc with parity (cc/5)&1. Each barrier
// can be at most one phase ahead of its waiter (next commit to the same
// barrier is 5 chunks later, behind per-iteration __syncthreads) -> no parity
// aliasing, no deadlock (R5 bug).
// ---------------------------------------------------------------------------
#define NSTAGE 5
#define GSMEM  (1024 + NSTAGE * 32768)

#if HAS_TCGEN05
__device__ __forceinline__ void gemm_issue(uint32_t sbase, const float* Ap,
                                           const float* Bp, int K, int c, int t)
{
    const uint32_t st = sbase + 1024u + (uint32_t)(c % NSTAGE) * 32768u;
#pragma unroll
    for (int r = 0; r < 4; r++) {
        int idx = t + r * 256, row = idx >> 3, seg = idx & 7;
        uint32_t off = SW128(row * 128 + seg * 16);
        const float* a = Ap + (size_t)row * K + c * 32 + seg * 4;
        const float* b = Bp + (size_t)row * K + c * 32 + seg * 4;
        CP_ASYNC16(st + off, a);
        CP_ASYNC16(st + 16384u + off, b);
    }
    CP_COMMIT();
}
#endif

template <int EPI, int TRANS, int RND>
__global__ __launch_bounds__(256)
void tgemm(const float* __restrict__ A, const float* __restrict__ XT,
           float* __restrict__ C,
           const float* __restrict__ g, const float* __restrict__ beta,
           const float* __restrict__ cb, const float* __restrict__ resid,
           int M, int K, float oscale)
{
#if HAS_TCGEN05
    extern __shared__ char smem[];
    const uint32_t sbase = smem_u32(smem);
    const int t = threadIdx.x, wid = t >> 5, lane = t & 31;
    const int bz = blockIdx.z;
    const int m0 = blockIdx.y * 128, n0 = blockIdx.x * 128;
    const float* Ap = A + (size_t)m0 * K;
    const float* Bp = XT + (size_t)bz * NN * K + (size_t)n0 * K;

    if (t < NSTAGE) MBAR_INIT(sbase + 16 + 8 * t, 1);
    if (wid == 0) TM_ALLOC(sbase + 0, 128);
    __syncthreads();
    uint32_t tmem;
    asm volatile("ld.shared.b32 %0, [%1];" : "=r"(tmem) : "r"(sbase + 0));
    const int nk = K >> 5;

    // prologue: stages 0..2
    gemm_issue(sbase, Ap, Bp, K, 0, t);
    gemm_issue(sbase, Ap, Bp, K, 1, t);
    gemm_issue(sbase, Ap, Bp, K, 2, t);

    for (int c = 0; c < nk; c++) {
        const int rem = nk - 1 - c;
        if (rem >= 2) CP_WAIT(2);
        else if (rem == 1) CP_WAIT(1);
        else CP_WAIT(0);
        __syncthreads();

        if (wid == 0 && elect1()) {
            FENCE_ASYNC();
            const uint32_t st = sbase + 1024u + (uint32_t)(c % NSTAGE) * 32768u;
            uint64_t ad = mkdesc(st);
            uint64_t bd = mkdesc(st + 16384u);
#pragma unroll
            for (int s = 0; s < 4; s++)
                mma_ss(tmem, ad + s * 2, bd + s * 2, IDESC_128,
                       (c > 0 || s > 0) ? 1u : 0u);
            TM_COMMIT(sbase + 16 + 8 * (c % NSTAGE));
        }
        if (c >= 2) {
            const int cc = c - 2;   // WAR guard for stage (c+3)%5 == cc%5
            MBAR_WAIT(sbase + 16 + 8 * (cc % NSTAGE), (cc / NSTAGE) & 1);
        }
        if (c + 3 < nk) gemm_issue(sbase, Ap, Bp, K, c + 3, t);
    }
    {   // drain: last two chunks
        const int c1 = nk - 2, c2 = nk - 1;
        MBAR_WAIT(sbase + 16 + 8 * (c1 % NSTAGE), (c1 / NSTAGE) & 1);
        MBAR_WAIT(sbase + 16 + 8 * (c2 % NSTAGE), (c2 / NSTAGE) & 1);
    }
    TM_FENCE_AFTER();

    // Epilogue: LDTM -> per-row math -> smem staging -> coalesced STG
    const int sp = wid & 3, ch = wid >> 2;
    uint32_t r0[32], r1[32];
    TM_LD_X32(r0, tmem + ch * 64);
    TM_LD_X32(r1, tmem + ch * 64 + 32);
    TM_WAIT_LD();
    __syncthreads();   // staging below may alias the pipeline stages

    const int ml = sp * 32 + lane;
    const int m = m0 + ml;
    float s = oscale, tt = 0.f;
    if (EPI) { s = g[m] * INVF; tt = cb[m] * s + beta[m]; }
    float* stg = (float*)(smem + 1024);
#pragma unroll
    for (int i = 0; i < 32; i++) {
        float v0 = fmaf(__uint_as_float(r0[i]), s, tt);
        float v1 = fmaf(__uint_as_float(r1[i]), s, tt);
        if (EPI == 1) { v0 = fmaxf(v0, 0.f); v1 = fmaxf(v1, 0.f); }
        if (RND) { v0 = to_tf32(v0); v1 = to_tf32(v1); }
        if (TRANS) {
            stg[(ch * 64 + i) * 132 + ml]      = v0;
            stg[(ch * 64 + 32 + i) * 132 + ml] = v1;
        } else {
            stg[ml * 132 + ch * 64 + i]      = v0;
            stg[ml * 132 + ch * 64 + 32 + i] = v1;
        }
    }
    __syncthreads();

    if (TRANS) {
        float* Ct = C + (size_t)bz * NN * M;
#pragma unroll
        for (int rr = 0; rr < 16; rr++) {
            int nn = rr * 8 + wid;
            float4 v = *(float4*)&stg[nn * 132 + lane * 4];
            *(float4*)(Ct + (size_t)(n0 + nn) * M + m0 + lane * 4) = v;
        }
    } else {
        float* Cp = C + (size_t)bz * M * NN;
#pragma unroll
        for (int rr = 0; rr < 16; rr++) {
            int row = rr * 8 + wid;
            float4 v = *(float4*)&stg[row * 132 + lane * 4];
            if (EPI == 2) {
                float4 rv = *(const float4*)(resid + (size_t)bz * M * NN +
                                             (size_t)(m0 + row) * NN + n0 + lane * 4);
                v.x = fmaxf(v.x + rv.x, 0.f); v.y = fmaxf(v.y + rv.y, 0.f);
                v.z = fmaxf(v.z + rv.z, 0.f); v.w = fmaxf(v.w + rv.w, 0.f);
            }
            *(float4*)(Cp + (size_t)(m0 + row) * NN + n0 + lane * 4) = v;
        }
    }
    __syncthreads();
    if (wid == 0) TM_DEALLOC(tmem, 128);

#else  // ---------------- fp32 fallback (never runs on GB300) ---------------
    extern __shared__ char smem_raw[];
    float (*As)[132] = (float(*)[132])smem_raw;
    float (*Bs)[132] = (float(*)[132])(smem_raw + 16 * 132 * 4);
    const int bz = blockIdx.z;
    const int m0 = blockIdx.y * 128, n0 = blockIdx.x * 128;
    const float* Ap = A + (size_t)m0 * K;
    const float* Bp = XT + (size_t)bz * NN * K + (size_t)n0 * K;
    const int t = threadIdx.x, tx = t & 15, ty = t >> 4;
    float acc[8][8];
#pragma unroll
    for (int i = 0; i < 8; i++)
#pragma unroll
        for (int j = 0; j < 8; j++) acc[i][j] = 0.f;
    for (int k0 = 0; k0 < K; k0 += 16) {
#pragma unroll
        for (int r = 0; r < 2; r++) {
            int i = t + r * 256, row = i >> 2, seg = i & 3;
            float4 v4 = *(const float4*)(Ap + (size_t)row * K + k0 + seg * 4);
            As[seg * 4 + 0][row] = v4.x; As[seg * 4 + 1][row] = v4.y;
            As[seg * 4 + 2][row] = v4.z; As[seg * 4 + 3][row] = v4.w;
            v4 = *(const float4*)(Bp + (size_t)row * K + k0 + seg * 4);
            Bs[seg * 4 + 0][row] = v4.x; Bs[seg * 4 + 1][row] = v4.y;
            Bs[seg * 4 + 2][row] = v4.z; Bs[seg * 4 + 3][row] = v4.w;
        }
        __syncthreads();
#pragma unroll
        for (int kk = 0; kk < 16; kk++) {
            float a[8], b[8];
            *(float4*)&a[0] = *(const float4*)&As[kk][ty * 4];
            *(float4*)&a[4] = *(const float4*)&As[kk][64 + ty * 4];
            *(float4*)&b[0] = *(const float4*)&Bs[kk][tx * 4];
            *(float4*)&b[4] = *(const float4*)&Bs[kk][64 + tx * 4];
#pragma unroll
            for (int i = 0; i < 8; i++)
#pragma unroll
                for (int j = 0; j < 8; j++) acc[i][j] += a[i] * b[j];
        }
        __syncthreads();
    }
#pragma unroll
    for (int i = 0; i < 8; i++) {
        int m = m0 + ((i < 4) ? (ty * 4 + i) : (64 + ty * 4 + i - 4));
        float s = oscale, tt = 0.f;
        if (EPI) { s = g[m] * INVF; tt = cb[m] * s + beta[m]; }
#pragma unroll
        for (int h = 0; h < 2; h++) {
            int n = n0 + h * 64 + tx * 4;
#pragma unroll
            for (int j = 0; j < 4; j++) {
                float v = acc[i][h * 4 + j];
                if (EPI == 0) v *= oscale;
                else {
                    v = v * s + tt;
                    if (EPI == 2)
                        v += resid[(size_t)bz * M * NN + (size_t)m * NN + n + j];
                    v = fmaxf(v, 0.f);
                }
                if (RND) v = to_tf32(v);
                if (TRANS) C[(size_t)bz * NN * M + (size_t)(n + j) * M + m] = v;
                else       C[(size_t)bz * M * NN + (size_t)m * NN + n + j] = v;
            }
        }
    }
#endif
}

// ---------------------------------------------------------------------------
// tcgen05 attention (R4 scheme, verified) + tf32-rounded o2T output
// ---------------------------------------------------------------------------
#define AS_Q   2048u
#define AS_KV0 (2048u + 65536u)
#define AS_KV1 (2048u + 65536u + 32768u)
#define ASMEM  133120

__global__ __launch_bounds__(128)
void attn_tc(const float* __restrict__ qT, const float* __restrict__ kT,
             const float* __restrict__ v, const float* __restrict__ o1T,
             const float* __restrict__ g2, const float* __restrict__ be2,
             float* __restrict__ o2T)
{
    extern __shared__ char sm[];
    const int t = threadIdx.x, wid = t >> 5, lane = t & 31;
    const int xt = blockIdx.x;
    const int sp = blockIdx.y >> 2, hh = blockIdx.y & 3;
    const int b = blockIdx.z;

    const size_t qrow = (size_t)b * NN + sp * 256 + xt * 128;
    const float* qp  = qT  + qrow * PP + hh * DH;
    const float* kp  = kT  + ((size_t)b * NN + sp * 256) * PP + hh * DH;
    const float* vp  = v   + ((size_t)b * PP + hh * DH) * NN + sp * 256;
    const float* o1p = o1T + qrow * PP + hh * DH;
    float* o2p       = o2T + qrow * PP + hh * DH;

#if HAS_TCGEN05
    const uint32_t sbase = smem_u32(sm);
    if (t == 0) { MBAR_INIT(sbase + 16, 1); MBAR_INIT(sbase + 24, 1); }
    if (wid == 0) TM_ALLOC(sbase + 0, 512);
    ((float*)(sm + 1024))[t] = g2[hh * DH + t] * INVF;
    ((float*)(sm + 1536))[t] = be2[hh * DH + t];
    __syncthreads();
    uint32_t tmem;
    asm volatile("ld.shared.b32 %0, [%1];" : "=r"(tmem) : "r"(sbase + 0));
    const uint32_t kvoff[2] = {AS_KV0, AS_KV1};

    // ---- load Q tile [128 x][128 d] into 4 d-chunk atoms ----
#pragma unroll
    for (int r = 0; r < 32; r++) {
        int i = t + r * 128;
        int row = i >> 5, rem = i & 31, j = rem >> 3, seg = rem & 7;
        float4 vq = *(const float4*)(qp + (size_t)row * PP + j * 32 + seg * 4);
        *(float4*)(sm + AS_Q + j * 16384 + SW128(row * 128 + seg * 16)) = vq;
    }

    // ---- S = Q.K^T over 4 d-chunks, double-buffered K ----
    float4 kv[16];
#pragma unroll
    for (int r = 0; r < 16; r++) {
        int i = t + r * 128, row = i >> 3, seg = i & 7;
        kv[r] = *(const float4*)(kp + (size_t)row * PP + seg * 4);
    }
    for (int c = 0; c < 4; c++) {
        const int buf = c & 1;
        const uint32_t mb = sbase + 16 + 8 * buf;
        if (c >= 2) MBAR_WAIT(mb, 0);
#pragma unroll
        for (int r = 0; r < 16; r++) {
            int i = t + r * 128, row = i >> 3, seg = i & 7;
            *(float4*)(sm + kvoff[buf] + SW128(row * 128 + seg * 16)) = kv[r];
        }
        if (c < 3) {
#pragma unroll
            for (int r = 0; r < 16; r++) {
                int i = t + r * 128, row = i >> 3, seg = i & 7;
                kv[r] = *(const float4*)(kp + (size_t)row * PP + (c + 1) * 32 + seg * 4);
            }
        }
        __syncthreads();
        if (wid == 0 && elect1()) {
            FENCE_ASYNC();
            uint64_t qd = mkdesc(sbase + AS_Q + c * 16384);
            uint64_t kd = mkdesc(sbase + kvoff[buf]);
#pragma unroll
            for (int s = 0; s < 4; s++)
                mma_ss(tmem, qd + s * 2, kd + s * 2, IDESC_256,
                       (c > 0 || s > 0) ? 1u : 0u);
            TM_COMMIT(mb);
        }
    }
    MBAR_WAIT(sbase + 24, 1);
    TM_FENCE_AFTER();

    // ---- softmax over 256 keys; lane = query row; P unnormalized ----
    uint32_t rs[32];
    float mx = -1e30f;
#pragma unroll
    for (int cc = 0; cc < 8; cc++) {
        TM_LD_X32(rs, tmem + cc * 32);
        TM_WAIT_LD();
#pragma unroll
        for (int i = 0; i < 32; i++) mx = fmaxf(mx, __uint_as_float(rs[i]));
    }
    float ssum = 0.f;
#pragma unroll
    for (int cc = 0; cc < 8; cc++) {
        TM_LD_X32(rs, tmem + cc * 32);
        TM_WAIT_LD();
#pragma unroll
        for (int i = 0; i < 32; i++) {
            float e = __expf(__uint_as_float(rs[i]) - mx);
            ssum += e;
            rs[i] = __float_as_uint(e);
        }
        TM_ST_X32(tmem + cc * 32, rs);
    }
    TM_WAIT_ST();
    const float sinv = 1.f / ssum;
    TM_FENCE_BEFORE();

    // ---- O = P.V over 4 y-chunks of 64 (TS mode) ----
#pragma unroll
    for (int r = 0; r < 16; r++) {
        int i = t + r * 128, row = i >> 4, seg = i & 15;
        kv[r] = *(const float4*)(vp + (size_t)row * NN + seg * 4);
    }
    for (int j = 0; j < 4; j++) {
        const int buf = j & 1;
        const uint32_t mb = sbase + 16 + 8 * buf;
        if (j >= 2) MBAR_WAIT(mb, 0);
#pragma unroll
        for (int r = 0; r < 16; r++) {
            int i = t + r * 128, row = i >> 4, seg = i & 15;
            *(float4*)(sm + kvoff[buf] + (seg >> 3) * 16384 +
                       SW128(row * 128 + (seg & 7) * 16)) = kv[r];
        }
        if (j < 3) {
#pragma unroll
            for (int r = 0; r < 16; r++) {
                int i = t + r * 128, row = i >> 4, seg = i & 15;
                kv[r] = *(const float4*)(vp + (size_t)row * NN + (j + 1) * 64 + seg * 4);
            }
        }
        __syncthreads();
        if (wid == 0 && elect1()) {
            FENCE_ASYNC();
            TM_FENCE_AFTER();
            uint64_t vd = mkdesc(sbase + kvoff[buf]);
#pragma unroll
            for (int s = 0; s < 8; s++)
                mma_ts(tmem + 256, tmem + j * 64 + s * 8,
                       vd + (s >> 2) * 1024 + (s & 3) * 2, IDESC_128,
                       (j > 0 || s > 0) ? 1u : 0u);
            TM_COMMIT(mb);
        }
    }
    MBAR_WAIT(sbase + 24, 1);
    TM_FENCE_AFTER();

    // ---- epilogue: (O*sinv + o1)*g2' + be2, relu, tf32-round -> o2T ----
    const float* g2s  = (const float*)(sm + 1024);
    const float* be2s = (const float*)(sm + 1536);
    const float* myo1 = o1p + (size_t)(wid * 32 + lane) * PP;
    float* myo2       = o2p + (size_t)(wid * 32 + lane) * PP;
#pragma unroll
    for (int k = 0; k < 4; k++) {
        TM_LD_X32(rs, tmem + 256 + k * 32);
        TM_WAIT_LD();
#pragma unroll
        for (int i = 0; i < 32; i += 4) {
            int d = k * 32 + i;
            float4 r1 = *(const float4*)(myo1 + d);
            float4 o;
            o.x = to_tf32(fmaxf(fmaf(fmaf(__uint_as_float(rs[i + 0]), sinv, r1.x), g2s[d + 0], be2s[d + 0]), 0.f));
            o.y = to_tf32(fmaxf(fmaf(fmaf(__uint_as_float(rs[i + 1]), sinv, r1.y), g2s[d + 1], be2s[d + 1]), 0.f));
            o.z = to_tf32(fmaxf(fmaf(fmaf(__uint_as_float(rs[i + 2]), sinv, r1.z), g2s[d + 2], be2s[d + 2]), 0.f));
            o.w = to_tf32(fmaxf(fmaf(fmaf(__uint_as_float(rs[i + 3]), sinv, r1.w), g2s[d + 3], be2s[d + 3]), 0.f));
            *(float4*)(myo2 + d) = o;
        }
    }
    __syncthreads();
    if (wid == 0) TM_DEALLOC(tmem, 512);

#else  // ---------------- fp32 fallback (never runs on GB300) ---------------
    const int x = t;
    float sb[256];
    float mx = -1e30f;
    for (int y = 0; y < 256; y++) {
        float s = 0.f;
        for (int d = 0; d < DH; d++)
            s += qp[(size_t)x * PP + d] * kp[(size_t)y * PP + d];
        sb[y] = s;
        mx = fmaxf(mx, s);
    }
    float ssum = 0.f;
    for (int y = 0; y < 256; y++) { sb[y] = __expf(sb[y] - mx); ssum += sb[y]; }
    float sinv = 1.f / ssum;
    for (int d = 0; d < DH; d++) {
        float o = 0.f;
        for (int y = 0; y < 256; y++) o += sb[y] * vp[(size_t)d * NN + y];
        float val = (o * sinv + o1p[(size_t)x * PP + d]) * (g2[hh * DH + d] * INVF)
                    + be2[hh * DH + d];
        o2p[(size_t)x * PP + d] = to_tf32(fmaxf(val, 0.f));
    }
#endif
}

// ---------------------------------------------------------------------------
extern "C" void kernel_launch(void* const* d_in, const int* in_sizes, int n_in,
                              void* d_out, int out_size)
{
    const float* x   = (const float*)d_in[0];
    const float* w1  = (const float*)d_in[1];
    const float* b1  = (const float*)d_in[2];
    const float* g1  = (const float*)d_in[3];
    const float* be1 = (const float*)d_in[4];
    const float* wq  = (const float*)d_in[5];
    const float* wk  = (const float*)d_in[6];
    const float* wv  = (const float*)d_in[7];
    const float* g2  = (const float*)d_in[8];
    const float* be2 = (const float*)d_in[9];
    const float* w3  = (const float*)d_in[10];
    const float* b3  = (const float*)d_in[11];
    const float* g3  = (const float*)d_in[12];
    const float* be3 = (const float*)d_in[13];
    float* out = (float*)d_out;

    float *xT, *o1T, *qT, *kT, *vb, *o2T, *wr;
    cudaGetSymbolAddress((void**)&xT,  g_xT);
    cudaGetSymbolAddress((void**)&o1T, g_o1T);
    cudaGetSymbolAddress((void**)&qT,  g_qT);
    cudaGetSymbolAddress((void**)&kT,  g_kT);
    cudaGetSymbolAddress((void**)&vb,  g_v);
    cudaGetSymbolAddress((void**)&o2T, g_o2T);
    cudaGetSymbolAddress((void**)&wr,  g_wr);

    cudaFuncSetAttribute((const void*)tgemm<0,0,1>, cudaFuncAttributeMaxDynamicSharedMemorySize, GSMEM);
    cudaFuncSetAttribute((const void*)tgemm<0,1,1>, cudaFuncAttributeMaxDynamicSharedMemorySize, GSMEM);
    cudaFuncSetAttribute((const void*)tgemm<1,1,1>, cudaFuncAttributeMaxDynamicSharedMemorySize, GSMEM);
    cudaFuncSetAttribute((const void*)tgemm<2,0,0>, cudaFuncAttributeMaxDynamicSharedMemorySize, GSMEM);
    cudaFuncSetAttribute((const void*)attn_tc, cudaFuncAttributeMaxDynamicSharedMemorySize, ASMEM);

    // 0a) round weights to tf32 (w1 | wq | wk | wv | w3)
    round_w<<<512, 256>>>(w1, wr + WR_W1, 512 * 1024 / 4);
    round_w<<<256, 256>>>(wq, wr + WR_WQ, 512 * 512 / 4);
    round_w<<<256, 256>>>(wk, wr + WR_WK, 512 * 512 / 4);
    round_w<<<256, 256>>>(wv, wr + WR_WV, 512 * 512 / 4);
    round_w<<<512, 256>>>(w3, wr + WR_W3, 1024 * 512 / 4);
    // 0b) xT[b][hw][c] (tf32-rounded)
    transpose_k<<<dim3(64, 32, BB), 256>>>(x, xT, CIN, NN);
    // 1) o1T = relu(bn1(conv1(x)))^T  [b][hw][p], rounded
    tgemm<1,1,1><<<dim3(16, 4, BB), 256, GSMEM>>>(wr + WR_W1, xT, o1T, g1, be1, b1,
                                                  nullptr, PP, CIN, 1.f);
    // 2) projections: qT,kT transposed+rounded; v normal+rounded
    tgemm<0,1,1><<<dim3(16, 4, BB), 256, GSMEM>>>(wr + WR_WQ, o1T, qT, nullptr, nullptr,
                                                  nullptr, nullptr, PP, PP, QSCALE);
    tgemm<0,1,1><<<dim3(16, 4, BB), 256, GSMEM>>>(wr + WR_WK, o1T, kT, nullptr, nullptr,
                                                  nullptr, nullptr, PP, PP, 1.f);
    tgemm<0,0,1><<<dim3(16, 4, BB), 256, GSMEM>>>(wr + WR_WV, o1T, vb, nullptr, nullptr,
                                                  nullptr, nullptr, PP, PP, 1.f);
    // 3) attention + residual + bn2 + relu -> o2T [b][hw][p], rounded
    attn_tc<<<dim3(2, 32, BB), 128, ASMEM>>>(qT, kT, vb, o1T, g2, be2, o2T);
    // 4) out = relu(bn3(conv3) + x)
    tgemm<2,0,0><<<dim3(16, 8, BB), 256, GSMEM>>>(wr + WR_W3, o2T, out, g3, be3, b3, x,
                                                  CIN, PP, 1.f);
}

// round 7
// speedup vs baseline: 6.4839x; 1.2542x over previous
#include <cuda_runtime.h>
#include <cstdint>

// Problem constants
#define BB 16
#define CIN 1024
#define PP 512
#define NN 2048          // H*W
#define DH 128           // head dim
#define INVF 0.99999500003749969f      // 1/sqrt(1+1e-5)
#define QSCALE 0.08838834764831843f    // 128^-0.5

#if defined(__CUDA_ARCH__) && (__CUDA_ARCH__ >= 1000) && \
    (defined(__CUDA_ARCH_FEAT_SM103_ALL) || defined(__CUDA_ARCH_FEAT_SM100_ALL) || \
     defined(__CUDA_ARCH_SPECIFIC__) || defined(__CUDA_ARCH_FAMILY_SPECIFIC__))
#define HAS_TCGEN05 1
#else
#define HAS_TCGEN05 0
#endif

// Scratch (device globals)
__device__ float g_xT [(size_t)BB * CIN * NN];   // [b][hw][c]  (tf32-rounded)
__device__ float g_o1T[(size_t)BB * PP * NN];    // [b][hw][p]  (tf32-rounded)
__device__ float g_qT [(size_t)BB * PP * NN];    // [b][hw][p]  (tf32-rounded)
__device__ float g_kT [(size_t)BB * PP * NN];    // [b][hw][p]  (tf32-rounded)
__device__ float g_v  [(size_t)BB * PP * NN];    // [b][p][hw]  (tf32-rounded)
__device__ float g_o2T[(size_t)BB * PP * NN];    // [b][hw][p]  (tf32-rounded)
// Rounded weights, contiguous: w1 | wq | wk | wv | w3  (wq|wk|wv = fused A)
#define WR_W1 0
#define WR_WQ (512 * 1024)
#define WR_WK (WR_WQ + 512 * 512)
#define WR_WV (WR_WK + 512 * 512)
#define WR_W3 (WR_WV + 512 * 512)
__device__ float g_wr[WR_W3 + 1024 * 512];

// ---------------------------------------------------------------------------
__device__ __forceinline__ uint32_t smem_u32(const void* p) {
    uint32_t a;
    asm("{ .reg .u64 t; cvta.to.shared.u64 t, %1; cvt.u32.u64 %0, t; }"
        : "=r"(a) : "l"(p));
    return a;
}
__device__ __forceinline__ float to_tf32(float x) {
    float r; asm("cvt.rna.tf32.f32 %0, %1;" : "=f"(r) : "f"(x)); return r;
}

#if HAS_TCGEN05
__device__ __forceinline__ uint32_t elect1() {
    uint32_t p;
    asm volatile("{ .reg .pred p; elect.sync _|p, 0xFFFFFFFF; selp.b32 %0,1,0,p; }"
                 : "=r"(p));
    return p;
}
#define SW128(o) ((o) ^ ((((uint32_t)(o)) >> 3) & 0x70))

#define MBAR_INIT(a, c) \
    asm volatile("mbarrier.init.shared.b64 [%0], %1;" :: "r"(a), "r"(c) : "memory")

#define MBAR_WAIT(a, ph) do { \
    uint32_t _d; \
    asm volatile("{ .reg .pred p; mbarrier.try_wait.parity.acquire.cta.shared::cta.b64 p,[%1],%2; selp.b32 %0,1,0,p; }" \
                 : "=r"(_d) : "r"(a), "r"((uint32_t)(ph)) : "memory"); \
    if (!_d) { \
        asm volatile("{ .reg .pred P;\nLW_%=:\nmbarrier.try_wait.parity.acquire.cta.shared::cta.b64 P,[%0],%1,0x989680;\n@P bra.uni LD_%=;\nbra.uni LW_%=;\nLD_%=:\n}" \
                     :: "r"(a), "r"((uint32_t)(ph)) : "memory"); \
    } } while (0)

#define TM_ALLOC(sa, n) \
    asm volatile("tcgen05.alloc.cta_group::1.sync.aligned.shared::cta.b32 [%0], %1;" \
                 :: "r"(sa), "r"(n) : "memory")
#define TM_DEALLOC(t, n) \
    asm volatile("tcgen05.dealloc.cta_group::1.sync.aligned.b32 %0, %1;" :: "r"(t), "r"(n))
#define TM_COMMIT(mb) \
    asm volatile("tcgen05.commit.cta_group::1.mbarrier::arrive::one.shared::cluster.b64 [%0];" \
                 :: "r"(mb) : "memory")
#define TM_FENCE_AFTER()  asm volatile("tcgen05.fence::after_thread_sync;" ::: "memory")
#define TM_FENCE_BEFORE() asm volatile("tcgen05.fence::before_thread_sync;" ::: "memory")
#define TM_WAIT_LD()      asm volatile("tcgen05.wait::ld.sync.aligned;" ::: "memory")
#define TM_WAIT_ST()      asm volatile("tcgen05.wait::st.sync.aligned;" ::: "memory")
#define FENCE_ASYNC()     asm volatile("fence.proxy.async.shared::cta;" ::: "memory")

#define CP_ASYNC16(dst, src) \
    asm volatile("cp.async.cg.shared.global [%0], [%1], 16;" \
                 :: "r"(dst), "l"(src) : "memory")
#define CP_COMMIT() asm volatile("cp.async.commit_group;" ::: "memory")
#define CP_WAIT(n)  asm volatile("cp.async.wait_group %0;" :: "n"(n) : "memory")

#define TM_LD_X32(r, addr) \
    asm volatile("tcgen05.ld.sync.aligned.32x32b.x32.b32 " \
        "{%0,%1,%2,%3,%4,%5,%6,%7,%8,%9,%10,%11,%12,%13,%14,%15," \
        "%16,%17,%18,%19,%20,%21,%22,%23,%24,%25,%26,%27,%28,%29,%30,%31}, [%32];" \
        : "=r"((r)[0]),"=r"((r)[1]),"=r"((r)[2]),"=r"((r)[3]), \
          "=r"((r)[4]),"=r"((r)[5]),"=r"((r)[6]),"=r"((r)[7]), \
          "=r"((r)[8]),"=r"((r)[9]),"=r"((r)[10]),"=r"((r)[11]), \
          "=r"((r)[12]),"=r"((r)[13]),"=r"((r)[14]),"=r"((r)[15]), \
          "=r"((r)[16]),"=r"((r)[17]),"=r"((r)[18]),"=r"((r)[19]), \
          "=r"((r)[20]),"=r"((r)[21]),"=r"((r)[22]),"=r"((r)[23]), \
          "=r"((r)[24]),"=r"((r)[25]),"=r"((r)[26]),"=r"((r)[27]), \
          "=r"((r)[28]),"=r"((r)[29]),"=r"((r)[30]),"=r"((r)[31]) \
        : "r"(addr))

#define TM_ST_X32(addr, r) \
    asm volatile("tcgen05.st.sync.aligned.32x32b.x32.b32 [%0], " \
        "{%1,%2,%3,%4,%5,%6,%7,%8,%9,%10,%11,%12,%13,%14,%15,%16," \
        "%17,%18,%19,%20,%21,%22,%23,%24,%25,%26,%27,%28,%29,%30,%31,%32};" \
        :: "r"(addr), \
           "r"((r)[0]),"r"((r)[1]),"r"((r)[2]),"r"((r)[3]), \
           "r"((r)[4]),"r"((r)[5]),"r"((r)[6]),"r"((r)[7]), \
           "r"((r)[8]),"r"((r)[9]),"r"((r)[10]),"r"((r)[11]), \
           "r"((r)[12]),"r"((r)[13]),"r"((r)[14]),"r"((r)[15]), \
           "r"((r)[16]),"r"((r)[17]),"r"((r)[18]),"r"((r)[19]), \
           "r"((r)[20]),"r"((r)[21]),"r"((r)[22]),"r"((r)[23]), \
           "r"((r)[24]),"r"((r)[25]),"r"((r)[26]),"r"((r)[27]), \
           "r"((r)[28]),"r"((r)[29]),"r"((r)[30]),"r"((r)[31]) \
        : "memory")

__device__ __forceinline__ uint64_t mkdesc(uint32_t addr) {
    return ((uint64_t)2 << 61) | ((uint64_t)1 << 46) | ((uint64_t)64 << 32) |
           ((uint64_t)1 << 16) | ((addr >> 4) & 0x3FFF);
}
__device__ __forceinline__ void mma_ss(uint32_t d, uint64_t ad, uint64_t bd,
                                       uint32_t id, uint32_t en) {
    asm volatile(
        "{ .reg .pred p; setp.ne.u32 p, %5, 0;\n\t"
        "tcgen05.mma.cta_group::1.kind::tf32 [%0], %1, %2, %3, {%4,%4,%4,%4}, p;\n\t}"
        :: "r"(d), "l"(ad), "l"(bd), "r"(id), "r"(0u), "r"(en) : "memory");
}
__device__ __forceinline__ void mma_ts(uint32_t d, uint32_t a, uint64_t bd,
                                       uint32_t id, uint32_t en) {
    asm volatile(
        "{ .reg .pred p; setp.ne.u32 p, %5, 0;\n\t"
        "tcgen05.mma.cta_group::1.kind::tf32 [%0], [%1], %2, %3, {%4,%4,%4,%4}, p;\n\t}"
        :: "r"(d), "r"(a), "l"(bd), "r"(id), "r"(0u), "r"(en) : "memory");
}
#define IDESC_128 ((1u << 4) | (2u << 7) | (2u << 10) | (16u << 17) | (8u << 24))
#define IDESC_256 ((1u << 4) | (2u << 7) | (2u << 10) | (32u << 17) | (8u << 24))
#endif  // HAS_TCGEN05

// ---------------------------------------------------------------------------
// Round all 5 weight matrices to tf32 in ONE launch, into contiguous g_wr
// ---------------------------------------------------------------------------
#define N4_W1 131072           // 512*1024/4
#define N4_P  65536            // 512*512/4
#define N4_W3 131072           // 1024*512/4
#define N4_TOT (N4_W1 + 3 * N4_P + N4_W3)

__global__ __launch_bounds__(256)
void round_w5(const float* __restrict__ w1, const float* __restrict__ wq,
              const float* __restrict__ wk, const float* __restrict__ wv,
              const float* __restrict__ w3, float* __restrict__ out)
{
    int i = blockIdx.x * 256 + threadIdx.x;
    if (i >= N4_TOT) return;
    const float4* src;
    int j = i;
    if (j < N4_W1) src = (const float4*)w1;
    else if ((j -= N4_W1) < N4_P) src = (const float4*)wq;
    else if ((j -= N4_P) < N4_P) src = (const float4*)wk;
    else if ((j -= N4_P) < N4_P) src = (const float4*)wv;
    else { j -= N4_P; src = (const float4*)w3; }
    float4 v = src[j];
    v.x = to_tf32(v.x); v.y = to_tf32(v.y);
    v.z = to_tf32(v.z); v.w = to_tf32(v.w);
    ((float4*)out)[i] = v;
}

// ---------------------------------------------------------------------------
// Tiled transpose per batch with tf32 rounding: in[b][R][C] -> out[b][C][R]
// ---------------------------------------------------------------------------
__global__ __launch_bounds__(256)
void transpose_k(const float* __restrict__ in, float* __restrict__ out, int R, int C)
{
    __shared__ float tile[32][33];
    const int b = blockIdx.z;
    const float* ip = in + (size_t)b * R * C;
    float* op = out + (size_t)b * R * C;
    const int c0 = blockIdx.x * 32, r0 = blockIdx.y * 32;
    const int tx = threadIdx.x & 31, ty = threadIdx.x >> 5;
#pragma unroll
    for (int i = 0; i < 32; i += 8)
        tile[ty + i][tx] = ip[(size_t)(r0 + ty + i) * C + c0 + tx];
    __syncthreads();
#pragma unroll
    for (int i = 0; i < 32; i += 8)
        op[(size_t)(c0 + ty + i) * R + r0 + tx] = to_tf32(tile[tx][ty + i]);
}

// ---------------------------------------------------------------------------
// tcgen05 tf32 batched GEMM, 128m x 256n tile, cp.async 4-stage pipeline.
// C = A (MxK, rounded) @ XT[bz] (2048xK, rounded)^T ; one N=256 MMA per k-atom.
// MODE 0: conv1  -> o1T   (trans store, bn1+relu, rnd)
// MODE 1: fused qkv (M=1536): y<4 -> qT (trans, *QSCALE, rnd), y<8 -> kT
//         (trans, rnd), else -> v (normal, rnd)
// MODE 2: conv3 -> out    (normal store, bn3 + resid + relu)
// Stage = 48KB (A 16K | B 32K), 4 stages; commit chunk c -> mb[c%4]; in-loop
// wait MMA(c-1) before reusing its stage for chunk c+3 (WAR-safe, <=1 phase).
// ---------------------------------------------------------------------------
#define NSTAGE 4
#define STAGE_B 49152u
#define GSMEM  (1024 + NSTAGE * STAGE_B)   // 197632

#if HAS_TCGEN05
__device__ __forceinline__ void gemm_issue256(uint32_t sbase, const float* Ap,
                                              const float* Bp, int K, int c, int t)
{
    const uint32_t st = sbase + 1024u + (uint32_t)(c % NSTAGE) * STAGE_B;
#pragma unroll
    for (int r = 0; r < 4; r++) {               // A: 128 x 32
        int idx = t + r * 256, row = idx >> 3, seg = idx & 7;
        CP_ASYNC16(st + SW128(row * 128 + seg * 16),
                   Ap + (size_t)row * K + c * 32 + seg * 4);
    }
#pragma unroll
    for (int r = 0; r < 8; r++) {               // B: 256 x 32
        int idx = t + r * 256, row = idx >> 3, seg = idx & 7;
        CP_ASYNC16(st + 16384u + SW128(row * 128 + seg * 16),
                   Bp + (size_t)row * K + c * 32 + seg * 4);
    }
    CP_COMMIT();
}
#endif

template <int MODE>
__global__ __launch_bounds__(256)
void tgemm256(const float* __restrict__ A, const float* __restrict__ XT,
              float* __restrict__ C0, float* __restrict__ C1,
              float* __restrict__ C2,
              const float* __restrict__ g, const float* __restrict__ beta,
              const float* __restrict__ cb, const float* __restrict__ resid,
              int M, int K)
{
    const int t = threadIdx.x;
    const int bz = blockIdx.z, yb = blockIdx.y;
    const int m0 = yb * 128, n0 = blockIdx.x * 256;
    const float* Ap = A + (size_t)m0 * K;
    const float* Bp = XT + (size_t)bz * NN * K + (size_t)n0 * K;

#if HAS_TCGEN05
    extern __shared__ char smem[];
    const uint32_t sbase = smem_u32(smem);
    const int wid = t >> 5, lane = t & 31;

    if (t < NSTAGE) MBAR_INIT(sbase + 16 + 8 * t, 1);
    if (wid == 0) TM_ALLOC(sbase + 0, 256);
    __syncthreads();
    uint32_t tmem;
    asm volatile("ld.shared.b32 %0, [%1];" : "=r"(tmem) : "r"(sbase + 0));
    const int nk = K >> 5;

    gemm_issue256(sbase, Ap, Bp, K, 0, t);
    gemm_issue256(sbase, Ap, Bp, K, 1, t);
    gemm_issue256(sbase, Ap, Bp, K, 2, t);

    for (int c = 0; c < nk; c++) {
        const int rem = nk - 1 - c;
        if (rem >= 2) CP_WAIT(2);
        else if (rem == 1) CP_WAIT(1);
        else CP_WAIT(0);
        __syncthreads();

        if (wid == 0 && elect1()) {
            FENCE_ASYNC();
            const uint32_t st = sbase + 1024u + (uint32_t)(c % NSTAGE) * STAGE_B;
            uint64_t ad = mkdesc(st);
            uint64_t bd = mkdesc(st + 16384u);
#pragma unroll
            for (int s = 0; s < 4; s++)
                mma_ss(tmem, ad + s * 2, bd + s * 2, IDESC_256,
                       (c > 0 || s > 0) ? 1u : 0u);
            TM_COMMIT(sbase + 16 + 8 * (c % NSTAGE));
        }
        if (c >= 1) {   // WAR guard: stage (c+3)%4 belongs to chunk c-1
            const int cc = c - 1;
            MBAR_WAIT(sbase + 16 + 8 * (cc % NSTAGE), (cc >> 2) & 1);
        }
        if (c + 3 < nk) gemm_issue256(sbase, Ap, Bp, K, c + 3, t);
    }
    {   // drain last chunk
        const int cl = nk - 1;
        MBAR_WAIT(sbase + 16 + 8 * (cl % NSTAGE), (cl >> 2) & 1);
    }
    TM_FENCE_AFTER();

    // ---- per-mode epilogue parameters (row m constants) ----
    const int sp = wid & 3, ch = wid >> 2;
    const int ml = sp * 32 + lane;
    const int m = m0 + ml;
    float s = 1.f, tt = 0.f;
    int trans = 0, mloc = 0;
    float* Ct = C0;
    if (MODE == 0) {
        s = g[m] * INVF; tt = cb[m] * s + beta[m];
        trans = 1; mloc = m0; Ct = C0;
    } else if (MODE == 1) {
        if (yb < 8) { trans = 1; Ct = (yb < 4) ? C0 : C1; s = (yb < 4) ? QSCALE : 1.f; }
        else { trans = 0; Ct = C2; }
        mloc = (yb & 3) * 128;
    } else {
        s = g[m] * INVF; tt = cb[m] * s + beta[m];
        trans = 0; mloc = m0; Ct = C0;
    }
    float* stg = (float*)(smem + 1024);

    for (int h = 0; h < 2; h++) {
        uint32_t r0[32], r1[32];
        TM_LD_X32(r0, tmem + h * 128 + ch * 64);
        TM_LD_X32(r1, tmem + h * 128 + ch * 64 + 32);
        TM_WAIT_LD();
        __syncthreads();   // staging aliases pipeline stages / prev half done

#pragma unroll
        for (int i = 0; i < 32; i++) {
            float v0 = fmaf(__uint_as_float(r0[i]), s, tt);
            float v1 = fmaf(__uint_as_float(r1[i]), s, tt);
            if (MODE == 0) { v0 = fmaxf(v0, 0.f); v1 = fmaxf(v1, 0.f); }
            if (MODE != 2) { v0 = to_tf32(v0); v1 = to_tf32(v1); }
            if (trans) {
                stg[(ch * 64 + i) * 132 + ml]      = v0;
                stg[(ch * 64 + 32 + i) * 132 + ml] = v1;
            } else {
                stg[ml * 132 + ch * 64 + i]      = v0;
                stg[ml * 132 + ch * 64 + 32 + i] = v1;
            }
        }
        __syncthreads();

        const int nb = n0 + h * 128;
        if (trans) {   // store [n][512]
#pragma unroll
            for (int rr = 0; rr < 16; rr++) {
                int nn = rr * 8 + wid;
                float4 v = *(float4*)&stg[nn * 132 + lane * 4];
                *(float4*)(Ct + ((size_t)bz * NN + nb + nn) * 512 + mloc + lane * 4) = v;
            }
        } else {       // store [m][NN]
#pragma unroll
            for (int rr = 0; rr < 16; rr++) {
                int row = rr * 8 + wid;
                float4 v = *(float4*)&stg[row * 132 + lane * 4];
                if (MODE == 2) {
                    float4 rv = *(const float4*)(resid + ((size_t)bz * M + m0 + row) * NN
                                                 + nb + lane * 4);
                    v.x = fmaxf(v.x + rv.x, 0.f); v.y = fmaxf(v.y + rv.y, 0.f);
                    v.z = fmaxf(v.z + rv.z, 0.f); v.w = fmaxf(v.w + rv.w, 0.f);
                }
                *(float4*)(Ct + ((size_t)bz * ((MODE == 1) ? 512 : M) + mloc + row) * NN
                           + nb + lane * 4) = v;
            }
        }
        __syncthreads();
    }
    if (wid == 0) TM_DEALLOC(tmem, 256);

#else  // ---------------- fp32 fallback (never runs on GB300) ---------------
    extern __shared__ char smem_raw[];
    float (*As)[132] = (float(*)[132])smem_raw;
    float (*Bs)[132] = (float(*)[132])(smem_raw + 16 * 132 * 4);
    const int tx = t & 15, ty = t >> 4;

    for (int h = 0; h < 2; h++) {
        const int nb = n0 + h * 128;
        const float* Bph = XT + (size_t)bz * NN * K + (size_t)nb * K;
        float acc[8][8];
#pragma unroll
        for (int i = 0; i < 8; i++)
#pragma unroll
            for (int j = 0; j < 8; j++) acc[i][j] = 0.f;
        for (int k0 = 0; k0 < K; k0 += 16) {
            __syncthreads();
#pragma unroll
            for (int r = 0; r < 2; r++) {
                int i = t + r * 256, row = i >> 2, seg = i & 3;
                float4 v4 = *(const float4*)(Ap + (size_t)row * K + k0 + seg * 4);
                As[seg * 4 + 0][row] = v4.x; As[seg * 4 + 1][row] = v4.y;
                As[seg * 4 + 2][row] = v4.z; As[seg * 4 + 3][row] = v4.w;
                v4 = *(const float4*)(Bph + (size_t)row * K + k0 + seg * 4);
                Bs[seg * 4 + 0][row] = v4.x; Bs[seg * 4 + 1][row] = v4.y;
                Bs[seg * 4 + 2][row] = v4.z; Bs[seg * 4 + 3][row] = v4.w;
            }
            __syncthreads();
#pragma unroll
            for (int kk = 0; kk < 16; kk++) {
                float a[8], b[8];
                *(float4*)&a[0] = *(const float4*)&As[kk][ty * 4];
                *(float4*)&a[4] = *(const float4*)&As[kk][64 + ty * 4];
                *(float4*)&b[0] = *(const float4*)&Bs[kk][tx * 4];
                *(float4*)&b[4] = *(const float4*)&Bs[kk][64 + tx * 4];
#pragma unroll
                for (int i = 0; i < 8; i++)
#pragma unroll
                    for (int j = 0; j < 8; j++) acc[i][j] += a[i] * b[j];
            }
        }
        __syncthreads();
#pragma unroll
        for (int i = 0; i < 8; i++) {
            int mll = (i < 4) ? (ty * 4 + i) : (64 + ty * 4 + i - 4);
            int m = m0 + mll;
            float s = 1.f, tt = 0.f;
            int trans = 0, mloc = 0; float* Ct = C0;
            if (MODE == 0) { s = g[m] * INVF; tt = cb[m] * s + beta[m]; trans = 1; mloc = m0; }
            else if (MODE == 1) {
                if (yb < 8) { trans = 1; Ct = (yb < 4) ? C0 : C1; s = (yb < 4) ? QSCALE : 1.f; }
                else Ct = C2;
                mloc = (yb & 3) * 128;
            } else { s = g[m] * INVF; tt = cb[m] * s + beta[m]; mloc = m0; }
#pragma unroll
            for (int hh2 = 0; hh2 < 2; hh2++) {
                int n = nb + hh2 * 64 + tx * 4;
#pragma unroll
                for (int j = 0; j < 4; j++) {
                    float v = acc[i][hh2 * 4 + j] * s + tt;
                    if (MODE == 0) v = fmaxf(v, 0.f);
                    if (MODE == 2) {
                        v += resid[((size_t)bz * M + m) * NN + n + j];
                        v = fmaxf(v, 0.f);
                    }
                    if (MODE != 2) v = to_tf32(v);
                    if (trans)
                        Ct[((size_t)bz * NN + n + j) * 512 + mloc + mll] = v;
                    else
                        Ct[((size_t)bz * ((MODE == 1) ? 512 : M) + mloc + mll) * NN + n + j] = v;
                }
            }
        }
    }
#endif
}

// ---------------------------------------------------------------------------
// tcgen05 attention (R6, verified) + tf32-rounded o2T output
// ---------------------------------------------------------------------------
#define AS_Q   2048u
#define AS_KV0 (2048u + 65536u)
#define AS_KV1 (2048u + 65536u + 32768u)
#define ASMEM  133120

__global__ __launch_bounds__(128)
void attn_tc(const float* __restrict__ qT, const float* __restrict__ kT,
             const float* __restrict__ v, const float* __restrict__ o1T,
             const float* __restrict__ g2, const float* __restrict__ be2,
             float* __restrict__ o2T)
{
    extern __shared__ char sm[];
    const int t = threadIdx.x, wid = t >> 5, lane = t & 31;
    const int xt = blockIdx.x;
    const int sp = blockIdx.y >> 2, hh = blockIdx.y & 3;
    const int b = blockIdx.z;

    const size_t qrow = (size_t)b * NN + sp * 256 + xt * 128;
    const float* qp  = qT  + qrow * PP + hh * DH;
    const float* kp  = kT  + ((size_t)b * NN + sp * 256) * PP + hh * DH;
    const float* vp  = v   + ((size_t)b * PP + hh * DH) * NN + sp * 256;
    const float* o1p = o1T + qrow * PP + hh * DH;
    float* o2p       = o2T + qrow * PP + hh * DH;

#if HAS_TCGEN05
    const uint32_t sbase = smem_u32(sm);
    if (t == 0) { MBAR_INIT(sbase + 16, 1); MBAR_INIT(sbase + 24, 1); }
    if (wid == 0) TM_ALLOC(sbase + 0, 512);
    ((float*)(sm + 1024))[t] = g2[hh * DH + t] * INVF;
    ((float*)(sm + 1536))[t] = be2[hh * DH + t];
    __syncthreads();
    uint32_t tmem;
    asm volatile("ld.shared.b32 %0, [%1];" : "=r"(tmem) : "r"(sbase + 0));
    const uint32_t kvoff[2] = {AS_KV0, AS_KV1};

#pragma unroll
    for (int r = 0; r < 32; r++) {
        int i = t + r * 128;
        int row = i >> 5, rem = i & 31, j = rem >> 3, seg = rem & 7;
        float4 vq = *(const float4*)(qp + (size_t)row * PP + j * 32 + seg * 4);
        *(float4*)(sm + AS_Q + j * 16384 + SW128(row * 128 + seg * 16)) = vq;
    }

    float4 kv[16];
#pragma unroll
    for (int r = 0; r < 16; r++) {
        int i = t + r * 128, row = i >> 3, seg = i & 7;
        kv[r] = *(const float4*)(kp + (size_t)row * PP + seg * 4);
    }
    for (int c = 0; c < 4; c++) {
        const int buf = c & 1;
        const uint32_t mb = sbase + 16 + 8 * buf;
        if (c >= 2) MBAR_WAIT(mb, 0);
#pragma unroll
        for (int r = 0; r < 16; r++) {
            int i = t + r * 128, row = i >> 3, seg = i & 7;
            *(float4*)(sm + kvoff[buf] + SW128(row * 128 + seg * 16)) = kv[r];
        }
        if (c < 3) {
#pragma unroll
            for (int r = 0; r < 16; r++) {
                int i = t + r * 128, row = i >> 3, seg = i & 7;
                kv[r] = *(const float4*)(kp + (size_t)row * PP + (c + 1) * 32 + seg * 4);
            }
        }
        __syncthreads();
        if (wid == 0 && elect1()) {
            FENCE_ASYNC();
            uint64_t qd = mkdesc(sbase + AS_Q + c * 16384);
            uint64_t kd = mkdesc(sbase + kvoff[buf]);
#pragma unroll
            for (int s = 0; s < 4; s++)
                mma_ss(tmem, qd + s * 2, kd + s * 2, IDESC_256,
                       (c > 0 || s > 0) ? 1u : 0u);
            TM_COMMIT(mb);
        }
    }
    MBAR_WAIT(sbase + 24, 1);
    TM_FENCE_AFTER();

    uint32_t rs[32];
    float mx = -1e30f;
#pragma unroll
    for (int cc = 0; cc < 8; cc++) {
        TM_LD_X32(rs, tmem + cc * 32);
        TM_WAIT_LD();
#pragma unroll
        for (int i = 0; i < 32; i++) mx = fmaxf(mx, __uint_as_float(rs[i]));
    }
    float ssum = 0.f;
#pragma unroll
    for (int cc = 0; cc < 8; cc++) {
        TM_LD_X32(rs, tmem + cc * 32);
        TM_WAIT_LD();
#pragma unroll
        for (int i = 0; i < 32; i++) {
            float e = __expf(__uint_as_float(rs[i]) - mx);
            ssum += e;
            rs[i] = __float_as_uint(e);
        }
        TM_ST_X32(tmem + cc * 32, rs);
    }
    TM_WAIT_ST();
    const float sinv = 1.f / ssum;
    TM_FENCE_BEFORE();

#pragma unroll
    for (int r = 0; r < 16; r++) {
        int i = t + r * 128, row = i >> 4, seg = i & 15;
        kv[r] = *(const float4*)(vp + (size_t)row * NN + seg * 4);
    }
    for (int j = 0; j < 4; j++) {
        const int buf = j & 1;
        const uint32_t mb = sbase + 16 + 8 * buf;
        if (j >= 2) MBAR_WAIT(mb, 0);
#pragma unroll
        for (int r = 0; r < 16; r++) {
            int i = t + r * 128, row = i >> 4, seg = i & 15;
            *(float4*)(sm + kvoff[buf] + (seg >> 3) * 16384 +
                       SW128(row * 128 + (seg & 7) * 16)) = kv[r];
        }
        if (j < 3) {
#pragma unroll
            for (int r = 0; r < 16; r++) {
                int i = t + r * 128, row = i >> 4, seg = i & 15;
                kv[r] = *(const float4*)(vp + (size_t)row * NN + (j + 1) * 64 + seg * 4);
            }
        }
        __syncthreads();
        if (wid == 0 && elect1()) {
            FENCE_ASYNC();
            TM_FENCE_AFTER();
            uint64_t vd = mkdesc(sbase + kvoff[buf]);
#pragma unroll
            for (int s = 0; s < 8; s++)
                mma_ts(tmem + 256, tmem + j * 64 + s * 8,
                       vd + (s >> 2) * 1024 + (s & 3) * 2, IDESC_128,
                       (j > 0 || s > 0) ? 1u : 0u);
            TM_COMMIT(mb);
        }
    }
    MBAR_WAIT(sbase + 24, 1);
    TM_FENCE_AFTER();

    const float* g2s  = (const float*)(sm + 1024);
    const float* be2s = (const float*)(sm + 1536);
    const float* myo1 = o1p + (size_t)(wid * 32 + lane) * PP;
    float* myo2       = o2p + (size_t)(wid * 32 + lane) * PP;
#pragma unroll
    for (int k = 0; k < 4; k++) {
        TM_LD_X32(rs, tmem + 256 + k * 32);
        TM_WAIT_LD();
#pragma unroll
        for (int i = 0; i < 32; i += 4) {
            int d = k * 32 + i;
            float4 r1 = *(const float4*)(myo1 + d);
            float4 o;
            o.x = to_tf32(fmaxf(fmaf(fmaf(__uint_as_float(rs[i + 0]), sinv, r1.x), g2s[d + 0], be2s[d + 0]), 0.f));
            o.y = to_tf32(fmaxf(fmaf(fmaf(__uint_as_float(rs[i + 1]), sinv, r1.y), g2s[d + 1], be2s[d + 1]), 0.f));
            o.z = to_tf32(fmaxf(fmaf(fmaf(__uint_as_float(rs[i + 2]), sinv, r1.z), g2s[d + 2], be2s[d + 2]), 0.f));
            o.w = to_tf32(fmaxf(fmaf(fmaf(__uint_as_float(rs[i + 3]), sinv, r1.w), g2s[d + 3], be2s[d + 3]), 0.f));
            *(float4*)(myo2 + d) = o;
        }
    }
    __syncthreads();
    if (wid == 0) TM_DEALLOC(tmem, 512);

#else  // ---------------- fp32 fallback (never runs on GB300) ---------------
    const int x = t;
    float sb[256];
    float mx = -1e30f;
    for (int y = 0; y < 256; y++) {
        float s = 0.f;
        for (int d = 0; d < DH; d++)
            s += qp[(size_t)x * PP + d] * kp[(size_t)y * PP + d];
        sb[y] = s;
        mx = fmaxf(mx, s);
    }
    float ssum = 0.f;
    for (int y = 0; y < 256; y++) { sb[y] = __expf(sb[y] - mx); ssum += sb[y]; }
    float sinv = 1.f / ssum;
    for (int d = 0; d < DH; d++) {
        float o = 0.f;
        for (int y = 0; y < 256; y++) o += sb[y] * vp[(size_t)d * NN + y];
        float val = (o * sinv + o1p[(size_t)x * PP + d]) * (g2[hh * DH + d] * INVF)
                    + be2[hh * DH + d];
        o2p[(size_t)x * PP + d] = to_tf32(fmaxf(val, 0.f));
    }
#endif
}

// ---------------------------------------------------------------------------
extern "C" void kernel_launch(void* const* d_in, const int* in_sizes, int n_in,
                              void* d_out, int out_size)
{
    const float* x   = (const float*)d_in[0];
    const float* w1  = (const float*)d_in[1];
    const float* b1  = (const float*)d_in[2];
    const float* g1  = (const float*)d_in[3];
    const float* be1 = (const float*)d_in[4];
    const float* wq  = (const float*)d_in[5];
    const float* wk  = (const float*)d_in[6];
    const float* wv  = (const float*)d_in[7];
    const float* g2  = (const float*)d_in[8];
    const float* be2 = (const float*)d_in[9];
    const float* w3  = (const float*)d_in[10];
    const float* b3  = (const float*)d_in[11];
    const float* g3  = (const float*)d_in[12];
    const float* be3 = (const float*)d_in[13];
    float* out = (float*)d_out;

    float *xT, *o1T, *qT, *kT, *vb, *o2T, *wr;
    cudaGetSymbolAddress((void**)&xT,  g_xT);
    cudaGetSymbolAddress((void**)&o1T, g_o1T);
    cudaGetSymbolAddress((void**)&qT,  g_qT);
    cudaGetSymbolAddress((void**)&kT,  g_kT);
    cudaGetSymbolAddress((void**)&vb,  g_v);
    cudaGetSymbolAddress((void**)&o2T, g_o2T);
    cudaGetSymbolAddress((void**)&wr,  g_wr);

    cudaFuncSetAttribute((const void*)tgemm256<0>, cudaFuncAttributeMaxDynamicSharedMemorySize, GSMEM);
    cudaFuncSetAttribute((const void*)tgemm256<1>, cudaFuncAttributeMaxDynamicSharedMemorySize, GSMEM);
    cudaFuncSetAttribute((const void*)tgemm256<2>, cudaFuncAttributeMaxDynamicSharedMemorySize, GSMEM);
    cudaFuncSetAttribute((const void*)attn_tc, cudaFuncAttributeMaxDynamicSharedMemorySize, ASMEM);

    // 0a) round all weights to tf32 (single launch, contiguous g_wr)
    round_w5<<<(N4_TOT + 255) / 256, 256>>>(w1, wq, wk, wv, w3, wr);
    // 0b) xT[b][hw][c] (tf32-rounded)
    transpose_k<<<dim3(64, 32, BB), 256>>>(x, xT, CIN, NN);
    // 1) o1T = relu(bn1(conv1(x)))^T  [b][hw][p], rounded
    tgemm256<0><<<dim3(8, 4, BB), 256, GSMEM>>>(wr + WR_W1, xT, o1T, nullptr, nullptr,
                                                g1, be1, b1, nullptr, PP, CIN);
    // 2) fused qkv: qT (scaled, trans), kT (trans), v (normal); all rounded
    tgemm256<1><<<dim3(8, 12, BB), 256, GSMEM>>>(wr + WR_WQ, o1T, qT, kT, vb,
                                                 nullptr, nullptr, nullptr, nullptr,
                                                 1536, PP);
    // 3) attention + residual + bn2 + relu -> o2T [b][hw][p], rounded
    attn_tc<<<dim3(2, 32, BB), 128, ASMEM>>>(qT, kT, vb, o1T, g2, be2, o2T);
    // 4) out = relu(bn3(conv3) + x)
    tgemm256<2><<<dim3(8, 8, BB), 256, GSMEM>>>(wr + WR_W3, o2T, out, nullptr, nullptr,
                                                g3, be3, b3, x, CIN, PP);
}

// round 8
// speedup vs baseline: 6.8541x; 1.0571x over previous
#include <cuda_runtime.h>
#include <cstdint>

// Problem constants
#define BB 16
#define CIN 1024
#define PP 512
#define NN 2048          // H*W
#define DH 128           // head dim
#define INVF 0.99999500003749969f      // 1/sqrt(1+1e-5)
#define QSCALE 0.08838834764831843f    // 128^-0.5
#define GRID_P 152                      // GB300 SM count (persistent grid)

#if defined(__CUDA_ARCH__) && (__CUDA_ARCH__ >= 1000) && \
    (defined(__CUDA_ARCH_FEAT_SM103_ALL) || defined(__CUDA_ARCH_FEAT_SM100_ALL) || \
     defined(__CUDA_ARCH_SPECIFIC__) || defined(__CUDA_ARCH_FAMILY_SPECIFIC__))
#define HAS_TCGEN05 1
#else
#define HAS_TCGEN05 0
#endif

// Scratch (device globals)
__device__ float g_xT [(size_t)BB * CIN * NN];   // [b][hw][c]  (tf32-rounded)
__device__ float g_o1T[(size_t)BB * PP * NN];    // [b][hw][p]  (tf32-rounded)
__device__ float g_qT [(size_t)BB * PP * NN];    // [b][hw][p]  (tf32-rounded)
__device__ float g_kT [(size_t)BB * PP * NN];    // [b][hw][p]  (tf32-rounded)
__device__ float g_v  [(size_t)BB * PP * NN];    // [b][p][hw]  (tf32-rounded)
__device__ float g_o2T[(size_t)BB * PP * NN];    // [b][hw][p]  (tf32-rounded)
// Rounded weights, contiguous: w1 | wq | wk | wv | w3
#define WR_W1 0
#define WR_WQ (512 * 1024)
#define WR_WK (WR_WQ + 512 * 512)
#define WR_WV (WR_WK + 512 * 512)
#define WR_W3 (WR_WV + 512 * 512)
__device__ float g_wr[WR_W3 + 1024 * 512];

// ---------------------------------------------------------------------------
__device__ __forceinline__ uint32_t smem_u32(const void* p) {
    uint32_t a;
    asm("{ .reg .u64 t; cvta.to.shared.u64 t, %1; cvt.u32.u64 %0, t; }"
        : "=r"(a) : "l"(p));
    return a;
}
__device__ __forceinline__ float to_tf32(float x) {
    float r; asm("cvt.rna.tf32.f32 %0, %1;" : "=f"(r) : "f"(x)); return r;
}

#if HAS_TCGEN05
__device__ __forceinline__ uint32_t elect1() {
    uint32_t p;
    asm volatile("{ .reg .pred p; elect.sync _|p, 0xFFFFFFFF; selp.b32 %0,1,0,p; }"
                 : "=r"(p));
    return p;
}
#define SW128(o) ((o) ^ ((((uint32_t)(o)) >> 3) & 0x70))

#define MBAR_INIT(a, c) \
    asm volatile("mbarrier.init.shared.b64 [%0], %1;" :: "r"(a), "r"(c) : "memory")

#define MBAR_WAIT(a, ph) do { \
    uint32_t _d; \
    asm volatile("{ .reg .pred p; mbarrier.try_wait.parity.acquire.cta.shared::cta.b64 p,[%1],%2; selp.b32 %0,1,0,p; }" \
                 : "=r"(_d) : "r"(a), "r"((uint32_t)(ph)) : "memory"); \
    if (!_d) { \
        asm volatile("{ .reg .pred P;\nLW_%=:\nmbarrier.try_wait.parity.acquire.cta.shared::cta.b64 P,[%0],%1,0x989680;\n@P bra.uni LD_%=;\nbra.uni LW_%=;\nLD_%=:\n}" \
                     :: "r"(a), "r"((uint32_t)(ph)) : "memory"); \
    } } while (0)

#define TM_ALLOC(sa, n) \
    asm volatile("tcgen05.alloc.cta_group::1.sync.aligned.shared::cta.b32 [%0], %1;" \
                 :: "r"(sa), "r"(n) : "memory")
#define TM_DEALLOC(t, n) \
    asm volatile("tcgen05.dealloc.cta_group::1.sync.aligned.b32 %0, %1;" :: "r"(t), "r"(n))
#define TM_COMMIT(mb) \
    asm volatile("tcgen05.commit.cta_group::1.mbarrier::arrive::one.shared::cluster.b64 [%0];" \
                 :: "r"(mb) : "memory")
#define TM_FENCE_AFTER()  asm volatile("tcgen05.fence::after_thread_sync;" ::: "memory")
#define TM_FENCE_BEFORE() asm volatile("tcgen05.fence::before_thread_sync;" ::: "memory")
#define TM_WAIT_LD()      asm volatile("tcgen05.wait::ld.sync.aligned;" ::: "memory")
#define TM_WAIT_ST()      asm volatile("tcgen05.wait::st.sync.aligned;" ::: "memory")
#define FENCE_ASYNC()     asm volatile("fence.proxy.async.shared::cta;" ::: "memory")

#define CP_ASYNC16(dst, src) \
    asm volatile("cp.async.cg.shared.global [%0], [%1], 16;" \
                 :: "r"(dst), "l"(src) : "memory")
#define CP_COMMIT() asm volatile("cp.async.commit_group;" ::: "memory")
#define CP_WAIT(n)  asm volatile("cp.async.wait_group %0;" :: "n"(n) : "memory")

#define TM_LD_X32(r, addr) \
    asm volatile("tcgen05.ld.sync.aligned.32x32b.x32.b32 " \
        "{%0,%1,%2,%3,%4,%5,%6,%7,%8,%9,%10,%11,%12,%13,%14,%15," \
        "%16,%17,%18,%19,%20,%21,%22,%23,%24,%25,%26,%27,%28,%29,%30,%31}, [%32];" \
        : "=r"((r)[0]),"=r"((r)[1]),"=r"((r)[2]),"=r"((r)[3]), \
          "=r"((r)[4]),"=r"((r)[5]),"=r"((r)[6]),"=r"((r)[7]), \
          "=r"((r)[8]),"=r"((r)[9]),"=r"((r)[10]),"=r"((r)[11]), \
          "=r"((r)[12]),"=r"((r)[13]),"=r"((r)[14]),"=r"((r)[15]), \
          "=r"((r)[16]),"=r"((r)[17]),"=r"((r)[18]),"=r"((r)[19]), \
          "=r"((r)[20]),"=r"((r)[21]),"=r"((r)[22]),"=r"((r)[23]), \
          "=r"((r)[24]),"=r"((r)[25]),"=r"((r)[26]),"=r"((r)[27]), \
          "=r"((r)[28]),"=r"((r)[29]),"=r"((r)[30]),"=r"((r)[31]) \
        : "r"(addr))

#define TM_ST_X32(addr, r) \
    asm volatile("tcgen05.st.sync.aligned.32x32b.x32.b32 [%0], " \
        "{%1,%2,%3,%4,%5,%6,%7,%8,%9,%10,%11,%12,%13,%14,%15,%16," \
        "%17,%18,%19,%20,%21,%22,%23,%24,%25,%26,%27,%28,%29,%30,%31,%32};" \
        :: "r"(addr), \
           "r"((r)[0]),"r"((r)[1]),"r"((r)[2]),"r"((r)[3]), \
           "r"((r)[4]),"r"((r)[5]),"r"((r)[6]),"r"((r)[7]), \
           "r"((r)[8]),"r"((r)[9]),"r"((r)[10]),"r"((r)[11]), \
           "r"((r)[12]),"r"((r)[13]),"r"((r)[14]),"r"((r)[15]), \
           "r"((r)[16]),"r"((r)[17]),"r"((r)[18]),"r"((r)[19]), \
           "r"((r)[20]),"r"((r)[21]),"r"((r)[22]),"r"((r)[23]), \
           "r"((r)[24]),"r"((r)[25]),"r"((r)[26]),"r"((r)[27]), \
           "r"((r)[28]),"r"((r)[29]),"r"((r)[30]),"r"((r)[31]) \
        : "memory")

__device__ __forceinline__ uint64_t mkdesc(uint32_t addr) {
    return ((uint64_t)2 << 61) | ((uint64_t)1 << 46) | ((uint64_t)64 << 32) |
           ((uint64_t)1 << 16) | ((addr >> 4) & 0x3FFF);
}
__device__ __forceinline__ void mma_ss(uint32_t d, uint64_t ad, uint64_t bd,
                                       uint32_t id, uint32_t en) {
    asm volatile(
        "{ .reg .pred p; setp.ne.u32 p, %5, 0;\n\t"
        "tcgen05.mma.cta_group::1.kind::tf32 [%0], %1, %2, %3, {%4,%4,%4,%4}, p;\n\t}"
        :: "r"(d), "l"(ad), "l"(bd), "r"(id), "r"(0u), "r"(en) : "memory");
}
__device__ __forceinline__ void mma_ts(uint32_t d, uint32_t a, uint64_t bd,
                                       uint32_t id, uint32_t en) {
    asm volatile(
        "{ .reg .pred p; setp.ne.u32 p, %5, 0;\n\t"
        "tcgen05.mma.cta_group::1.kind::tf32 [%0], [%1], %2, %3, {%4,%4,%4,%4}, p;\n\t}"
        :: "r"(d), "r"(a), "l"(bd), "r"(id), "r"(0u), "r"(en) : "memory");
}
#define IDESC_128 ((1u << 4) | (2u << 7) | (2u << 10) | (16u << 17) | (8u << 24))
#define IDESC_256 ((1u << 4) | (2u << 7) | (2u << 10) | (32u << 17) | (8u << 24))
#endif  // HAS_TCGEN05

// ---------------------------------------------------------------------------
// Round all 5 weight matrices to tf32 in one launch, into contiguous g_wr
// ---------------------------------------------------------------------------
#define N4_W1 131072
#define N4_P  65536
#define N4_W3 131072
#define N4_TOT (N4_W1 + 3 * N4_P + N4_W3)

__global__ __launch_bounds__(256)
void round_w5(const float* __restrict__ w1, const float* __restrict__ wq,
              const float* __restrict__ wk, const float* __restrict__ wv,
              const float* __restrict__ w3, float* __restrict__ out)
{
    int i = blockIdx.x * 256 + threadIdx.x;
    if (i >= N4_TOT) return;
    const float4* src;
    int j = i;
    if (j < N4_W1) src = (const float4*)w1;
    else if ((j -= N4_W1) < N4_P) src = (const float4*)wq;
    else if ((j -= N4_P) < N4_P) src = (const float4*)wk;
    else if ((j -= N4_P) < N4_P) src = (const float4*)wv;
    else { j -= N4_P; src = (const float4*)w3; }
    float4 v = src[j];
    v.x = to_tf32(v.x); v.y = to_tf32(v.y);
    v.z = to_tf32(v.z); v.w = to_tf32(v.w);
    ((float4*)out)[i] = v;
}

// ---------------------------------------------------------------------------
// Tiled transpose per batch with tf32 rounding: in[b][R][C] -> out[b][C][R]
// ---------------------------------------------------------------------------
__global__ __launch_bounds__(256)
void transpose_k(const float* __restrict__ in, float* __restrict__ out, int R, int C)
{
    __shared__ float tile[32][33];
    const int b = blockIdx.z;
    const float* ip = in + (size_t)b * R * C;
    float* op = out + (size_t)b * R * C;
    const int c0 = blockIdx.x * 32, r0 = blockIdx.y * 32;
    const int tx = threadIdx.x & 31, ty = threadIdx.x >> 5;
#pragma unroll
    for (int i = 0; i < 32; i += 8)
        tile[ty + i][tx] = ip[(size_t)(r0 + ty + i) * C + c0 + tx];
    __syncthreads();
#pragma unroll
    for (int i = 0; i < 32; i += 8)
        op[(size_t)(c0 + ty + i) * R + r0 + tx] = to_tf32(tile[tx][ty + i]);
}

// ---------------------------------------------------------------------------
// Persistent tcgen05 tf32 GEMM. 128m x 256n tiles, 4-stage cp.async pipeline
// with a GLOBAL chunk counter across tiles; TMEM 512 cols = 2 accumulation
// buffers (tile parity); epilogue of tile i-1 runs while tile i's MMAs fly.
// All stores are register-direct coalesced STG.32 (lane dim = contiguous dim).
// MODE 0: conv1  D[p][hw]  -> o1T[hw][p]   (bn1+relu, rnd; per-lane bn)
// MODE 1: qkv    id<1024: D[p][hw] -> qT/kT[hw][p] (q scaled; rnd)
//                id>=1024 (flipped): D[hw][p] -> v[p][hw] (rnd)
// MODE 2: conv3 (flipped) D[hw][c] -> out[c][hw]  (bn3 per-reg + resid + relu)
// ---------------------------------------------------------------------------
#define NSTAGE 4
#define STAGE_B 49152u
#define GS_BN   (1024u + NSTAGE * STAGE_B)          // bn tables for MODE 2
#define GSMEM   (GS_BN + 2 * 1024 * 4)              // 205824 B

template <int MODE>
__device__ __forceinline__ void tile_ab(int id, const float* W, const float* ACT,
                                        const float*& A, const float*& B)
{
    if (MODE == 0) {
        int m0 = (id & 3) << 7, n0 = ((id >> 2) & 7) << 8, bz = id >> 5;
        A = W + (size_t)m0 * 1024;
        B = ACT + ((size_t)bz * NN + n0) * 1024;
    } else if (MODE == 1) {
        if (id < 1024) {
            int m0 = (id & 7) << 7, n0 = ((id >> 3) & 7) << 8, bz = id >> 6;
            A = W + (size_t)m0 * 512;
            B = ACT + ((size_t)bz * NN + n0) * 512;
        } else {
            int j = id - 1024;
            int m0 = (j & 15) << 7, n0 = ((j >> 4) & 1) << 8, bz = j >> 5;
            A = ACT + ((size_t)bz * NN + m0) * 512;   // activations on M side
            B = W + 524288u + (size_t)n0 * 512;       // wv
        }
    } else {
        int m0 = (id & 15) << 7, n0 = ((id >> 4) & 3) << 8, bz = id >> 6;
        A = ACT + ((size_t)bz * NN + m0) * 512;       // o2T rows (hw)
        B = W + (size_t)n0 * 512;                     // w3 rows (c)
    }
}

// Single-element epilogue (shared by the fp32 fallback)
template <int MODE>
__device__ __forceinline__ void epi_scalar(int id, int ml, int n, float acc,
    float* O0, float* O1, float* O2, const float* resid,
    const float* g, const float* be, const float* cb)
{
    if (MODE == 0) {
        int m0 = (id & 3) << 7, n0 = ((id >> 2) & 7) << 8, bz = id >> 5;
        int m = m0 + ml;
        float s = g[m] * INVF, tt = cb[m] * s + be[m];
        O0[((size_t)bz * NN + n0 + n) * 512 + m] = to_tf32(fmaxf(fmaf(acc, s, tt), 0.f));
    } else if (MODE == 1) {
        if (id < 1024) {
            int m0 = (id & 7) << 7, n0 = ((id >> 3) & 7) << 8, bz = id >> 6;
            float* T = (m0 < 512) ? O0 : O1;
            float qs = (m0 < 512) ? QSCALE : 1.f;
            T[((size_t)bz * NN + n0 + n) * 512 + ((m0 + ml) & 511)] = to_tf32(acc * qs);
        } else {
            int j = id - 1024;
            int m0 = (j & 15) << 7, n0 = ((j >> 4) & 1) << 8, bz = j >> 5;
            O2[((size_t)bz * 512 + n0 + n) * NN + m0 + ml] = to_tf32(acc);
        }
    } else {
        int m0 = (id & 15) << 7, n0 = ((id >> 4) & 3) << 8, bz = id >> 6;
        int c = n0 + n;
        float s = g[c] * INVF, tt = cb[c] * s + be[c];
        size_t off = ((size_t)bz * 1024 + c) * NN + m0 + ml;
        O0[off] = fmaxf(fmaf(acc, s, tt) + resid[off], 0.f);
    }
}

#if HAS_TCGEN05
template <int MODE>
__device__ __forceinline__ void issue_chunk(uint32_t sbase, int gc, int cta,
                                            const float* W, const float* ACT, int t)
{
    constexpr int NKS = (MODE == 0) ? 5 : 4;
    constexpr int K = (MODE == 0) ? 1024 : 512;
    const int lt = gc >> NKS, c = gc & ((1 << NKS) - 1);
    const float *A, *B;
    tile_ab<MODE>(cta + lt * GRID_P, W, ACT, A, B);
    const uint32_t st = sbase + 1024u + (uint32_t)(gc & 3) * STAGE_B;
#pragma unroll
    for (int r = 0; r < 4; r++) {
        int idx = t + r * 256, row = idx >> 3, seg = idx & 7;
        CP_ASYNC16(st + SW128(row * 128 + seg * 16),
                   A + (size_t)row * K + c * 32 + seg * 4);
    }
#pragma unroll
    for (int r = 0; r < 8; r++) {
        int idx = t + r * 256, row = idx >> 3, seg = idx & 7;
        CP_ASYNC16(st + 16384u + SW128(row * 128 + seg * 16),
                   B + (size_t)row * K + c * 32 + seg * 4);
    }
    CP_COMMIT();
}

// Register-direct epilogue; lane dim is always the output-contiguous dim.
template <int MODE>
__device__ __forceinline__ void epi_tile(int id, int abuf, uint32_t tmem, char* smem,
    float* O0, float* O1, float* O2, const float* resid,
    const float* g, const float* be, const float* cb, int wid, int lane)
{
    float* Ob; const float* Rb = nullptr;
    size_t sN; int n0g = 0, m0;
    float qs = 1.f;
    if (MODE == 0) {
        m0 = (id & 3) << 7; int n0 = ((id >> 2) & 7) << 8; int bz = id >> 5;
        Ob = O0 + ((size_t)bz * NN + n0) * 512 + m0;  sN = 512;
    } else if (MODE == 1) {
        if (id < 1024) {
            m0 = (id & 7) << 7; int n0 = ((id >> 3) & 7) << 8; int bz = id >> 6;
            float* T = (m0 < 512) ? O0 : O1;
            if (m0 < 512) qs = QSCALE;
            Ob = T + ((size_t)bz * NN + n0) * 512 + (m0 & 511);  sN = 512;
        } else {
            int j = id - 1024;
            m0 = (j & 15) << 7; int n0 = ((j >> 4) & 1) << 8; int bz = j >> 5;
            Ob = O2 + ((size_t)bz * 512 + n0) * NN + m0;  sN = NN;
        }
    } else {
        m0 = (id & 15) << 7; int n0 = ((id >> 4) & 3) << 8; int bz = id >> 6;
        Ob = O0 + ((size_t)bz * 1024 + n0) * NN + m0;
        Rb = resid + ((size_t)bz * 1024 + n0) * NN + m0;
        sN = NN; n0g = n0;
    }
    const int sp = wid & 3, ch = wid >> 2;
    const int ml = sp * 32 + lane;
    float sL = qs, tL = 0.f;
    if (MODE == 0) { int m = m0 + ml; sL = g[m] * INVF; tL = cb[m] * sL + be[m]; }
    const float* bs = (const float*)(smem + GS_BN);          // MODE2: s table
    const float* bt = (const float*)(smem + GS_BN + 4096);   // MODE2: t table

    TM_FENCE_AFTER();
    uint32_t r0[32], r1[32];
#pragma unroll
    for (int h = 0; h < 2; h++) {
        TM_LD_X32(r0, tmem + abuf * 256 + h * 128 + ch * 64);
        TM_LD_X32(r1, tmem + abuf * 256 + h * 128 + ch * 64 + 32);
        TM_WAIT_LD();
#pragma unroll
        for (int i = 0; i < 32; i++) {
            const int n = h * 128 + ch * 64 + i, n2 = n + 32;
            float v0 = __uint_as_float(r0[i]);
            float v1 = __uint_as_float(r1[i]);
            if (MODE == 2) {
                v0 = fmaxf(fmaf(v0, bs[n0g + n],  bt[n0g + n])  + Rb[(size_t)n  * sN + ml], 0.f);
                v1 = fmaxf(fmaf(v1, bs[n0g + n2], bt[n0g + n2]) + Rb[(size_t)n2 * sN + ml], 0.f);
            } else if (MODE == 0) {
                v0 = to_tf32(fmaxf(fmaf(v0, sL, tL), 0.f));
                v1 = to_tf32(fmaxf(fmaf(v1, sL, tL), 0.f));
            } else {
                v0 = to_tf32(v0 * sL);
                v1 = to_tf32(v1 * sL);
            }
            Ob[(size_t)n  * sN + ml] = v0;
            Ob[(size_t)n2 * sN + ml] = v1;
        }
    }
    TM_FENCE_BEFORE();
}
#endif  // HAS_TCGEN05

template <int MODE>
__global__ __launch_bounds__(256)
void tgp(const float* __restrict__ W, const float* __restrict__ ACT,
         float* __restrict__ O0, float* __restrict__ O1, float* __restrict__ O2,
         const float* __restrict__ resid,
         const float* __restrict__ g, const float* __restrict__ be,
         const float* __restrict__ cb)
{
    constexpr int TOT   = (MODE == 0) ? 512 : (MODE == 1) ? 1536 : 1024;
    constexpr int NKS   = (MODE == 0) ? 5 : 4;
    constexpr int NK    = 1 << NKS;
    const int cta = blockIdx.x;
    const int t = threadIdx.x;
    const int ntl = (TOT - cta + GRID_P - 1) / GRID_P;
    if (ntl <= 0) return;
    const int totc = ntl * NK;

#if HAS_TCGEN05
    extern __shared__ char smem[];
    const uint32_t sbase = smem_u32(smem);
    const int wid = t >> 5, lane = t & 31;

    if (t < NSTAGE) MBAR_INIT(sbase + 16 + 8 * t, 1);
    if (wid == 0) TM_ALLOC(sbase + 0, 512);
    if (MODE == 2) {   // precompute bn3 scale/bias tables (1024 channels)
        for (int i = t; i < 1024; i += 256) {
            float s = g[i] * INVF;
            ((float*)(smem + GS_BN))[i] = s;
            ((float*)(smem + GS_BN + 4096))[i] = cb[i] * s + be[i];
        }
    }
    __syncthreads();
    uint32_t tmem;
    asm volatile("ld.shared.b32 %0, [%1];" : "=r"(tmem) : "r"(sbase + 0));

    issue_chunk<MODE>(sbase, 0, cta, W, ACT, t);
    issue_chunk<MODE>(sbase, 1, cta, W, ACT, t);
    issue_chunk<MODE>(sbase, 2, cta, W, ACT, t);

    for (int gc = 0; gc < totc; gc++) {
        const int c = gc & (NK - 1);
        const int rem = totc - 1 - gc;
        if (rem >= 2) CP_WAIT(2);
        else if (rem == 1) CP_WAIT(1);
        else CP_WAIT(0);
        __syncthreads();

        if (wid == 0 && elect1()) {
            FENCE_ASYNC();
            const uint32_t st = sbase + 1024u + (uint32_t)(gc & 3) * STAGE_B;
            const uint64_t ad = mkdesc(st);
            const uint64_t bd = mkdesc(st + 16384u);
            const uint32_t dacc = tmem + (uint32_t)(((gc >> NKS) & 1) << 8);
#pragma unroll
            for (int s = 0; s < 4; s++)
                mma_ss(dacc, ad + s * 2, bd + s * 2, IDESC_256,
                       (c > 0 || s > 0) ? 1u : 0u);
            TM_COMMIT(sbase + 16 + 8 * (gc & 3));
        }
        if (gc >= 1)
            MBAR_WAIT(sbase + 16 + 8 * ((gc - 1) & 3), ((gc - 1) >> 2) & 1);
        if (gc + 3 < totc) issue_chunk<MODE>(sbase, gc + 3, cta, W, ACT, t);

        if (c == NK - 1) {   // tile (gc>>NKS) fully issued; drain tile-1
            const int lt = gc >> NKS;
            if (lt >= 1)
                epi_tile<MODE>(cta + (lt - 1) * GRID_P, (lt - 1) & 1, tmem, smem,
                               O0, O1, O2, resid, g, be, cb, wid, lane);
        }
    }
    MBAR_WAIT(sbase + 16 + 8 * ((totc - 1) & 3), ((totc - 1) >> 2) & 1);
    epi_tile<MODE>(cta + (ntl - 1) * GRID_P, (ntl - 1) & 1, tmem, smem,
                   O0, O1, O2, resid, g, be, cb, wid, lane);
    __syncthreads();
    if (wid == 0) TM_DEALLOC(tmem, 512);

#else  // ---------------- fp32 fallback (never runs on GB300) ---------------
    constexpr int K = (MODE == 0) ? 1024 : 512;
    for (int lt = 0; lt < ntl; lt++) {
        const int id = cta + lt * GRID_P;
        const float *A, *B;
        tile_ab<MODE>(id, W, ACT, A, B);
        for (int e = t; e < 128 * 256; e += 256) {
            const int ml = e & 127, n = e >> 7;
            float acc = 0.f;
            for (int k = 0; k < K; k++)
                acc += A[(size_t)ml * K + k] * B[(size_t)n * K + k];
            epi_scalar<MODE>(id, ml, n, acc, O0, O1, O2, resid, g, be, cb);
        }
    }
#endif
}

// ---------------------------------------------------------------------------
// tcgen05 attention (R6/R7, verified) + tf32-rounded o2T output
// ---------------------------------------------------------------------------
#define AS_Q   2048u
#define AS_KV0 (2048u + 65536u)
#define AS_KV1 (2048u + 65536u + 32768u)
#define ASMEM  133120

__global__ __launch_bounds__(128)
void attn_tc(const float* __restrict__ qT, const float* __restrict__ kT,
             const float* __restrict__ v, const float* __restrict__ o1T,
             const float* __restrict__ g2, const float* __restrict__ be2,
             float* __restrict__ o2T)
{
    extern __shared__ char sm[];
    const int t = threadIdx.x, wid = t >> 5, lane = t & 31;
    const int xt = blockIdx.x;
    const int sp = blockIdx.y >> 2, hh = blockIdx.y & 3;
    const int b = blockIdx.z;

    const size_t qrow = (size_t)b * NN + sp * 256 + xt * 128;
    const float* qp  = qT  + qrow * PP + hh * DH;
    const float* kp  = kT  + ((size_t)b * NN + sp * 256) * PP + hh * DH;
    const float* vp  = v   + ((size_t)b * PP + hh * DH) * NN + sp * 256;
    const float* o1p = o1T + qrow * PP + hh * DH;
    float* o2p       = o2T + qrow * PP + hh * DH;

#if HAS_TCGEN05
    const uint32_t sbase = smem_u32(sm);
    if (t == 0) { MBAR_INIT(sbase + 16, 1); MBAR_INIT(sbase + 24, 1); }
    if (wid == 0) TM_ALLOC(sbase + 0, 512);
    ((float*)(sm + 1024))[t] = g2[hh * DH + t] * INVF;
    ((float*)(sm + 1536))[t] = be2[hh * DH + t];
    __syncthreads();
    uint32_t tmem;
    asm volatile("ld.shared.b32 %0, [%1];" : "=r"(tmem) : "r"(sbase + 0));
    const uint32_t kvoff[2] = {AS_KV0, AS_KV1};

#pragma unroll
    for (int r = 0; r < 32; r++) {
        int i = t + r * 128;
        int row = i >> 5, rem = i & 31, j = rem >> 3, seg = rem & 7;
        float4 vq = *(const float4*)(qp + (size_t)row * PP + j * 32 + seg * 4);
        *(float4*)(sm + AS_Q + j * 16384 + SW128(row * 128 + seg * 16)) = vq;
    }

    float4 kv[16];
#pragma unroll
    for (int r = 0; r < 16; r++) {
        int i = t + r * 128, row = i >> 3, seg = i & 7;
        kv[r] = *(const float4*)(kp + (size_t)row * PP + seg * 4);
    }
    for (int c = 0; c < 4; c++) {
        const int buf = c & 1;
        const uint32_t mb = sbase + 16 + 8 * buf;
        if (c >= 2) MBAR_WAIT(mb, 0);
#pragma unroll
        for (int r = 0; r < 16; r++) {
            int i = t + r * 128, row = i >> 3, seg = i & 7;
            *(float4*)(sm + kvoff[buf] + SW128(row * 128 + seg * 16)) = kv[r];
        }
        if (c < 3) {
#pragma unroll
            for (int r = 0; r < 16; r++) {
                int i = t + r * 128, row = i >> 3, seg = i & 7;
                kv[r] = *(const float4*)(kp + (size_t)row * PP + (c + 1) * 32 + seg * 4);
            }
        }
        __syncthreads();
        if (wid == 0 && elect1()) {
            FENCE_ASYNC();
            uint64_t qd = mkdesc(sbase + AS_Q + c * 16384);
            uint64_t kd = mkdesc(sbase + kvoff[buf]);
#pragma unroll
            for (int s = 0; s < 4; s++)
                mma_ss(tmem, qd + s * 2, kd + s * 2, IDESC_256,
                       (c > 0 || s > 0) ? 1u : 0u);
            TM_COMMIT(mb);
        }
    }
    MBAR_WAIT(sbase + 24, 1);
    TM_FENCE_AFTER();

    uint32_t rs[32];
    float mx = -1e30f;
#pragma unroll
    for (int cc = 0; cc < 8; cc++) {
        TM_LD_X32(rs, tmem + cc * 32);
        TM_WAIT_LD();
#pragma unroll
        for (int i = 0; i < 32; i++) mx = fmaxf(mx, __uint_as_float(rs[i]));
    }
    float ssum = 0.f;
#pragma unroll
    for (int cc = 0; cc < 8; cc++) {
        TM_LD_X32(rs, tmem + cc * 32);
        TM_WAIT_LD();
#pragma unroll
        for (int i = 0; i < 32; i++) {
            float e = __expf(__uint_as_float(rs[i]) - mx);
            ssum += e;
            rs[i] = __float_as_uint(e);
        }
        TM_ST_X32(tmem + cc * 32, rs);
    }
    TM_WAIT_ST();
    const float sinv = 1.f / ssum;
    TM_FENCE_BEFORE();

#pragma unroll
    for (int r = 0; r < 16; r++) {
        int i = t + r * 128, row = i >> 4, seg = i & 15;
        kv[r] = *(const float4*)(vp + (size_t)row * NN + seg * 4);
    }
    for (int j = 0; j < 4; j++) {
        const int buf = j & 1;
        const uint32_t mb = sbase + 16 + 8 * buf;
        if (j >= 2) MBAR_WAIT(mb, 0);
#pragma unroll
        for (int r = 0; r < 16; r++) {
            int i = t + r * 128, row = i >> 4, seg = i & 15;
            *(float4*)(sm + kvoff[buf] + (seg >> 3) * 16384 +
                       SW128(row * 128 + (seg & 7) * 16)) = kv[r];
        }
        if (j < 3) {
#pragma unroll
            for (int r = 0; r < 16; r++) {
                int i = t + r * 128, row = i >> 4, seg = i & 15;
                kv[r] = *(const float4*)(vp + (size_t)row * NN + (j + 1) * 64 + seg * 4);
            }
        }
        __syncthreads();
        if (wid == 0 && elect1()) {
            FENCE_ASYNC();
            TM_FENCE_AFTER();
            uint64_t vd = mkdesc(sbase + kvoff[buf]);
#pragma unroll
            for (int s = 0; s < 8; s++)
                mma_ts(tmem + 256, tmem + j * 64 + s * 8,
                       vd + (s >> 2) * 1024 + (s & 3) * 2, IDESC_128,
                       (j > 0 || s > 0) ? 1u : 0u);
            TM_COMMIT(mb);
        }
    }
    MBAR_WAIT(sbase + 24, 1);
    TM_FENCE_AFTER();

    const float* g2s  = (const float*)(sm + 1024);
    const float* be2s = (const float*)(sm + 1536);
    const float* myo1 = o1p + (size_t)(wid * 32 + lane) * PP;
    float* myo2       = o2p + (size_t)(wid * 32 + lane) * PP;
#pragma unroll
    for (int k = 0; k < 4; k++) {
        TM_LD_X32(rs, tmem + 256 + k * 32);
        TM_WAIT_LD();
#pragma unroll
        for (int i = 0; i < 32; i += 4) {
            int d = k * 32 + i;
            float4 r1 = *(const float4*)(myo1 + d);
            float4 o;
            o.x = to_tf32(fmaxf(fmaf(fmaf(__uint_as_float(rs[i + 0]), sinv, r1.x), g2s[d + 0], be2s[d + 0]), 0.f));
            o.y = to_tf32(fmaxf(fmaf(fmaf(__uint_as_float(rs[i + 1]), sinv, r1.y), g2s[d + 1], be2s[d + 1]), 0.f));
            o.z = to_tf32(fmaxf(fmaf(fmaf(__uint_as_float(rs[i + 2]), sinv, r1.z), g2s[d + 2], be2s[d + 2]), 0.f));
            o.w = to_tf32(fmaxf(fmaf(fmaf(__uint_as_float(rs[i + 3]), sinv, r1.w), g2s[d + 3], be2s[d + 3]), 0.f));
            *(float4*)(myo2 + d) = o;
        }
    }
    __syncthreads();
    if (wid == 0) TM_DEALLOC(tmem, 512);

#else  // ---------------- fp32 fallback (never runs on GB300) ---------------
    const int x = t;
    float sb[256];
    float mx = -1e30f;
    for (int y = 0; y < 256; y++) {
        float s = 0.f;
        for (int d = 0; d < DH; d++)
            s += qp[(size_t)x * PP + d] * kp[(size_t)y * PP + d];
        sb[y] = s;
        mx = fmaxf(mx, s);
    }
    float ssum = 0.f;
    for (int y = 0; y < 256; y++) { sb[y] = __expf(sb[y] - mx); ssum += sb[y]; }
    float sinv = 1.f / ssum;
    for (int d = 0; d < DH; d++) {
        float o = 0.f;
        for (int y = 0; y < 256; y++) o += sb[y] * vp[(size_t)d * NN + y];
        float val = (o * sinv + o1p[(size_t)x * PP + d]) * (g2[hh * DH + d] * INVF)
                    + be2[hh * DH + d];
        o2p[(size_t)x * PP + d] = to_tf32(fmaxf(val, 0.f));
    }
#endif
}

// ---------------------------------------------------------------------------
extern "C" void kernel_launch(void* const* d_in, const int* in_sizes, int n_in,
                              void* d_out, int out_size)
{
    const float* x   = (const float*)d_in[0];
    const float* w1  = (const float*)d_in[1];
    const float* b1  = (const float*)d_in[2];
    const float* g1  = (const float*)d_in[3];
    const float* be1 = (const float*)d_in[4];
    const float* wq  = (const float*)d_in[5];
    const float* wk  = (const float*)d_in[6];
    const float* wv  = (const float*)d_in[7];
    const float* g2  = (const float*)d_in[8];
    const float* be2 = (const float*)d_in[9];
    const float* w3  = (const float*)d_in[10];
    const float* b3  = (const float*)d_in[11];
    const float* g3  = (const float*)d_in[12];
    const float* be3 = (const float*)d_in[13];
    float* out = (float*)d_out;

    float *xT, *o1T, *qT, *kT, *vb, *o2T, *wr;
    cudaGetSymbolAddress((void**)&xT,  g_xT);
    cudaGetSymbolAddress((void**)&o1T, g_o1T);
    cudaGetSymbolAddress((void**)&qT,  g_qT);
    cudaGetSymbolAddress((void**)&kT,  g_kT);
    cudaGetSymbolAddress((void**)&vb,  g_v);
    cudaGetSymbolAddress((void**)&o2T, g_o2T);
    cudaGetSymbolAddress((void**)&wr,  g_wr);

    cudaFuncSetAttribute((const void*)tgp<0>, cudaFuncAttributeMaxDynamicSharedMemorySize, GSMEM);
    cudaFuncSetAttribute((const void*)tgp<1>, cudaFuncAttributeMaxDynamicSharedMemorySize, GSMEM);
    cudaFuncSetAttribute((const void*)tgp<2>, cudaFuncAttributeMaxDynamicSharedMemorySize, GSMEM);
    cudaFuncSetAttribute((const void*)attn_tc, cudaFuncAttributeMaxDynamicSharedMemorySize, ASMEM);

    // 0a) round all weights to tf32 (single launch, contiguous g_wr)
    round_w5<<<(N4_TOT + 255) / 256, 256>>>(w1, wq, wk, wv, w3, wr);
    // 0b) xT[b][hw][c] (tf32-rounded)
    transpose_k<<<dim3(64, 32, BB), 256>>>(x, xT, CIN, NN);
    // 1) o1T = relu(bn1(conv1(x)))^T  [b][hw][p], rounded   (persistent)
    tgp<0><<<GRID_P, 256, GSMEM>>>(wr + WR_W1, xT, o1T, nullptr, nullptr,
                                   nullptr, g1, be1, b1);
    // 2) fused qkv persistent: qT (scaled, trans), kT (trans), v (flipped)
    tgp<1><<<GRID_P, 256, GSMEM>>>(wr + WR_WQ, o1T, qT, kT, vb,
                                   nullptr, nullptr, nullptr, nullptr);
    // 3) attention + residual + bn2 + relu -> o2T [b][hw][p], rounded
    attn_tc<<<dim3(2, 32, BB), 128, ASMEM>>>(qT, kT, vb, o1T, g2, be2, o2T);
    // 4) out = relu(bn3(conv3) + x)   (flipped persistent)
    tgp<2><<<GRID_P, 256, GSMEM>>>(wr + WR_W3, o2T, out, nullptr, nullptr,
                                   x, g3, be3, b3);
}

// round 9
// speedup vs baseline: 6.8555x; 1.0002x over previous
#include <cuda_runtime.h>
#include <cstdint>

// Problem constants
#define BB 16
#define CIN 1024
#define PP 512
#define NN 2048          // H*W
#define DH 128           // head dim
#define INVF 0.99999500003749969f      // 1/sqrt(1+1e-5)
#define QSCALE 0.08838834764831843f    // 128^-0.5
#define GRID_P 152                      // GB300 SM count (persistent grid)

#if defined(__CUDA_ARCH__) && (__CUDA_ARCH__ >= 1000) && \
    (defined(__CUDA_ARCH_FEAT_SM103_ALL) || defined(__CUDA_ARCH_FEAT_SM100_ALL) || \
     defined(__CUDA_ARCH_SPECIFIC__) || defined(__CUDA_ARCH_FAMILY_SPECIFIC__))
#define HAS_TCGEN05 1
#else
#define HAS_TCGEN05 0
#endif

// Scratch (device globals)
__device__ float g_xT [(size_t)BB * CIN * NN];   // [b][hw][c]  (tf32-rounded)
__device__ float g_o1T[(size_t)BB * PP * NN];    // [b][hw][p]  (tf32-rounded)
__device__ float g_qT [(size_t)BB * PP * NN];    // [b][hw][p]  (tf32-rounded)
__device__ float g_kT [(size_t)BB * PP * NN];    // [b][hw][p]  (tf32-rounded)
__device__ float g_v  [(size_t)BB * PP * NN];    // [b][p][hw]  (tf32-rounded)
__device__ float g_o2T[(size_t)BB * PP * NN];    // [b][hw][p]  (tf32-rounded)
// Rounded weights, contiguous: w1 | wq | wk | wv | w3
#define WR_W1 0
#define WR_WQ (512 * 1024)
#define WR_WK (WR_WQ + 512 * 512)
#define WR_WV (WR_WK + 512 * 512)
#define WR_W3 (WR_WV + 512 * 512)
__device__ float g_wr[WR_W3 + 1024 * 512];

// ---------------------------------------------------------------------------
__device__ __forceinline__ uint32_t smem_u32(const void* p) {
    uint32_t a;
    asm("{ .reg .u64 t; cvta.to.shared.u64 t, %1; cvt.u32.u64 %0, t; }"
        : "=r"(a) : "l"(p));
    return a;
}
__device__ __forceinline__ float to_tf32(float x) {
    float r; asm("cvt.rna.tf32.f32 %0, %1;" : "=f"(r) : "f"(x)); return r;
}

#if HAS_TCGEN05
__device__ __forceinline__ uint32_t elect1() {
    uint32_t p;
    asm volatile("{ .reg .pred p; elect.sync _|p, 0xFFFFFFFF; selp.b32 %0,1,0,p; }"
                 : "=r"(p));
    return p;
}
#define SW128(o) ((o) ^ ((((uint32_t)(o)) >> 3) & 0x70))

#define MBAR_INIT(a, c) \
    asm volatile("mbarrier.init.shared.b64 [%0], %1;" :: "r"(a), "r"(c) : "memory")

#define MBAR_ARRIVE(a) \
    asm volatile("mbarrier.arrive.shared::cta.b64 _, [%0];" :: "r"(a) : "memory")

#define MBAR_WAIT(a, ph) do { \
    uint32_t _d; \
    asm volatile("{ .reg .pred p; mbarrier.try_wait.parity.acquire.cta.shared::cta.b64 p,[%1],%2; selp.b32 %0,1,0,p; }" \
                 : "=r"(_d) : "r"(a), "r"((uint32_t)(ph)) : "memory"); \
    if (!_d) { \
        asm volatile("{ .reg .pred P;\nLW_%=:\nmbarrier.try_wait.parity.acquire.cta.shared::cta.b64 P,[%0],%1,0x989680;\n@P bra.uni LD_%=;\nbra.uni LW_%=;\nLD_%=:\n}" \
                     :: "r"(a), "r"((uint32_t)(ph)) : "memory"); \
    } } while (0)

#define TM_ALLOC(sa, n) \
    asm volatile("tcgen05.alloc.cta_group::1.sync.aligned.shared::cta.b32 [%0], %1;" \
                 :: "r"(sa), "r"(n) : "memory")
#define TM_DEALLOC(t, n) \
    asm volatile("tcgen05.dealloc.cta_group::1.sync.aligned.b32 %0, %1;" :: "r"(t), "r"(n))
#define TM_COMMIT(mb) \
    asm volatile("tcgen05.commit.cta_group::1.mbarrier::arrive::one.shared::cluster.b64 [%0];" \
                 :: "r"(mb) : "memory")
#define TM_FENCE_AFTER()  asm volatile("tcgen05.fence::after_thread_sync;" ::: "memory")
#define TM_FENCE_BEFORE() asm volatile("tcgen05.fence::before_thread_sync;" ::: "memory")
#define TM_WAIT_LD()      asm volatile("tcgen05.wait::ld.sync.aligned;" ::: "memory")
#define TM_WAIT_ST()      asm volatile("tcgen05.wait::st.sync.aligned;" ::: "memory")
#define FENCE_ASYNC()     asm volatile("fence.proxy.async.shared::cta;" ::: "memory")

#define CP_ASYNC16(dst, src) \
    asm volatile("cp.async.cg.shared.global [%0], [%1], 16;" \
                 :: "r"(dst), "l"(src) : "memory")
#define CP_MBAR_ARRIVE(mb) \
    asm volatile("cp.async.mbarrier.arrive.noinc.shared::cta.b64 [%0];" \
                 :: "r"(mb) : "memory")

#define TM_LD_X32(r, addr) \
    asm volatile("tcgen05.ld.sync.aligned.32x32b.x32.b32 " \
        "{%0,%1,%2,%3,%4,%5,%6,%7,%8,%9,%10,%11,%12,%13,%14,%15," \
        "%16,%17,%18,%19,%20,%21,%22,%23,%24,%25,%26,%27,%28,%29,%30,%31}, [%32];" \
        : "=r"((r)[0]),"=r"((r)[1]),"=r"((r)[2]),"=r"((r)[3]), \
          "=r"((r)[4]),"=r"((r)[5]),"=r"((r)[6]),"=r"((r)[7]), \
          "=r"((r)[8]),"=r"((r)[9]),"=r"((r)[10]),"=r"((r)[11]), \
          "=r"((r)[12]),"=r"((r)[13]),"=r"((r)[14]),"=r"((r)[15]), \
          "=r"((r)[16]),"=r"((r)[17]),"=r"((r)[18]),"=r"((r)[19]), \
          "=r"((r)[20]),"=r"((r)[21]),"=r"((r)[22]),"=r"((r)[23]), \
          "=r"((r)[24]),"=r"((r)[25]),"=r"((r)[26]),"=r"((r)[27]), \
          "=r"((r)[28]),"=r"((r)[29]),"=r"((r)[30]),"=r"((r)[31]) \
        : "r"(addr))

#define TM_ST_X32(addr, r) \
    asm volatile("tcgen05.st.sync.aligned.32x32b.x32.b32 [%0], " \
        "{%1,%2,%3,%4,%5,%6,%7,%8,%9,%10,%11,%12,%13,%14,%15,%16," \
        "%17,%18,%19,%20,%21,%22,%23,%24,%25,%26,%27,%28,%29,%30,%31,%32};" \
        :: "r"(addr), \
           "r"((r)[0]),"r"((r)[1]),"r"((r)[2]),"r"((r)[3]), \
           "r"((r)[4]),"r"((r)[5]),"r"((r)[6]),"r"((r)[7]), \
           "r"((r)[8]),"r"((r)[9]),"r"((r)[10]),"r"((r)[11]), \
           "r"((r)[12]),"r"((r)[13]),"r"((r)[14]),"r"((r)[15]), \
           "r"((r)[16]),"r"((r)[17]),"r"((r)[18]),"r"((r)[19]), \
           "r"((r)[20]),"r"((r)[21]),"r"((r)[22]),"r"((r)[23]), \
           "r"((r)[24]),"r"((r)[25]),"r"((r)[26]),"r"((r)[27]), \
           "r"((r)[28]),"r"((r)[29]),"r"((r)[30]),"r"((r)[31]) \
        : "memory")

__device__ __forceinline__ uint64_t mkdesc(uint32_t addr) {
    return ((uint64_t)2 << 61) | ((uint64_t)1 << 46) | ((uint64_t)64 << 32) |
           ((uint64_t)1 << 16) | ((addr >> 4) & 0x3FFF);
}
__device__ __forceinline__ void mma_ss(uint32_t d, uint64_t ad, uint64_t bd,
                                       uint32_t id, uint32_t en) {
    asm volatile(
        "{ .reg .pred p; setp.ne.u32 p, %5, 0;\n\t"
        "tcgen05.mma.cta_group::1.kind::tf32 [%0], %1, %2, %3, {%4,%4,%4,%4}, p;\n\t}"
        :: "r"(d), "l"(ad), "l"(bd), "r"(id), "r"(0u), "r"(en) : "memory");
}
__device__ __forceinline__ void mma_ts(uint32_t d, uint32_t a, uint64_t bd,
                                       uint32_t id, uint32_t en) {
    asm volatile(
        "{ .reg .pred p; setp.ne.u32 p, %5, 0;\n\t"
        "tcgen05.mma.cta_group::1.kind::tf32 [%0], [%1], %2, %3, {%4,%4,%4,%4}, p;\n\t}"
        :: "r"(d), "r"(a), "l"(bd), "r"(id), "r"(0u), "r"(en) : "memory");
}
#define IDESC_128 ((1u << 4) | (2u << 7) | (2u << 10) | (16u << 17) | (8u << 24))
#define IDESC_256 ((1u << 4) | (2u << 7) | (2u << 10) | (32u << 17) | (8u << 24))
#endif  // HAS_TCGEN05

// ---------------------------------------------------------------------------
// Round all 5 weight matrices to tf32 in one launch, into contiguous g_wr
// ---------------------------------------------------------------------------
#define N4_W1 131072
#define N4_P  65536
#define N4_W3 131072
#define N4_TOT (N4_W1 + 3 * N4_P + N4_W3)

__global__ __launch_bounds__(256)
void round_w5(const float* __restrict__ w1, const float* __restrict__ wq,
              const float* __restrict__ wk, const float* __restrict__ wv,
              const float* __restrict__ w3, float* __restrict__ out)
{
    int i = blockIdx.x * 256 + threadIdx.x;
    if (i >= N4_TOT) return;
    const float4* src;
    int j = i;
    if (j < N4_W1) src = (const float4*)w1;
    else if ((j -= N4_W1) < N4_P) src = (const float4*)wq;
    else if ((j -= N4_P) < N4_P) src = (const float4*)wk;
    else if ((j -= N4_P) < N4_P) src = (const float4*)wv;
    else { j -= N4_P; src = (const float4*)w3; }
    float4 v = src[j];
    v.x = to_tf32(v.x); v.y = to_tf32(v.y);
    v.z = to_tf32(v.z); v.w = to_tf32(v.w);
    ((float4*)out)[i] = v;
}

// ---------------------------------------------------------------------------
// Tiled transpose per batch with tf32 rounding: in[b][R][C] -> out[b][C][R]
// ---------------------------------------------------------------------------
__global__ __launch_bounds__(256)
void transpose_k(const float* __restrict__ in, float* __restrict__ out, int R, int C)
{
    __shared__ float tile[32][33];
    const int b = blockIdx.z;
    const float* ip = in + (size_t)b * R * C;
    float* op = out + (size_t)b * R * C;
    const int c0 = blockIdx.x * 32, r0 = blockIdx.y * 32;
    const int tx = threadIdx.x & 31, ty = threadIdx.x >> 5;
#pragma unroll
    for (int i = 0; i < 32; i += 8)
        tile[ty + i][tx] = ip[(size_t)(r0 + ty + i) * C + c0 + tx];
    __syncthreads();
#pragma unroll
    for (int i = 0; i < 32; i += 8)
        op[(size_t)(c0 + ty + i) * R + r0 + tx] = to_tf32(tile[tx][ty + i]);
}

// ---------------------------------------------------------------------------
// Warp-specialized persistent tcgen05 tf32 GEMM.
// Producers (warps 0-3): cp.async feed + MMA issue (warp 0 elect), no
//   __syncthreads in the loop; stage-full via cp.async.mbarrier.arrive.noinc.
// Consumers (warps 4-7 = TMEM subpartitions 0-3): per-tile epilogue from the
//   double-buffered TMEM accumulators, fully overlapped with the mainloop.
// Barriers: full[4](cnt 128) / mma[4](cnt 1) / tiledone[2](cnt 1) /
//   epifree[2](cnt 128).
// MODE 0: conv1  D[p][hw]  -> o1T[hw][p]   (bn1+relu, rnd)
// MODE 1: qkv    id<1024: D[p][hw] -> qT/kT[hw][p] (q scaled; rnd)
//                id>=1024 (flipped): D[hw][p] -> v[p][hw] (rnd)
// MODE 2: conv3 (flipped) D[hw][c] -> out[c][hw]  (bn3 per-reg + resid + relu)
// ---------------------------------------------------------------------------
#define NSTAGE 4
#define STAGE_B 49152u
#define GS_BN   (1024u + NSTAGE * STAGE_B)          // bn tables for MODE 2
#define GSMEM   (GS_BN + 2 * 1024 * 4)              // 205824 B

template <int MODE>
__device__ __forceinline__ void tile_ab(int id, const float* W, const float* ACT,
                                        const float*& A, const float*& B)
{
    if (MODE == 0) {
        int m0 = (id & 3) << 7, n0 = ((id >> 2) & 7) << 8, bz = id >> 5;
        A = W + (size_t)m0 * 1024;
        B = ACT + ((size_t)bz * NN + n0) * 1024;
    } else if (MODE == 1) {
        if (id < 1024) {
            int m0 = (id & 7) << 7, n0 = ((id >> 3) & 7) << 8, bz = id >> 6;
            A = W + (size_t)m0 * 512;
            B = ACT + ((size_t)bz * NN + n0) * 512;
        } else {
            int j = id - 1024;
            int m0 = (j & 15) << 7, n0 = ((j >> 4) & 1) << 8, bz = j >> 5;
            A = ACT + ((size_t)bz * NN + m0) * 512;   // activations on M side
            B = W + 524288u + (size_t)n0 * 512;       // wv
        }
    } else {
        int m0 = (id & 15) << 7, n0 = ((id >> 4) & 3) << 8, bz = id >> 6;
        A = ACT + ((size_t)bz * NN + m0) * 512;       // o2T rows (hw)
        B = W + (size_t)n0 * 512;                     // w3 rows (c)
    }
}

// Single-element epilogue (fp32 fallback only)
template <int MODE>
__device__ __forceinline__ void epi_scalar(int id, int ml, int n, float acc,
    float* O0, float* O1, float* O2, const float* resid,
    const float* g, const float* be, const float* cb)
{
    if (MODE == 0) {
        int m0 = (id & 3) << 7, n0 = ((id >> 2) & 7) << 8, bz = id >> 5;
        int m = m0 + ml;
        float s = g[m] * INVF, tt = cb[m] * s + be[m];
        O0[((size_t)bz * NN + n0 + n) * 512 + m] = to_tf32(fmaxf(fmaf(acc, s, tt), 0.f));
    } else if (MODE == 1) {
        if (id < 1024) {
            int m0 = (id & 7) << 7, n0 = ((id >> 3) & 7) << 8, bz = id >> 6;
            float* T = (m0 < 512) ? O0 : O1;
            float qs = (m0 < 512) ? QSCALE : 1.f;
            T[((size_t)bz * NN + n0 + n) * 512 + ((m0 + ml) & 511)] = to_tf32(acc * qs);
        } else {
            int j = id - 1024;
            int m0 = (j & 15) << 7, n0 = ((j >> 4) & 1) << 8, bz = j >> 5;
            O2[((size_t)bz * 512 + n0 + n) * NN + m0 + ml] = to_tf32(acc);
        }
    } else {
        int m0 = (id & 15) << 7, n0 = ((id >> 4) & 3) << 8, bz = id >> 6;
        int c = n0 + n;
        float s = g[c] * INVF, tt = cb[c] * s + be[c];
        size_t off = ((size_t)bz * 1024 + c) * NN + m0 + ml;
        O0[off] = fmaxf(fmaf(acc, s, tt) + resid[off], 0.f);
    }
}

#if HAS_TCGEN05
// Producer feed: 128 threads load one 48KB chunk (A 16K + B 32K) with cp.async
template <int MODE>
__device__ __forceinline__ void issue_chunk(uint32_t sbase, int gc, int cta,
                                            const float* W, const float* ACT, int t)
{
    constexpr int NKS = (MODE == 0) ? 5 : 4;
    constexpr int K = (MODE == 0) ? 1024 : 512;
    const int lt = gc >> NKS, c = gc & ((1 << NKS) - 1);
    const float *A, *B;
    tile_ab<MODE>(cta + lt * GRID_P, W, ACT, A, B);
    const uint32_t st = sbase + 1024u + (uint32_t)(gc & 3) * STAGE_B;
#pragma unroll
    for (int r = 0; r < 8; r++) {               // A: 128 x 32
        int idx = t + r * 128, row = idx >> 3, seg = idx & 7;
        CP_ASYNC16(st + SW128(row * 128 + seg * 16),
                   A + (size_t)row * K + c * 32 + seg * 4);
    }
#pragma unroll
    for (int r = 0; r < 16; r++) {              // B: 256 x 32
        int idx = t + r * 128, row = idx >> 3, seg = idx & 7;
        CP_ASYNC16(st + 16384u + SW128(row * 128 + seg * 16),
                   B + (size_t)row * K + c * 32 + seg * 4);
    }
    CP_MBAR_ARRIVE(sbase + 16 + 8 * (gc & 3));
}

// Consumer epilogue: 4 warps (subpartitions 0-3) drain one 128x256 TMEM buffer
template <int MODE>
__device__ __forceinline__ void epi_tile(int id, int abuf, uint32_t tmem, char* smem,
    float* O0, float* O1, float* O2, const float* resid,
    const float* g, const float* be, const float* cb, int wid, int lane)
{
    float* Ob; const float* Rb = nullptr;
    size_t sN; int n0g = 0, m0;
    float qs = 1.f;
    if (MODE == 0) {
        m0 = (id & 3) << 7; int n0 = ((id >> 2) & 7) << 8; int bz = id >> 5;
        Ob = O0 + ((size_t)bz * NN + n0) * 512 + m0;  sN = 512;
    } else if (MODE == 1) {
        if (id < 1024) {
            m0 = (id & 7) << 7; int n0 = ((id >> 3) & 7) << 8; int bz = id >> 6;
            float* T = (m0 < 512) ? O0 : O1;
            if (m0 < 512) qs = QSCALE;
            Ob = T + ((size_t)bz * NN + n0) * 512 + (m0 & 511);  sN = 512;
        } else {
            int j = id - 1024;
            m0 = (j & 15) << 7; int n0 = ((j >> 4) & 1) << 8; int bz = j >> 5;
            Ob = O2 + ((size_t)bz * 512 + n0) * NN + m0;  sN = NN;
        }
    } else {
        m0 = (id & 15) << 7; int n0 = ((id >> 4) & 3) << 8; int bz = id >> 6;
        Ob = O0 + ((size_t)bz * 1024 + n0) * NN + m0;
        Rb = resid + ((size_t)bz * 1024 + n0) * NN + m0;
        sN = NN; n0g = n0;
    }
    const int ml = (wid & 3) * 32 + lane;        // warps 4-7 -> subpartition 0-3
    float sL = qs, tL = 0.f;
    if (MODE == 0) { int m = m0 + ml; sL = g[m] * INVF; tL = cb[m] * sL + be[m]; }
    const float* bs = (const float*)(smem + GS_BN);
    const float* bt = (const float*)(smem + GS_BN + 4096);

    uint32_t r0[32];
#pragma unroll
    for (int k = 0; k < 8; k++) {
        TM_LD_X32(r0, tmem + abuf * 256 + k * 32);
        TM_WAIT_LD();
#pragma unroll
        for (int i = 0; i < 32; i++) {
            const int n = k * 32 + i;
            float v = __uint_as_float(r0[i]);
            if (MODE == 2)
                v = fmaxf(fmaf(v, bs[n0g + n], bt[n0g + n]) + Rb[(size_t)n * sN + ml], 0.f);
            else if (MODE == 0)
                v = to_tf32(fmaxf(fmaf(v, sL, tL), 0.f));
            else
                v = to_tf32(v * sL);
            Ob[(size_t)n * sN + ml] = v;
        }
    }
}
#endif  // HAS_TCGEN05

template <int MODE>
__global__ __launch_bounds__(256)
void tgp(const float* __restrict__ W, const float* __restrict__ ACT,
         float* __restrict__ O0, float* __restrict__ O1, float* __restrict__ O2,
         const float* __restrict__ resid,
         const float* __restrict__ g, const float* __restrict__ be,
         const float* __restrict__ cb)
{
    constexpr int TOT   = (MODE == 0) ? 512 : (MODE == 1) ? 1536 : 1024;
    constexpr int NKS   = (MODE == 0) ? 5 : 4;
    constexpr int NK    = 1 << NKS;
    const int cta = blockIdx.x;
    const int t = threadIdx.x;
    const int ntl = (TOT - cta + GRID_P - 1) / GRID_P;
    if (ntl <= 0) return;
    const int totc = ntl * NK;

#if HAS_TCGEN05
    extern __shared__ char smem[];
    const uint32_t sbase = smem_u32(smem);
    const int wid = t >> 5, lane = t & 31;
    // mbar layout: full[4]@16  mma[4]@48  tiledone[2]@80  epifree[2]@96
    if (t < 4)                MBAR_INIT(sbase + 16 + 8 * t, 128);
    else if (t < 8)           MBAR_INIT(sbase + 48 + 8 * (t - 4), 1);
    else if (t < 10)          MBAR_INIT(sbase + 80 + 8 * (t - 8), 1);
    else if (t < 12)          MBAR_INIT(sbase + 96 + 8 * (t - 10), 128);
    if (wid == 0) TM_ALLOC(sbase + 0, 512);
    if (MODE == 2) {
        for (int i = t; i < 1024; i += 256) {
            float s = g[i] * INVF;
            ((float*)(smem + GS_BN))[i] = s;
            ((float*)(smem + GS_BN + 4096))[i] = cb[i] * s + be[i];
        }
    }
    __syncthreads();
    uint32_t tmem;
    asm volatile("ld.shared.b32 %0, [%1];" : "=r"(tmem) : "r"(sbase + 0));

    if (t < 128) {
        // ----------------- producers (warps 0-3) -----------------
        issue_chunk<MODE>(sbase, 0, cta, W, ACT, t);
        if (totc > 1) issue_chunk<MODE>(sbase, 1, cta, W, ACT, t);
        if (totc > 2) issue_chunk<MODE>(sbase, 2, cta, W, ACT, t);

        for (int gc = 0; gc < totc; gc++) {
            const int s = gc & 3, c = gc & (NK - 1), lt = gc >> NKS;
            if (wid == 0 && elect1()) {
                if (c == 0 && lt >= 2) {   // buffer reuse WAR vs epilogue lt-2
                    MBAR_WAIT(sbase + 96 + 8 * (lt & 1), ((lt >> 1) - 1) & 1);
                    TM_FENCE_AFTER();
                }
                MBAR_WAIT(sbase + 16 + 8 * s, (gc >> 2) & 1);   // chunk data ready
                FENCE_ASYNC();
                const uint32_t st = sbase + 1024u + (uint32_t)s * STAGE_B;
                const uint64_t ad = mkdesc(st);
                const uint64_t bd = mkdesc(st + 16384u);
                const uint32_t dacc = tmem + (uint32_t)((lt & 1) << 8);
#pragma unroll
                for (int si = 0; si < 4; si++)
                    mma_ss(dacc, ad + si * 2, bd + si * 2, IDESC_256,
                           (c > 0 || si > 0) ? 1u : 0u);
                TM_COMMIT(sbase + 48 + 8 * s);
            }
            if (gc >= 1) {
                MBAR_WAIT(sbase + 48 + 8 * ((gc - 1) & 3), ((gc - 1) >> 2) & 1);
                if (c == 0 && wid == 0 && elect1())
                    MBAR_ARRIVE(sbase + 80 + 8 * ((lt - 1) & 1));  // tile lt-1 done
            }
            if (gc + 3 < totc) issue_chunk<MODE>(sbase, gc + 3, cta, W, ACT, t);
        }
        MBAR_WAIT(sbase + 48 + 8 * ((totc - 1) & 3), ((totc - 1) >> 2) & 1);
        if (wid == 0 && elect1())
            MBAR_ARRIVE(sbase + 80 + 8 * ((ntl - 1) & 1));         // last tile done
    } else {
        // ----------------- consumers (warps 4-7) -----------------
        for (int lt = 0; lt < ntl; lt++) {
            MBAR_WAIT(sbase + 80 + 8 * (lt & 1), (lt >> 1) & 1);
            TM_FENCE_AFTER();
            epi_tile<MODE>(cta + lt * GRID_P, lt & 1, tmem, smem,
                           O0, O1, O2, resid, g, be, cb, wid, lane);
            TM_FENCE_BEFORE();
            MBAR_ARRIVE(sbase + 96 + 8 * (lt & 1));                // buffer free
        }
    }
    __syncthreads();
    if (wid == 0) TM_DEALLOC(tmem, 512);

#else  // ---------------- fp32 fallback (never runs on GB300) ---------------
    constexpr int K = (MODE == 0) ? 1024 : 512;
    for (int lt = 0; lt < ntl; lt++) {
        const int id = cta + lt * GRID_P;
        const float *A, *B;
        tile_ab<MODE>(id, W, ACT, A, B);
        for (int e = t; e < 128 * 256; e += 256) {
            const int ml = e & 127, n = e >> 7;
            float acc = 0.f;
            for (int k = 0; k < K; k++)
                acc += A[(size_t)ml * K + k] * B[(size_t)n * K + k];
            epi_scalar<MODE>(id, ml, n, acc, O0, O1, O2, resid, g, be, cb);
        }
    }
#endif
}

// ---------------------------------------------------------------------------
// tcgen05 attention (verified) + tf32-rounded o2T output
// ---------------------------------------------------------------------------
#define AS_Q   2048u
#define AS_KV0 (2048u + 65536u)
#define AS_KV1 (2048u + 65536u + 32768u)
#define ASMEM  133120

__global__ __launch_bounds__(128)
void attn_tc(const float* __restrict__ qT, const float* __restrict__ kT,
             const float* __restrict__ v, const float* __restrict__ o1T,
             const float* __restrict__ g2, const float* __restrict__ be2,
             float* __restrict__ o2T)
{
    extern __shared__ char sm[];
    const int t = threadIdx.x, wid = t >> 5, lane = t & 31;
    const int xt = blockIdx.x;
    const int sp = blockIdx.y >> 2, hh = blockIdx.y & 3;
    const int b = blockIdx.z;

    const size_t qrow = (size_t)b * NN + sp * 256 + xt * 128;
    const float* qp  = qT  + qrow * PP + hh * DH;
    const float* kp  = kT  + ((size_t)b * NN + sp * 256) * PP + hh * DH;
    const float* vp  = v   + ((size_t)b * PP + hh * DH) * NN + sp * 256;
    const float* o1p = o1T + qrow * PP + hh * DH;
    float* o2p       = o2T + qrow * PP + hh * DH;

#if HAS_TCGEN05
    const uint32_t sbase = smem_u32(sm);
    if (t == 0) { MBAR_INIT(sbase + 16, 1); MBAR_INIT(sbase + 24, 1); }
    if (wid == 0) TM_ALLOC(sbase + 0, 512);
    ((float*)(sm + 1024))[t] = g2[hh * DH + t] * INVF;
    ((float*)(sm + 1536))[t] = be2[hh * DH + t];
    __syncthreads();
    uint32_t tmem;
    asm volatile("ld.shared.b32 %0, [%1];" : "=r"(tmem) : "r"(sbase + 0));
    const uint32_t kvoff[2] = {AS_KV0, AS_KV1};

#pragma unroll
    for (int r = 0; r < 32; r++) {
        int i = t + r * 128;
        int row = i >> 5, rem = i & 31, j = rem >> 3, seg = rem & 7;
        float4 vq = *(const float4*)(qp + (size_t)row * PP + j * 32 + seg * 4);
        *(float4*)(sm + AS_Q + j * 16384 + SW128(row * 128 + seg * 16)) = vq;
    }

    float4 kv[16];
#pragma unroll
    for (int r = 0; r < 16; r++) {
        int i = t + r * 128, row = i >> 3, seg = i & 7;
        kv[r] = *(const float4*)(kp + (size_t)row * PP + seg * 4);
    }
    for (int c = 0; c < 4; c++) {
        const int buf = c & 1;
        const uint32_t mb = sbase + 16 + 8 * buf;
        if (c >= 2) MBAR_WAIT(mb, 0);
#pragma unroll
        for (int r = 0; r < 16; r++) {
            int i = t + r * 128, row = i >> 3, seg = i & 7;
            *(float4*)(sm + kvoff[buf] + SW128(row * 128 + seg * 16)) = kv[r];
        }
        if (c < 3) {
#pragma unroll
            for (int r = 0; r < 16; r++) {
                int i = t + r * 128, row = i >> 3, seg = i & 7;
                kv[r] = *(const float4*)(kp + (size_t)row * PP + (c + 1) * 32 + seg * 4);
            }
        }
        __syncthreads();
        if (wid == 0 && elect1()) {
            FENCE_ASYNC();
            uint64_t qd = mkdesc(sbase + AS_Q + c * 16384);
            uint64_t kd = mkdesc(sbase + kvoff[buf]);
#pragma unroll
            for (int s = 0; s < 4; s++)
                mma_ss(tmem, qd + s * 2, kd + s * 2, IDESC_256,
                       (c > 0 || s > 0) ? 1u : 0u);
            TM_COMMIT(mb);
        }
    }
    MBAR_WAIT(sbase + 24, 1);
    TM_FENCE_AFTER();

    uint32_t rs[32];
    float mx = -1e30f;
#pragma unroll
    for (int cc = 0; cc < 8; cc++) {
        TM_LD_X32(rs, tmem + cc * 32);
        TM_WAIT_LD();
#pragma unroll
        for (int i = 0; i < 32; i++) mx = fmaxf(mx, __uint_as_float(rs[i]));
    }
    float ssum = 0.f;
#pragma unroll
    for (int cc = 0; cc < 8; cc++) {
        TM_LD_X32(rs, tmem + cc * 32);
        TM_WAIT_LD();
#pragma unroll
        for (int i = 0; i < 32; i++) {
            float e = __expf(__uint_as_float(rs[i]) - mx);
            ssum += e;
            rs[i] = __float_as_uint(e);
        }
        TM_ST_X32(tmem + cc * 32, rs);
    }
    TM_WAIT_ST();
    const float sinv = 1.f / ssum;
    TM_FENCE_BEFORE();

#pragma unroll
    for (int r = 0; r < 16; r++) {
        int i = t + r * 128, row = i >> 4, seg = i & 15;
        kv[r] = *(const float4*)(vp + (size_t)row * NN + seg * 4);
    }
    for (int j = 0; j < 4; j++) {
        const int buf = j & 1;
        const uint32_t mb = sbase + 16 + 8 * buf;
        if (j >= 2) MBAR_WAIT(mb, 0);
#pragma unroll
        for (int r = 0; r < 16; r++) {
            int i = t + r * 128, row = i >> 4, seg = i & 15;
            *(float4*)(sm + kvoff[buf] + (seg >> 3) * 16384 +
                       SW128(row * 128 + (seg & 7) * 16)) = kv[r];
        }
        if (j < 3) {
#pragma unroll
            for (int r = 0; r < 16; r++) {
                int i = t + r * 128, row = i >> 4, seg = i & 15;
                kv[r] = *(const float4*)(vp + (size_t)row * NN + (j + 1) * 64 + seg * 4);
            }
        }
        __syncthreads();
        if (wid == 0 && elect1()) {
            FENCE_ASYNC();
            TM_FENCE_AFTER();
            uint64_t vd = mkdesc(sbase + kvoff[buf]);
#pragma unroll
            for (int s = 0; s < 8; s++)
                mma_ts(tmem + 256, tmem + j * 64 + s * 8,
                       vd + (s >> 2) * 1024 + (s & 3) * 2, IDESC_128,
                       (j > 0 || s > 0) ? 1u : 0u);
            TM_COMMIT(mb);
        }
    }
    MBAR_WAIT(sbase + 24, 1);
    TM_FENCE_AFTER();

    const float* g2s  = (const float*)(sm + 1024);
    const float* be2s = (const float*)(sm + 1536);
    const float* myo1 = o1p + (size_t)(wid * 32 + lane) * PP;
    float* myo2       = o2p + (size_t)(wid * 32 + lane) * PP;
#pragma unroll
    for (int k = 0; k < 4; k++) {
        TM_LD_X32(rs, tmem + 256 + k * 32);
        TM_WAIT_LD();
#pragma unroll
        for (int i = 0; i < 32; i += 4) {
            int d = k * 32 + i;
            float4 r1 = *(const float4*)(myo1 + d);
            float4 o;
            o.x = to_tf32(fmaxf(fmaf(fmaf(__uint_as_float(rs[i + 0]), sinv, r1.x), g2s[d + 0], be2s[d + 0]), 0.f));
            o.y = to_tf32(fmaxf(fmaf(fmaf(__uint_as_float(rs[i + 1]), sinv, r1.y), g2s[d + 1], be2s[d + 1]), 0.f));
            o.z = to_tf32(fmaxf(fmaf(fmaf(__uint_as_float(rs[i + 2]), sinv, r1.z), g2s[d + 2], be2s[d + 2]), 0.f));
            o.w = to_tf32(fmaxf(fmaf(fmaf(__uint_as_float(rs[i + 3]), sinv, r1.w), g2s[d + 3], be2s[d + 3]), 0.f));
            *(float4*)(myo2 + d) = o;
        }
    }
    __syncthreads();
    if (wid == 0) TM_DEALLOC(tmem, 512);

#else  // ---------------- fp32 fallback (never runs on GB300) ---------------
    const int x = t;
    float sb[256];
    float mx = -1e30f;
    for (int y = 0; y < 256; y++) {
        float s = 0.f;
        for (int d = 0; d < DH; d++)
            s += qp[(size_t)x * PP + d] * kp[(size_t)y * PP + d];
        sb[y] = s;
        mx = fmaxf(mx, s);
    }
    float ssum = 0.f;
    for (int y = 0; y < 256; y++) { sb[y] = __expf(sb[y] - mx); ssum += sb[y]; }
    float sinv = 1.f / ssum;
    for (int d = 0; d < DH; d++) {
        float o = 0.f;
        for (int y = 0; y < 256; y++) o += sb[y] * vp[(size_t)d * NN + y];
        float val = (o * sinv + o1p[(size_t)x * PP + d]) * (g2[hh * DH + d] * INVF)
                    + be2[hh * DH + d];
        o2p[(size_t)x * PP + d] = to_tf32(fmaxf(val, 0.f));
    }
#endif
}

// ---------------------------------------------------------------------------
extern "C" void kernel_launch(void* const* d_in, const int* in_sizes, int n_in,
                              void* d_out, int out_size)
{
    const float* x   = (const float*)d_in[0];
    const float* w1  = (const float*)d_in[1];
    const float* b1  = (const float*)d_in[2];
    const float* g1  = (const float*)d_in[3];
    const float* be1 = (const float*)d_in[4];
    const float* wq  = (const float*)d_in[5];
    const float* wk  = (const float*)d_in[6];
    const float* wv  = (const float*)d_in[7];
    const float* g2  = (const float*)d_in[8];
    const float* be2 = (const float*)d_in[9];
    const float* w3  = (const float*)d_in[10];
    const float* b3  = (const float*)d_in[11];
    const float* g3  = (const float*)d_in[12];
    const float* be3 = (const float*)d_in[13];
    float* out = (float*)d_out;

    float *xT, *o1T, *qT, *kT, *vb, *o2T, *wr;
    cudaGetSymbolAddress((void**)&xT,  g_xT);
    cudaGetSymbolAddress((void**)&o1T, g_o1T);
    cudaGetSymbolAddress((void**)&qT,  g_qT);
    cudaGetSymbolAddress((void**)&kT,  g_kT);
    cudaGetSymbolAddress((void**)&vb,  g_v);
    cudaGetSymbolAddress((void**)&o2T, g_o2T);
    cudaGetSymbolAddress((void**)&wr,  g_wr);

    cudaFuncSetAttribute((const void*)tgp<0>, cudaFuncAttributeMaxDynamicSharedMemorySize, GSMEM);
    cudaFuncSetAttribute((const void*)tgp<1>, cudaFuncAttributeMaxDynamicSharedMemorySize, GSMEM);
    cudaFuncSetAttribute((const void*)tgp<2>, cudaFuncAttributeMaxDynamicSharedMemorySize, GSMEM);
    cudaFuncSetAttribute((const void*)attn_tc, cudaFuncAttributeMaxDynamicSharedMemorySize, ASMEM);

    // 0a) round all weights to tf32 (single launch, contiguous g_wr)
    round_w5<<<(N4_TOT + 255) / 256, 256>>>(w1, wq, wk, wv, w3, wr);
    // 0b) xT[b][hw][c] (tf32-rounded)
    transpose_k<<<dim3(64, 32, BB), 256>>>(x, xT, CIN, NN);
    // 1) o1T = relu(bn1(conv1(x)))^T  [b][hw][p], rounded   (persistent WS)
    tgp<0><<<GRID_P, 256, GSMEM>>>(wr + WR_W1, xT, o1T, nullptr, nullptr,
                                   nullptr, g1, be1, b1);
    // 2) fused qkv persistent WS: qT (scaled, trans), kT (trans), v (flipped)
    tgp<1><<<GRID_P, 256, GSMEM>>>(wr + WR_WQ, o1T, qT, kT, vb,
                                   nullptr, nullptr, nullptr, nullptr);
    // 3) attention + residual + bn2 + relu -> o2T [b][hw][p], rounded
    attn_tc<<<dim3(2, 32, BB), 128, ASMEM>>>(qT, kT, vb, o1T, g2, be2, o2T);
    // 4) out = relu(bn3(conv3) + x)   (flipped persistent WS)
    tgp<2><<<GRID_P, 256, GSMEM>>>(wr + WR_W3, o2T, out, nullptr, nullptr,
                                   x, g3, be3, b3);
}